// round 9
// baseline (speedup 1.0000x reference)
#include <cuda_runtime.h>
#include <cuda_fp16.h>
#include <cstdint>
#include <cstddef>

// Problem constants
#define SEQ   4096
#define DIM   2048
#define NH    16
#define HD    128
#define QKVW  (3 * DIM)   // 6144

// Scratch (device globals: allocation-free per harness rules)
__device__ __half g_qkvh [(size_t)SEQ * QKVW];  // (S, 3*dim) fp16
__device__ __half g_oh   [(size_t)SEQ * DIM];   // attention out fp16
__device__ __half g_xh   [(size_t)SEQ * DIM];   // x fp16
__device__ __half g_wqkvT[(size_t)QKVW * DIM];  // w_qkv^T fp16 (6144, 2048)
__device__ __half g_woT  [(size_t)DIM * DIM];   // w_o^T fp16
__device__ __half g_vTh  [(size_t)DIM * SEQ];   // V^T fp16: [h*128+d][s]

// ===========================================================================
// Helpers
// ===========================================================================
__device__ __forceinline__ uint32_t smem_u32(const void* p) {
    uint32_t a;
    asm("{ .reg .u64 t; cvta.to.shared.u64 t, %1; cvt.u32.u64 %0, t; }"
        : "=r"(a) : "l"(p));
    return a;
}

__device__ __forceinline__ uint32_t pack_h2(float lo, float hi) {
    __half2 h = __floats2half2_rn(lo, hi);
    return *(uint32_t*)&h;
}

__device__ __forceinline__ void cp_async16(uint32_t dst, const void* src) {
    asm volatile("cp.async.cg.shared.global [%0], [%1], 16;"
                 :: "r"(dst), "l"(src));
}

__device__ __forceinline__ void ldsm4(uint32_t& r0, uint32_t& r1,
                                      uint32_t& r2, uint32_t& r3, uint32_t addr) {
    asm volatile("ldmatrix.sync.aligned.m8n8.x4.shared.b16 {%0,%1,%2,%3}, [%4];"
                 : "=r"(r0), "=r"(r1), "=r"(r2), "=r"(r3) : "r"(addr));
}

__device__ __forceinline__ void mma_f16(float* c, const uint32_t* a, const uint32_t* b) {
    asm volatile(
        "mma.sync.aligned.m16n8k16.row.col.f32.f16.f16.f32 "
        "{%0,%1,%2,%3}, {%4,%5,%6,%7}, {%8,%9}, {%0,%1,%2,%3};"
        : "+f"(c[0]), "+f"(c[1]), "+f"(c[2]), "+f"(c[3])
        : "r"(a[0]), "r"(a[1]), "r"(a[2]), "r"(a[3]), "r"(b[0]), "r"(b[1]));
}

// swizzled smem address: row of RS bytes, 16B chunk c16, XOR low3 with row&7
__device__ __forceinline__ uint32_t swz(uint32_t base, int row, int c16, int rs_bytes) {
    return base + (uint32_t)row * (uint32_t)rs_bytes
                + ((uint32_t)(c16 ^ (row & 7)) << 4);
}

__device__ __forceinline__ void sts_f32(uint32_t addr, float v) {
    asm volatile("st.shared.f32 [%0], %1;" :: "r"(addr), "f"(v));
}
__device__ __forceinline__ float lds_f32(uint32_t addr) {
    float v;
    asm volatile("ld.shared.f32 %0, [%1];" : "=f"(v) : "r"(addr));
    return v;
}
__device__ __forceinline__ void bar_pair(int id) {
    asm volatile("bar.sync %0, 64;" :: "r"(id) : "memory");
}

// ---- mbarrier primitives (base ISA) ----
#define MBARRIER_INIT(mbar, cnt) \
    asm volatile("mbarrier.init.shared.b64 [%0], %1;" \
        :: "r"((uint32_t)(mbar)), "r"((uint32_t)(cnt)) : "memory")

#define MBARRIER_ARRIVE(mbar) \
    asm volatile("mbarrier.arrive.shared.b64 _, [%0];" \
        :: "r"((uint32_t)(mbar)) : "memory")

#define CPASYNC_MBAR_ARRIVE(mbar) \
    asm volatile("cp.async.mbarrier.arrive.noinc.shared.b64 [%0];" \
        :: "r"((uint32_t)(mbar)) : "memory")

#define MBARRIER_WAIT_PARITY(mbar, parity) do { \
    uint32_t _m = (uint32_t)(mbar); \
    uint32_t _p = (uint32_t)(parity); \
    uint32_t _done; \
    asm volatile( \
        "{\n\t.reg .pred p;\n\t" \
        "mbarrier.try_wait.parity.acquire.cta.shared::cta.b64 p, [%1], %2;\n\t" \
        "selp.b32 %0, 1, 0, p;\n\t}" \
        : "=r"(_done) : "r"(_m), "r"(_p) : "memory"); \
    if (!_done) { \
        asm volatile( \
            "{\n\t.reg .pred P1;\n\t" \
            "WAIT_LOOP_%=:\n\t" \
            "mbarrier.try_wait.parity.acquire.cta.shared::cta.b64 P1, [%0], %1, 0x989680;\n\t" \
            "@P1 bra.uni WAIT_DONE_%=;\n\t" \
            "bra.uni WAIT_LOOP_%=;\n\t" \
            "WAIT_DONE_%=:\n\t}" \
            :: "r"(_m), "r"(_p) : "memory"); \
    } \
} while (0)

// ===========================================================================
// fp16 mma GEMM: C[M,N] = A[M,K] @ Bt[N,K]^T (half, K-major).
// 256x128 CTA tile, warp tile 64x64 (8 warps 4x2), BK=64, 3-stage cp.async.
// M%256==0, N%128==0, K%64==0, K/64>=2. OUT_HALF: store half, else float.
// ===========================================================================
#define GEMM_STAGES 3
#define STAGE_BYTES 49152            // A 32KB + B 16KB
#define GEMM_SMEM (GEMM_STAGES * STAGE_BYTES)  // 147456

template<int OUT_HALF>
__global__ __launch_bounds__(256) void gemm_f16_mma(
    const __half* __restrict__ A, const __half* __restrict__ Bt,
    void* __restrict__ Cv, int M, int N, int K)
{
    extern __shared__ __align__(1024) char smem[];
    const uint32_t sb = smem_u32(smem);

    const int tid  = threadIdx.x;
    const int lane = tid & 31;
    const int wid  = tid >> 5;
    const int wm   = (wid & 3) * 64;   // warp M offset (0..192)
    const int wn   = (wid >> 2) * 64;  // warp N offset (0/64)

    const int m0 = blockIdx.y * 256;
    const int n0 = blockIdx.x * 128;
    const __half* Ag = A  + (size_t)m0 * K;
    const __half* Bg = Bt + (size_t)n0 * K;
    const int T = K / 64;

    auto load_stage = [&](int t, int s) {
        if (t < T) {
            const uint32_t baseA = sb + (uint32_t)s * STAGE_BYTES;
            const uint32_t baseB = baseA + 32768;
            const int k0 = t * 64;
            #pragma unroll
            for (int i = 0; i < 8; i++) {          // A: 256 rows x 8 chunks
                int slot = i * 256 + tid;
                int row = slot >> 3, c = slot & 7;
                cp_async16(swz(baseA, row, c, 128),
                           Ag + (size_t)row * K + k0 + c * 8);
            }
            #pragma unroll
            for (int i = 0; i < 4; i++) {          // B: 128 rows x 8 chunks
                int slot = i * 256 + tid;
                int row = slot >> 3, c = slot & 7;
                cp_async16(swz(baseB, row, c, 128),
                           Bg + (size_t)row * K + k0 + c * 8);
            }
        }
        asm volatile("cp.async.commit_group;" ::: "memory");
    };

    float acc[4][8][4];
    #pragma unroll
    for (int mt = 0; mt < 4; mt++)
        #pragma unroll
        for (int nt = 0; nt < 8; nt++)
            #pragma unroll
            for (int q = 0; q < 4; q++) acc[mt][nt][q] = 0.f;

    load_stage(0, 0);
    load_stage(1, 1);

    const int a_row16 = lane & 15;
    const int a_ch    = lane >> 4;
    const int b_row   = (lane & 7) + (lane >> 4) * 8;
    const int b_ch    = (lane >> 3) & 1;

    for (int t = 0; t < T; t++) {
        const int s = t % GEMM_STAGES;
        asm volatile("cp.async.wait_group 1;" ::: "memory");
        __syncthreads();

        load_stage(t + 2, (t + 2) % GEMM_STAGES);

        const uint32_t baseA = sb + (uint32_t)s * STAGE_BYTES;
        const uint32_t baseB = baseA + 32768;

        #pragma unroll
        for (int k16 = 0; k16 < 4; k16++) {
            uint32_t afr[4][4], bfr[4][4];
            #pragma unroll
            for (int mt = 0; mt < 4; mt++)
                ldsm4(afr[mt][0], afr[mt][1], afr[mt][2], afr[mt][3],
                      swz(baseA, wm + mt * 16 + a_row16, k16 * 2 + a_ch, 128));
            #pragma unroll
            for (int np = 0; np < 4; np++)
                ldsm4(bfr[np][0], bfr[np][1], bfr[np][2], bfr[np][3],
                      swz(baseB, wn + np * 16 + b_row, k16 * 2 + b_ch, 128));
            #pragma unroll
            for (int mt = 0; mt < 4; mt++)
                #pragma unroll
                for (int nt = 0; nt < 8; nt++) {
                    uint32_t b2[2] = { bfr[nt >> 1][(nt & 1) * 2],
                                       bfr[nt >> 1][(nt & 1) * 2 + 1] };
                    mma_f16(acc[mt][nt], afr[mt], b2);
                }
        }
    }

    const int g = lane >> 2;
    const int tg = lane & 3;
    #pragma unroll
    for (int mt = 0; mt < 4; mt++) {
        int row0 = m0 + wm + mt * 16 + g;
        #pragma unroll
        for (int nt = 0; nt < 8; nt++) {
            int col = n0 + wn + nt * 8 + tg * 2;
            if (OUT_HALF) {
                __half* C = (__half*)Cv;
                *(uint32_t*)(C + (size_t)row0 * N + col) =
                    pack_h2(acc[mt][nt][0], acc[mt][nt][1]);
                *(uint32_t*)(C + (size_t)(row0 + 8) * N + col) =
                    pack_h2(acc[mt][nt][2], acc[mt][nt][3]);
            } else {
                float* C = (float*)Cv;
                *(float2*)(C + (size_t)row0 * N + col) =
                    make_float2(acc[mt][nt][0], acc[mt][nt][1]);
                *(float2*)(C + (size_t)(row0 + 8) * N + col) =
                    make_float2(acc[mt][nt][2], acc[mt][nt][3]);
            }
        }
    }
}

// ===========================================================================
// Pre-passes
// ===========================================================================
__global__ __launch_bounds__(256) void conv_half_kernel(
    const float* __restrict__ in, __half* __restrict__ out, size_t n4)
{
    size_t i = (size_t)blockIdx.x * blockDim.x + threadIdx.x;
    size_t stride = (size_t)gridDim.x * blockDim.x;
    for (; i < n4; i += stride) {
        float4 v = ((const float4*)in)[i];
        uint2 o;
        o.x = pack_h2(v.x, v.y);
        o.y = pack_h2(v.z, v.w);
        ((uint2*)out)[i] = o;
    }
}

__global__ __launch_bounds__(256) void transpose_h_kernel(
    const float* __restrict__ in, __half* __restrict__ out, int R, int C)
{
    __shared__ float tile[32][33];
    const int bx = blockIdx.x * 32, by = blockIdx.y * 32;
    const int tx = threadIdx.x, ty = threadIdx.y;
    #pragma unroll
    for (int i = 0; i < 32; i += 8)
        tile[ty + i][tx] = in[(size_t)(by + ty + i) * C + bx + tx];
    __syncthreads();
    #pragma unroll
    for (int i = 0; i < 32; i += 8)
        out[(size_t)(bx + ty + i) * R + by + tx] = __float2half_rn(tile[tx][ty + i]);
}

__global__ __launch_bounds__(256) void v_transpose_h_kernel(
    const __half* __restrict__ qkvh, __half* __restrict__ vT)
{
    __shared__ __half tile[32][34];
    const int bx = blockIdx.x * 32;   // c block
    const int by = blockIdx.y * 32;   // s block
    const int tx = threadIdx.x, ty = threadIdx.y;
    #pragma unroll
    for (int i = 0; i < 32; i += 8)
        tile[ty + i][tx] = qkvh[(size_t)(by + ty + i) * QKVW + 2 * DIM + bx + tx];
    __syncthreads();
    #pragma unroll
    for (int i = 0; i < 32; i += 8)
        vT[(size_t)(bx + ty + i) * SEQ + by + tx] = tile[tx][ty + i];
}

// ===========================================================================
// Flash attention, fp16 mma, PAIR-SPLIT PV.
// 256 threads (8 warps), 128 queries x 1 head per CTA, 64-key tiles.
// S-phase: warp w owns softmax rows [w*16, w*16+16) (all 64 keys).
// PV-phase: warp pair p = w>>1 owns rows [32p, 32p+32); each warp of the
//   pair takes 64 of the 128 V columns. PV gating uses ABSOLUTE rows
//   (pvabs = qb*128 + pvrow0) — R8's bug was comparing against relative rows.
// smem: 3 stages x 32KB + PS 16KB + FS 512B + mbars = 115264 B
// ===========================================================================
#define FLASH_SMEM 115264

__global__ __launch_bounds__(256, 1) void flash_mma_kernel(
    const __half* __restrict__ qkv, const __half* __restrict__ vT,
    __half* __restrict__ O)
{
    extern __shared__ __align__(1024) char smem[];
    const uint32_t sb  = smem_u32(smem);
    const uint32_t PS  = sb + 98304u;            // 16KB P tile (128 x 128B)
    const uint32_t FS  = sb + 114688u;           // 512B f/l strip (128 floats)
    const uint32_t MB  = sb + 115200u;           // full[s]=MB+8s, empty[s]=MB+24+8s

    const int tid  = threadIdx.x;
    const int lane = tid & 31;
    const int wid  = tid >> 5;
    const int pair = wid >> 1;          // 0..3
    const int sub  = wid & 1;           // V column half
    const int vcol0  = sub * 64;
    const int pvrow0 = pair * 32;       // tile-relative
    const int qb   = 31 - blockIdx.x;   // heavy blocks first
    const int h    = blockIdx.y;
    const float scale2 = 0.12751879652672068f;   // (1/sqrt(128)) * log2(e)

    const int a_row16 = lane & 15;
    const int a_ch    = lane >> 4;
    const int b_row   = (lane & 7) + (lane >> 4) * 8;
    const int b_ch    = (lane >> 3) & 1;
    const int g       = lane >> 2;
    const int tg      = lane & 3;

    // ---- Stage Q tile (128 x 256B rows, 32KB) into stage0 region
    {
        const __half* Qg = qkv + (size_t)(qb * 128) * QKVW + h * HD;
        #pragma unroll
        for (int i = 0; i < 8; i++) {
            int slot = i * 256 + tid;
            int r = slot >> 4, c = slot & 15;
            cp_async16(swz(sb, r, c, 256), Qg + (size_t)r * QKVW + c * 8);
        }
        asm volatile("cp.async.commit_group;" ::: "memory");
        asm volatile("cp.async.wait_group 0;" ::: "memory");
        __syncthreads();
    }
    uint32_t qf[8][4];
    #pragma unroll
    for (int k16 = 0; k16 < 8; k16++)
        ldsm4(qf[k16][0], qf[k16][1], qf[k16][2], qf[k16][3],
              swz(sb, wid * 16 + a_row16, k16 * 2 + a_ch, 256));
    __syncthreads();

    if (tid == 0) {
        #pragma unroll
        for (int s = 0; s < 3; s++) {
            MBARRIER_INIT(MB + 8 * s, 256);        // full[s]
            MBARRIER_INIT(MB + 24 + 8 * s, 256);   // empty[s]
        }
    }
    __syncthreads();

    float oacc[2][8][4];                 // 32 rows x 64 V-cols per warp
    #pragma unroll
    for (int mt = 0; mt < 2; mt++)
        #pragma unroll
        for (int nt = 0; nt < 8; nt++)
            #pragma unroll
            for (int q = 0; q < 4; q++) oacc[mt][nt][q] = 0.f;
    float m0 = -1e30f, m1 = -1e30f, l0 = 0.f, l1 = 0.f;

    const int kb_end = min(2 * qb + 2, 63);
    const int qi0   = qb * 128 + wid * 16;          // absolute softmax rows
    const int pvabs = qb * 128 + pvrow0;            // absolute PV row base

    auto load_tile = [&](int t, int st) {
        const uint32_t KSb  = sb + (uint32_t)st * 32768u;
        const uint32_t VTSb = KSb + 16384u;
        const __half* Kg = qkv + (size_t)(t * 64) * QKVW + DIM + h * HD;
        const __half* Vg = vT + (size_t)(h * HD) * SEQ + t * 64;
        #pragma unroll
        for (int i = 0; i < 4; i++) {
            int slot = i * 256 + tid;
            int r = slot >> 4, c = slot & 15;            // K: 64 rows x 16 chunks
            cp_async16(swz(KSb, r, c, 256), Kg + (size_t)r * QKVW + c * 8);
        }
        #pragma unroll
        for (int i = 0; i < 4; i++) {
            int slot = i * 256 + tid;
            int r = slot >> 3, c = slot & 7;             // VT: 128 rows x 8 chunks
            cp_async16(swz(VTSb, r, c, 128), Vg + (size_t)r * SEQ + c * 8);
        }
    };

    load_tile(0, 0); CPASYNC_MBAR_ARRIVE(MB + 0);
    load_tile(1, 1); CPASYNC_MBAR_ARRIVE(MB + 8);

    for (int kb = 0; kb <= kb_end; kb++) {
        // ---- producer: tile kb+2 into stage (kb+2)%3
        {
            const int t = kb + 2;
            if (t <= kb_end) {
                const int st = t % 3;
                if (t >= 3)
                    MBARRIER_WAIT_PARITY(MB + 24 + 8 * st, (uint32_t)((t / 3 - 1) & 1));
                load_tile(t, st);
                CPASYNC_MBAR_ARRIVE(MB + 8 * st);
            }
        }

        const int s  = kb % 3;
        const int ph = (kb / 3) & 1;
        MBARRIER_WAIT_PARITY(MB + 8 * s, (uint32_t)ph);

        const uint32_t KSb  = sb + (uint32_t)s * 32768u;
        const uint32_t VTSb = KSb + 16384u;

        // ============ S phase (own 16 rows) ============
        const bool sactive = (kb * 64 <= qi0 + 16);
        float f0 = 1.f, f1 = 1.f;
        float sacc[8][4];
        float rs0 = 0.f, rs1 = 0.f;
        if (sactive) {
            #pragma unroll
            for (int nt = 0; nt < 8; nt++)
                #pragma unroll
                for (int q = 0; q < 4; q++) sacc[nt][q] = 0.f;
            #pragma unroll
            for (int k16 = 0; k16 < 8; k16++) {
                uint32_t bfr[4][4];
                #pragma unroll
                for (int np = 0; np < 4; np++)
                    ldsm4(bfr[np][0], bfr[np][1], bfr[np][2], bfr[np][3],
                          swz(KSb, np * 16 + b_row, k16 * 2 + b_ch, 256));
                #pragma unroll
                for (int nt = 0; nt < 8; nt++) {
                    uint32_t b2[2] = { bfr[nt >> 1][(nt & 1) * 2],
                                       bfr[nt >> 1][(nt & 1) * 2 + 1] };
                    mma_f16(sacc[nt], qf[k16], b2);
                }
            }

            const int row0 = qi0 + g, row1 = qi0 + g + 8;
            const bool nomask = (kb * 64 + 63 <= qi0 + 1);
            float mx0 = -1e30f, mx1 = -1e30f;
            if (nomask) {
                #pragma unroll
                for (int nt = 0; nt < 8; nt++)
                    #pragma unroll
                    for (int c = 0; c < 2; c++) {
                        float v0 = sacc[nt][c] * scale2;
                        float v1 = sacc[nt][c + 2] * scale2;
                        sacc[nt][c] = v0; sacc[nt][c + 2] = v1;
                        mx0 = fmaxf(mx0, v0); mx1 = fmaxf(mx1, v1);
                    }
            } else {
                #pragma unroll
                for (int nt = 0; nt < 8; nt++)
                    #pragma unroll
                    for (int c = 0; c < 2; c++) {
                        int kj = kb * 64 + nt * 8 + tg * 2 + c;
                        float v0 = (kj <= row0 + 1) ? sacc[nt][c] * scale2 : -1e30f;
                        float v1 = (kj <= row1 + 1) ? sacc[nt][c + 2] * scale2 : -1e30f;
                        sacc[nt][c] = v0; sacc[nt][c + 2] = v1;
                        mx0 = fmaxf(mx0, v0); mx1 = fmaxf(mx1, v1);
                    }
            }
            mx0 = fmaxf(mx0, __shfl_xor_sync(0xffffffffu, mx0, 1));
            mx0 = fmaxf(mx0, __shfl_xor_sync(0xffffffffu, mx0, 2));
            mx1 = fmaxf(mx1, __shfl_xor_sync(0xffffffffu, mx1, 1));
            mx1 = fmaxf(mx1, __shfl_xor_sync(0xffffffffu, mx1, 2));

            float newm0 = fmaxf(m0, mx0), newm1 = fmaxf(m1, mx1);
            f0 = exp2f(m0 - newm0); f1 = exp2f(m1 - newm1);
            m0 = newm0; m1 = newm1;

            #pragma unroll
            for (int nt = 0; nt < 8; nt++)
                #pragma unroll
                for (int c = 0; c < 2; c++) {
                    float p0 = exp2f(sacc[nt][c] - newm0);
                    float p1 = exp2f(sacc[nt][c + 2] - newm1);
                    sacc[nt][c] = p0; sacc[nt][c + 2] = p1;
                    rs0 += p0; rs1 += p1;
                }
        }

        // barA: partner finished PV(kb-1) -> PS/FS rows reusable
        bar_pair(1 + pair);

        if (sactive) {
            const int r0 = wid * 16 + g, r1 = r0 + 8;
            #pragma unroll
            for (int nt = 0; nt < 8; nt++) {
                uint32_t byte_in = (uint32_t)(tg * 4);
                asm volatile("st.shared.u32 [%0], %1;"
                    :: "r"(swz(PS, r0, nt, 128) + byte_in),
                       "r"(pack_h2(sacc[nt][0], sacc[nt][1])));
                asm volatile("st.shared.u32 [%0], %1;"
                    :: "r"(swz(PS, r1, nt, 128) + byte_in),
                       "r"(pack_h2(sacc[nt][2], sacc[nt][3])));
            }
        }
        if (tg == 0) {                        // publish per-row rescale factor
            sts_f32(FS + (uint32_t)(wid * 16 + g) * 4, f0);
            sts_f32(FS + (uint32_t)(wid * 16 + 8 + g) * 4, f1);
        }
        if (sactive) {
            rs0 += __shfl_xor_sync(0xffffffffu, rs0, 1);
            rs0 += __shfl_xor_sync(0xffffffffu, rs0, 2);
            rs1 += __shfl_xor_sync(0xffffffffu, rs1, 1);
            rs1 += __shfl_xor_sync(0xffffffffu, rs1, 2);
            l0 = l0 * f0 + rs0;
            l1 = l1 * f1 + rs1;
        }

        // barB: pair's P + f visible
        bar_pair(1 + pair);

        // ===== PV phase (pair rows [pvabs, pvabs+32), own 64 V cols) =====
        const bool act0 = (kb * 64 <= pvabs + 16);   // == partner-warp-2p sactive
        const bool act1 = (kb * 64 <= pvabs + 32);   // == partner-warp-2p+1 sactive
        if (act1) {
            // rescale oacc by per-row f (f==1 for rows whose S was skipped)
            #pragma unroll
            for (int mt = 0; mt < 2; mt++) {
                float fa = lds_f32(FS + (uint32_t)(pvrow0 + mt * 16 + g) * 4);
                float fb = lds_f32(FS + (uint32_t)(pvrow0 + mt * 16 + 8 + g) * 4);
                #pragma unroll
                for (int nt = 0; nt < 8; nt++) {
                    oacc[mt][nt][0] *= fa; oacc[mt][nt][1] *= fa;
                    oacc[mt][nt][2] *= fb; oacc[mt][nt][3] *= fb;
                }
            }
            #pragma unroll
            for (int k16 = 0; k16 < 4; k16++) {
                uint32_t bfr[4][4];
                #pragma unroll
                for (int np = 0; np < 4; np++)
                    ldsm4(bfr[np][0], bfr[np][1], bfr[np][2], bfr[np][3],
                          swz(VTSb, vcol0 + np * 16 + b_row, k16 * 2 + b_ch, 128));
                uint32_t afr0[4], afr1[4];
                if (act0)
                    ldsm4(afr0[0], afr0[1], afr0[2], afr0[3],
                          swz(PS, pvrow0 + a_row16, k16 * 2 + a_ch, 128));
                ldsm4(afr1[0], afr1[1], afr1[2], afr1[3],
                      swz(PS, pvrow0 + 16 + a_row16, k16 * 2 + a_ch, 128));
                #pragma unroll
                for (int nt = 0; nt < 8; nt++) {
                    uint32_t b2[2] = { bfr[nt >> 1][(nt & 1) * 2],
                                       bfr[nt >> 1][(nt & 1) * 2 + 1] };
                    if (act0) mma_f16(oacc[0][nt], afr0, b2);
                    mma_f16(oacc[1][nt], afr1, b2);
                }
            }
        }

        MBARRIER_ARRIVE(MB + 24 + 8 * s);
    }

    // ---- final l exchange (reuse FS strip), then normalize + store
    if (tg == 0) {
        sts_f32(FS + (uint32_t)(wid * 16 + g) * 4, l0);
        sts_f32(FS + (uint32_t)(wid * 16 + 8 + g) * 4, l1);
    }
    bar_pair(1 + pair);

    #pragma unroll
    for (int mt = 0; mt < 2; mt++) {
        float la = lds_f32(FS + (uint32_t)(pvrow0 + mt * 16 + g) * 4);
        float lb = lds_f32(FS + (uint32_t)(pvrow0 + mt * 16 + 8 + g) * 4);
        float inva = 1.f / la, invb = 1.f / lb;
        int row0 = qb * 128 + pvrow0 + mt * 16 + g;
        __half* Og = O + (size_t)row0 * DIM + h * HD + vcol0;
        #pragma unroll
        for (int nt = 0; nt < 8; nt++) {
            int col = nt * 8 + tg * 2;
            *(uint32_t*)(Og + col) =
                pack_h2(oacc[mt][nt][0] * inva, oacc[mt][nt][1] * inva);
            *(uint32_t*)(Og + (size_t)8 * DIM + col) =
                pack_h2(oacc[mt][nt][2] * invb, oacc[mt][nt][3] * invb);
        }
    }
}

// ===========================================================================
// Launch
// ===========================================================================
extern "C" void kernel_launch(void* const* d_in, const int* in_sizes, int n_in,
                              void* d_out, int out_size)
{
    const float* x     = (const float*)d_in[0];  // (4096, 2048)
    const float* w_qkv = (const float*)d_in[1];  // (2048, 6144)
    const float* w_o   = (const float*)d_in[2];  // (2048, 2048)
    float* out = (float*)d_out;                  // (4096, 2048)

    __half *qkvh, *oh, *xh, *wqkvT, *woT, *vTh;
    cudaGetSymbolAddress((void**)&qkvh,  g_qkvh);
    cudaGetSymbolAddress((void**)&oh,    g_oh);
    cudaGetSymbolAddress((void**)&xh,    g_xh);
    cudaGetSymbolAddress((void**)&wqkvT, g_wqkvT);
    cudaGetSymbolAddress((void**)&woT,   g_woT);
    cudaGetSymbolAddress((void**)&vTh,   g_vTh);

    cudaFuncSetAttribute(gemm_f16_mma<1>,
                         cudaFuncAttributeMaxDynamicSharedMemorySize, GEMM_SMEM);
    cudaFuncSetAttribute(gemm_f16_mma<0>,
                         cudaFuncAttributeMaxDynamicSharedMemorySize, GEMM_SMEM);
    cudaFuncSetAttribute(flash_mma_kernel,
                         cudaFuncAttributeMaxDynamicSharedMemorySize, FLASH_SMEM);

    // 0) convert x; transpose+convert weights
    conv_half_kernel<<<2048, 256>>>(x, xh, (size_t)SEQ * DIM / 4);
    transpose_h_kernel<<<dim3(QKVW / 32, DIM / 32), dim3(32, 8)>>>(w_qkv, wqkvT, DIM, QKVW);
    transpose_h_kernel<<<dim3(DIM / 32, DIM / 32), dim3(32, 8)>>>(w_o, woT, DIM, DIM);

    // 1) QKV projection (fp16 mma, half output): 256x128 tiles
    gemm_f16_mma<1><<<dim3(QKVW / 128, SEQ / 256), 256, GEMM_SMEM>>>(
        xh, wqkvT, qkvh, SEQ, QKVW, DIM);

    // 1b) transpose V per head
    v_transpose_h_kernel<<<dim3(DIM / 32, SEQ / 32), dim3(32, 8)>>>(qkvh, vTh);

    // 2) Attention (fp16 mma flash, pair-split PV)
    flash_mma_kernel<<<dim3(SEQ / 128, NH), 256, FLASH_SMEM>>>(qkvh, vTh, oh);

    // 3) Output projection (fp16 mma, float output): 256x128 tiles
    gemm_f16_mma<0><<<dim3(DIM / 128, SEQ / 256), 256, GEMM_SMEM>>>(
        oh, woT, out, SEQ, DIM, DIM);
}

// round 10
// speedup vs baseline: 1.1735x; 1.1735x over previous
#include <cuda_runtime.h>
#include <cuda_fp16.h>
#include <cstdint>
#include <cstddef>

// Problem constants
#define SEQ   4096
#define DIM   2048
#define NH    16
#define HD    128
#define QKVW  (3 * DIM)   // 6144

// Scratch (device globals: allocation-free per harness rules)
__device__ __half g_qkvh [(size_t)SEQ * QKVW];  // (S, 3*dim) fp16
__device__ __half g_oh   [(size_t)SEQ * DIM];   // attention out fp16
__device__ __half g_xh   [(size_t)SEQ * DIM];   // x fp16
__device__ __half g_wqkvT[(size_t)QKVW * DIM];  // w_qkv^T fp16 (6144, 2048)
__device__ __half g_woT  [(size_t)DIM * DIM];   // w_o^T fp16
__device__ __half g_vTh  [(size_t)DIM * SEQ];   // V^T fp16: [h*128+d][s]

// ===========================================================================
// Helpers
// ===========================================================================
__device__ __forceinline__ uint32_t smem_u32(const void* p) {
    uint32_t a;
    asm("{ .reg .u64 t; cvta.to.shared.u64 t, %1; cvt.u32.u64 %0, t; }"
        : "=r"(a) : "l"(p));
    return a;
}

__device__ __forceinline__ uint32_t pack_h2(float lo, float hi) {
    __half2 h = __floats2half2_rn(lo, hi);
    return *(uint32_t*)&h;
}

__device__ __forceinline__ void cp_async16(uint32_t dst, const void* src) {
    asm volatile("cp.async.cg.shared.global [%0], [%1], 16;"
                 :: "r"(dst), "l"(src));
}

__device__ __forceinline__ void ldsm4(uint32_t& r0, uint32_t& r1,
                                      uint32_t& r2, uint32_t& r3, uint32_t addr) {
    asm volatile("ldmatrix.sync.aligned.m8n8.x4.shared.b16 {%0,%1,%2,%3}, [%4];"
                 : "=r"(r0), "=r"(r1), "=r"(r2), "=r"(r3) : "r"(addr));
}

__device__ __forceinline__ void mma_f16(float* c, const uint32_t* a, const uint32_t* b) {
    asm volatile(
        "mma.sync.aligned.m16n8k16.row.col.f32.f16.f16.f32 "
        "{%0,%1,%2,%3}, {%4,%5,%6,%7}, {%8,%9}, {%0,%1,%2,%3};"
        : "+f"(c[0]), "+f"(c[1]), "+f"(c[2]), "+f"(c[3])
        : "r"(a[0]), "r"(a[1]), "r"(a[2]), "r"(a[3]), "r"(b[0]), "r"(b[1]));
}

// swizzled smem address: row of RS bytes, 16B chunk c16, XOR low3 with row&7
__device__ __forceinline__ uint32_t swz(uint32_t base, int row, int c16, int rs_bytes) {
    return base + (uint32_t)row * (uint32_t)rs_bytes
                + ((uint32_t)(c16 ^ (row & 7)) << 4);
}

// ---- mbarrier primitives (base ISA) ----
#define MBARRIER_INIT(mbar, cnt) \
    asm volatile("mbarrier.init.shared.b64 [%0], %1;" \
        :: "r"((uint32_t)(mbar)), "r"((uint32_t)(cnt)) : "memory")

#define MBARRIER_ARRIVE(mbar) \
    asm volatile("mbarrier.arrive.shared.b64 _, [%0];" \
        :: "r"((uint32_t)(mbar)) : "memory")

#define CPASYNC_MBAR_ARRIVE(mbar) \
    asm volatile("cp.async.mbarrier.arrive.noinc.shared.b64 [%0];" \
        :: "r"((uint32_t)(mbar)) : "memory")

#define MBARRIER_WAIT_PARITY(mbar, parity) do { \
    uint32_t _m = (uint32_t)(mbar); \
    uint32_t _p = (uint32_t)(parity); \
    uint32_t _done; \
    asm volatile( \
        "{\n\t.reg .pred p;\n\t" \
        "mbarrier.try_wait.parity.acquire.cta.shared::cta.b64 p, [%1], %2;\n\t" \
        "selp.b32 %0, 1, 0, p;\n\t}" \
        : "=r"(_done) : "r"(_m), "r"(_p) : "memory"); \
    if (!_done) { \
        asm volatile( \
            "{\n\t.reg .pred P1;\n\t" \
            "WAIT_LOOP_%=:\n\t" \
            "mbarrier.try_wait.parity.acquire.cta.shared::cta.b64 P1, [%0], %1, 0x989680;\n\t" \
            "@P1 bra.uni WAIT_DONE_%=;\n\t" \
            "bra.uni WAIT_LOOP_%=;\n\t" \
            "WAIT_DONE_%=:\n\t}" \
            :: "r"(_m), "r"(_p) : "memory"); \
    } \
} while (0)

// ===========================================================================
// fp16 mma GEMM (R7 config): C[M,N] = A[M,K] @ Bt[N,K]^T (half, K-major).
// 128x128 CTA tile, BK=64 (128B rows), 3-stage cp.async, 256 threads (4x2).
// OUT_HALF: store half, else float.
// ===========================================================================
#define GEMM_STAGES 3
#define STAGE_BYTES 32768            // A 16KB + B 16KB
#define GEMM_SMEM (GEMM_STAGES * STAGE_BYTES)  // 98304

template<int OUT_HALF>
__global__ __launch_bounds__(256) void gemm_f16_mma(
    const __half* __restrict__ A, const __half* __restrict__ Bt,
    void* __restrict__ Cv, int M, int N, int K)
{
    extern __shared__ __align__(1024) char smem[];
    const uint32_t sb = smem_u32(smem);

    const int tid  = threadIdx.x;
    const int lane = tid & 31;
    const int wid  = tid >> 5;
    const int wm   = (wid & 3) * 32;
    const int wn   = (wid >> 2) * 64;

    const int m0 = blockIdx.y * 128;
    const int n0 = blockIdx.x * 128;
    const __half* Ag = A  + (size_t)m0 * K;
    const __half* Bg = Bt + (size_t)n0 * K;
    const int T = K / 64;

    auto load_stage = [&](int t, int s) {
        if (t < T) {
            const uint32_t baseA = sb + (uint32_t)s * STAGE_BYTES;
            const uint32_t baseB = baseA + 16384;
            const int k0 = t * 64;
            #pragma unroll
            for (int i = 0; i < 4; i++) {
                int slot = i * 256 + tid;
                int row = slot >> 3, c = slot & 7;       // 128 rows x 8 chunks
                cp_async16(swz(baseA, row, c, 128),
                           Ag + (size_t)row * K + k0 + c * 8);
                cp_async16(swz(baseB, row, c, 128),
                           Bg + (size_t)row * K + k0 + c * 8);
            }
        }
        asm volatile("cp.async.commit_group;" ::: "memory");
    };

    float acc[2][8][4];
    #pragma unroll
    for (int mt = 0; mt < 2; mt++)
        #pragma unroll
        for (int nt = 0; nt < 8; nt++)
            #pragma unroll
            for (int q = 0; q < 4; q++) acc[mt][nt][q] = 0.f;

    load_stage(0, 0);
    load_stage(1, 1);

    const int a_row16 = lane & 15;
    const int a_ch    = lane >> 4;
    const int b_row   = (lane & 7) + (lane >> 4) * 8;
    const int b_ch    = (lane >> 3) & 1;

    for (int t = 0; t < T; t++) {
        const int s = t % GEMM_STAGES;
        asm volatile("cp.async.wait_group 1;" ::: "memory");
        __syncthreads();

        load_stage(t + 2, (t + 2) % GEMM_STAGES);

        const uint32_t baseA = sb + (uint32_t)s * STAGE_BYTES;
        const uint32_t baseB = baseA + 16384;

        #pragma unroll
        for (int k16 = 0; k16 < 4; k16++) {
            uint32_t afr[2][4], bfr[4][4];
            #pragma unroll
            for (int mt = 0; mt < 2; mt++)
                ldsm4(afr[mt][0], afr[mt][1], afr[mt][2], afr[mt][3],
                      swz(baseA, wm + mt * 16 + a_row16, k16 * 2 + a_ch, 128));
            #pragma unroll
            for (int np = 0; np < 4; np++)
                ldsm4(bfr[np][0], bfr[np][1], bfr[np][2], bfr[np][3],
                      swz(baseB, wn + np * 16 + b_row, k16 * 2 + b_ch, 128));
            #pragma unroll
            for (int mt = 0; mt < 2; mt++)
                #pragma unroll
                for (int nt = 0; nt < 8; nt++) {
                    uint32_t b2[2] = { bfr[nt >> 1][(nt & 1) * 2],
                                       bfr[nt >> 1][(nt & 1) * 2 + 1] };
                    mma_f16(acc[mt][nt], afr[mt], b2);
                }
        }
    }

    const int g = lane >> 2;
    const int tg = lane & 3;
    #pragma unroll
    for (int mt = 0; mt < 2; mt++) {
        int row0 = m0 + wm + mt * 16 + g;
        #pragma unroll
        for (int nt = 0; nt < 8; nt++) {
            int col = n0 + wn + nt * 8 + tg * 2;
            if (OUT_HALF) {
                __half* C = (__half*)Cv;
                *(uint32_t*)(C + (size_t)row0 * N + col) =
                    pack_h2(acc[mt][nt][0], acc[mt][nt][1]);
                *(uint32_t*)(C + (size_t)(row0 + 8) * N + col) =
                    pack_h2(acc[mt][nt][2], acc[mt][nt][3]);
            } else {
                float* C = (float*)Cv;
                *(float2*)(C + (size_t)row0 * N + col) =
                    make_float2(acc[mt][nt][0], acc[mt][nt][1]);
                *(float2*)(C + (size_t)(row0 + 8) * N + col) =
                    make_float2(acc[mt][nt][2], acc[mt][nt][3]);
            }
        }
    }
}

// ===========================================================================
// Pre-passes
// ===========================================================================
__global__ __launch_bounds__(256) void conv_half_kernel(
    const float* __restrict__ in, __half* __restrict__ out, size_t n4)
{
    size_t i = (size_t)blockIdx.x * blockDim.x + threadIdx.x;
    size_t stride = (size_t)gridDim.x * blockDim.x;
    for (; i < n4; i += stride) {
        float4 v = ((const float4*)in)[i];
        uint2 o;
        o.x = pack_h2(v.x, v.y);
        o.y = pack_h2(v.z, v.w);
        ((uint2*)out)[i] = o;
    }
}

__global__ __launch_bounds__(256) void transpose_h_kernel(
    const float* __restrict__ in, __half* __restrict__ out, int R, int C)
{
    __shared__ float tile[32][33];
    const int bx = blockIdx.x * 32, by = blockIdx.y * 32;
    const int tx = threadIdx.x, ty = threadIdx.y;
    #pragma unroll
    for (int i = 0; i < 32; i += 8)
        tile[ty + i][tx] = in[(size_t)(by + ty + i) * C + bx + tx];
    __syncthreads();
    #pragma unroll
    for (int i = 0; i < 32; i += 8)
        out[(size_t)(bx + ty + i) * R + by + tx] = __float2half_rn(tile[tx][ty + i]);
}

__global__ __launch_bounds__(256) void v_transpose_h_kernel(
    const __half* __restrict__ qkvh, __half* __restrict__ vT)
{
    __shared__ __half tile[32][34];
    const int bx = blockIdx.x * 32;   // c block
    const int by = blockIdx.y * 32;   // s block
    const int tx = threadIdx.x, ty = threadIdx.y;
    #pragma unroll
    for (int i = 0; i < 32; i += 8)
        tile[ty + i][tx] = qkvh[(size_t)(by + ty + i) * QKVW + 2 * DIM + bx + tx];
    __syncthreads();
    #pragma unroll
    for (int i = 0; i < 32; i += 8)
        vT[(size_t)(bx + ty + i) * SEQ + by + tx] = tile[tx][ty + i];
}

// ===========================================================================
// Flash attention, fp16 mma, REGISTER-FED PV (FA2 trick).
// 256 threads (8 warps), 128 queries x 1 head per CTA, 64-key tiles.
// S accumulator fragments ARE the PV A-operand fragments:
//   a0 = pack(sacc[2k][0],sacc[2k][1]);  a1 = pack(sacc[2k][2],sacc[2k][3]);
//   a2/a3 from n-tile 2k+1.  No P smem store/load, no intra-pair barriers.
// 3 K+V stages of 32KB each + mbarrier ring. smem: 3*32768 + 64 = 98368 B
// ===========================================================================
#define FLASH_SMEM 98368

__global__ __launch_bounds__(256, 1) void flash_mma_kernel(
    const __half* __restrict__ qkv, const __half* __restrict__ vT,
    __half* __restrict__ O)
{
    extern __shared__ __align__(1024) char smem[];
    const uint32_t sb  = smem_u32(smem);
    const uint32_t MB  = sb + 98304u;            // full[s]=MB+8s, empty[s]=MB+24+8s

    const int tid  = threadIdx.x;
    const int lane = tid & 31;
    const int wid  = tid >> 5;
    const int qb   = 31 - blockIdx.x;   // heavy blocks first
    const int h    = blockIdx.y;
    const float scale2 = 0.12751879652672068f;   // (1/sqrt(128)) * log2(e)

    const int a_row16 = lane & 15;
    const int a_ch    = lane >> 4;
    const int b_row   = (lane & 7) + (lane >> 4) * 8;
    const int b_ch    = (lane >> 3) & 1;
    const int g       = lane >> 2;
    const int tg      = lane & 3;

    // ---- Stage Q tile (128 x 256B rows, 32KB) into stage0 region
    {
        const __half* Qg = qkv + (size_t)(qb * 128) * QKVW + h * HD;
        #pragma unroll
        for (int i = 0; i < 8; i++) {
            int slot = i * 256 + tid;
            int r = slot >> 4, c = slot & 15;
            cp_async16(swz(sb, r, c, 256), Qg + (size_t)r * QKVW + c * 8);
        }
        asm volatile("cp.async.commit_group;" ::: "memory");
        asm volatile("cp.async.wait_group 0;" ::: "memory");
        __syncthreads();
    }
    uint32_t qf[8][4];
    #pragma unroll
    for (int k16 = 0; k16 < 8; k16++)
        ldsm4(qf[k16][0], qf[k16][1], qf[k16][2], qf[k16][3],
              swz(sb, wid * 16 + a_row16, k16 * 2 + a_ch, 256));
    __syncthreads();   // Q extraction done before stage0 overwritten

    if (tid == 0) {
        #pragma unroll
        for (int s = 0; s < 3; s++) {
            MBARRIER_INIT(MB + 8 * s, 256);        // full[s]
            MBARRIER_INIT(MB + 24 + 8 * s, 256);   // empty[s]
        }
    }
    __syncthreads();

    float oacc[16][4];
    #pragma unroll
    for (int nt = 0; nt < 16; nt++)
        #pragma unroll
        for (int q = 0; q < 4; q++) oacc[nt][q] = 0.f;
    float m0 = -1e30f, m1 = -1e30f, l0 = 0.f, l1 = 0.f;

    const int kb_end = min(2 * qb + 2, 63);   // always >= 2
    const int qi0 = qb * 128 + wid * 16;

    // Load K+V tile t into stage st (8 cp.async per thread)
    auto load_tile = [&](int t, int st) {
        const uint32_t KSb  = sb + (uint32_t)st * 32768u;
        const uint32_t VTSb = KSb + 16384u;
        const __half* Kg = qkv + (size_t)(t * 64) * QKVW + DIM + h * HD;
        const __half* Vg = vT + (size_t)(h * HD) * SEQ + t * 64;
        #pragma unroll
        for (int i = 0; i < 4; i++) {
            int slot = i * 256 + tid;
            int r = slot >> 4, c = slot & 15;            // K: 64 rows x 16 chunks
            cp_async16(swz(KSb, r, c, 256), Kg + (size_t)r * QKVW + c * 8);
        }
        #pragma unroll
        for (int i = 0; i < 4; i++) {
            int slot = i * 256 + tid;
            int r = slot >> 3, c = slot & 7;             // VT: 128 rows x 8 chunks
            cp_async16(swz(VTSb, r, c, 128), Vg + (size_t)r * SEQ + c * 8);
        }
    };

    // prologue: tiles 0 and 1 (generation 0 — no empty wait needed)
    load_tile(0, 0); CPASYNC_MBAR_ARRIVE(MB + 0);
    load_tile(1, 1); CPASYNC_MBAR_ARRIVE(MB + 8);

    for (int kb = 0; kb <= kb_end; kb++) {
        // ---- producer: tile kb+2 into stage (kb+2)%3
        {
            const int t = kb + 2;
            if (t <= kb_end) {
                const int st = t % 3;
                if (t >= 3)
                    MBARRIER_WAIT_PARITY(MB + 24 + 8 * st, (uint32_t)((t / 3 - 1) & 1));
                load_tile(t, st);
                CPASYNC_MBAR_ARRIVE(MB + 8 * st);
            }
        }

        const int s  = kb % 3;
        const int ph = (kb / 3) & 1;
        MBARRIER_WAIT_PARITY(MB + 8 * s, (uint32_t)ph);   // K+V tile kb resident

        const bool skipw = (kb * 64 > qi0 + 16);   // fully masked for this warp
        if (!skipw) {
            const uint32_t KSb  = sb + (uint32_t)s * 32768u;
            const uint32_t VTSb = KSb + 16384u;

            // ---- S = Q @ K^T  (m16 per warp, n64, k128)
            float sacc[8][4];
            #pragma unroll
            for (int nt = 0; nt < 8; nt++)
                #pragma unroll
                for (int q = 0; q < 4; q++) sacc[nt][q] = 0.f;

            #pragma unroll
            for (int k16 = 0; k16 < 8; k16++) {
                uint32_t bfr[4][4];
                #pragma unroll
                for (int np = 0; np < 4; np++)
                    ldsm4(bfr[np][0], bfr[np][1], bfr[np][2], bfr[np][3],
                          swz(KSb, np * 16 + b_row, k16 * 2 + b_ch, 256));
                #pragma unroll
                for (int nt = 0; nt < 8; nt++) {
                    uint32_t b2[2] = { bfr[nt >> 1][(nt & 1) * 2],
                                       bfr[nt >> 1][(nt & 1) * 2 + 1] };
                    mma_f16(sacc[nt], qf[k16], b2);
                }
            }

            // ---- online softmax in exp2 domain (rows qi0+g, qi0+g+8)
            const int row0 = qi0 + g, row1 = qi0 + g + 8;
            const bool nomask = (kb * 64 + 63 <= qi0 + 1);
            float mx0 = -1e30f, mx1 = -1e30f;
            if (nomask) {
                #pragma unroll
                for (int nt = 0; nt < 8; nt++)
                    #pragma unroll
                    for (int c = 0; c < 2; c++) {
                        float v0 = sacc[nt][c] * scale2;
                        float v1 = sacc[nt][c + 2] * scale2;
                        sacc[nt][c] = v0; sacc[nt][c + 2] = v1;
                        mx0 = fmaxf(mx0, v0); mx1 = fmaxf(mx1, v1);
                    }
            } else {
                #pragma unroll
                for (int nt = 0; nt < 8; nt++)
                    #pragma unroll
                    for (int c = 0; c < 2; c++) {
                        int kj = kb * 64 + nt * 8 + tg * 2 + c;
                        float v0 = (kj <= row0 + 1) ? sacc[nt][c] * scale2 : -1e30f;
                        float v1 = (kj <= row1 + 1) ? sacc[nt][c + 2] * scale2 : -1e30f;
                        sacc[nt][c] = v0; sacc[nt][c + 2] = v1;
                        mx0 = fmaxf(mx0, v0); mx1 = fmaxf(mx1, v1);
                    }
            }
            mx0 = fmaxf(mx0, __shfl_xor_sync(0xffffffffu, mx0, 1));
            mx0 = fmaxf(mx0, __shfl_xor_sync(0xffffffffu, mx0, 2));
            mx1 = fmaxf(mx1, __shfl_xor_sync(0xffffffffu, mx1, 1));
            mx1 = fmaxf(mx1, __shfl_xor_sync(0xffffffffu, mx1, 2));

            float newm0 = fmaxf(m0, mx0), newm1 = fmaxf(m1, mx1);
            float f0 = exp2f(m0 - newm0), f1 = exp2f(m1 - newm1);
            m0 = newm0; m1 = newm1;

            float rs0 = 0.f, rs1 = 0.f;
            #pragma unroll
            for (int nt = 0; nt < 8; nt++)
                #pragma unroll
                for (int c = 0; c < 2; c++) {
                    float p0 = exp2f(sacc[nt][c] - newm0);
                    float p1 = exp2f(sacc[nt][c + 2] - newm1);
                    sacc[nt][c] = p0; sacc[nt][c + 2] = p1;
                    rs0 += p0; rs1 += p1;
                }
            rs0 += __shfl_xor_sync(0xffffffffu, rs0, 1);
            rs0 += __shfl_xor_sync(0xffffffffu, rs0, 2);
            rs1 += __shfl_xor_sync(0xffffffffu, rs1, 1);
            rs1 += __shfl_xor_sync(0xffffffffu, rs1, 2);
            l0 = l0 * f0 + rs0;
            l1 = l1 * f1 + rs1;

            #pragma unroll
            for (int nt = 0; nt < 16; nt++) {
                oacc[nt][0] *= f0; oacc[nt][1] *= f0;
                oacc[nt][2] *= f1; oacc[nt][3] *= f1;
            }

            // ---- O += P @ V  (A fragments packed directly from sacc)
            #pragma unroll
            for (int k16 = 0; k16 < 4; k16++) {
                uint32_t afr[4];
                afr[0] = pack_h2(sacc[2 * k16][0],     sacc[2 * k16][1]);
                afr[1] = pack_h2(sacc[2 * k16][2],     sacc[2 * k16][3]);
                afr[2] = pack_h2(sacc[2 * k16 + 1][0], sacc[2 * k16 + 1][1]);
                afr[3] = pack_h2(sacc[2 * k16 + 1][2], sacc[2 * k16 + 1][3]);
                #pragma unroll
                for (int np = 0; np < 8; np++) {
                    uint32_t bfr[4];
                    ldsm4(bfr[0], bfr[1], bfr[2], bfr[3],
                          swz(VTSb, np * 16 + b_row, k16 * 2 + b_ch, 128));
                    uint32_t b2a[2] = { bfr[0], bfr[1] };
                    uint32_t b2b[2] = { bfr[2], bfr[3] };
                    mma_f16(oacc[np * 2 + 0], afr, b2a);
                    mma_f16(oacc[np * 2 + 1], afr, b2b);
                }
            }
        }

        MBARRIER_ARRIVE(MB + 24 + 8 * s);   // done with stage s this generation
    }

    // ---- epilogue: normalize, store half (GEMM2 consumes fp16)
    const float inv0 = 1.f / l0, inv1 = 1.f / l1;
    const int row0 = qb * 128 + wid * 16 + g;
    __half* Og = O + (size_t)row0 * DIM + h * HD;
    #pragma unroll
    for (int nt = 0; nt < 16; nt++) {
        int col = nt * 8 + tg * 2;
        *(uint32_t*)(Og + col) = pack_h2(oacc[nt][0] * inv0, oacc[nt][1] * inv0);
        *(uint32_t*)(Og + (size_t)8 * DIM + col) =
            pack_h2(oacc[nt][2] * inv1, oacc[nt][3] * inv1);
    }
}

// ===========================================================================
// Launch
// ===========================================================================
extern "C" void kernel_launch(void* const* d_in, const int* in_sizes, int n_in,
                              void* d_out, int out_size)
{
    const float* x     = (const float*)d_in[0];  // (4096, 2048)
    const float* w_qkv = (const float*)d_in[1];  // (2048, 6144)
    const float* w_o   = (const float*)d_in[2];  // (2048, 2048)
    float* out = (float*)d_out;                  // (4096, 2048)

    __half *qkvh, *oh, *xh, *wqkvT, *woT, *vTh;
    cudaGetSymbolAddress((void**)&qkvh,  g_qkvh);
    cudaGetSymbolAddress((void**)&oh,    g_oh);
    cudaGetSymbolAddress((void**)&xh,    g_xh);
    cudaGetSymbolAddress((void**)&wqkvT, g_wqkvT);
    cudaGetSymbolAddress((void**)&woT,   g_woT);
    cudaGetSymbolAddress((void**)&vTh,   g_vTh);

    cudaFuncSetAttribute(gemm_f16_mma<1>,
                         cudaFuncAttributeMaxDynamicSharedMemorySize, GEMM_SMEM);
    cudaFuncSetAttribute(gemm_f16_mma<0>,
                         cudaFuncAttributeMaxDynamicSharedMemorySize, GEMM_SMEM);
    cudaFuncSetAttribute(flash_mma_kernel,
                         cudaFuncAttributeMaxDynamicSharedMemorySize, FLASH_SMEM);

    // 0) convert x; transpose+convert weights
    conv_half_kernel<<<2048, 256>>>(x, xh, (size_t)SEQ * DIM / 4);
    transpose_h_kernel<<<dim3(QKVW / 32, DIM / 32), dim3(32, 8)>>>(w_qkv, wqkvT, DIM, QKVW);
    transpose_h_kernel<<<dim3(DIM / 32, DIM / 32), dim3(32, 8)>>>(w_o, woT, DIM, DIM);

    // 1) QKV projection (fp16 mma, half output): 128x128 tiles (R7 config)
    gemm_f16_mma<1><<<dim3(QKVW / 128, SEQ / 128), 256, GEMM_SMEM>>>(
        xh, wqkvT, qkvh, SEQ, QKVW, DIM);

    // 1b) transpose V per head
    v_transpose_h_kernel<<<dim3(DIM / 32, SEQ / 32), dim3(32, 8)>>>(qkvh, vTh);

    // 2) Attention (fp16 mma flash, register-fed PV)
    flash_mma_kernel<<<dim3(SEQ / 128, NH), 256, FLASH_SMEM>>>(qkvh, vTh, oh);

    // 3) Output projection (fp16 mma, float output)
    gemm_f16_mma<0><<<dim3(DIM / 128, SEQ / 128), 256, GEMM_SMEM>>>(
        oh, woT, out, SEQ, DIM, DIM);
}

// round 11
// speedup vs baseline: 1.1781x; 1.0039x over previous
#include <cuda_runtime.h>
#include <cuda_fp16.h>
#include <cstdint>
#include <cstddef>

// Problem constants
#define SEQ   4096
#define DIM   2048
#define NH    16
#define HD    128
#define QKVW  (3 * DIM)   // 6144

// Scratch (device globals: allocation-free per harness rules)
__device__ __half g_qkvh [(size_t)SEQ * QKVW];  // (S, 3*dim) fp16
__device__ __half g_oh   [(size_t)SEQ * DIM];   // attention out fp16
__device__ __half g_xh   [(size_t)SEQ * DIM];   // x fp16
__device__ __half g_wqkvT[(size_t)QKVW * DIM];  // w_qkv^T fp16 (6144, 2048)
__device__ __half g_woT  [(size_t)DIM * DIM];   // w_o^T fp16

// ===========================================================================
// Helpers
// ===========================================================================
__device__ __forceinline__ uint32_t smem_u32(const void* p) {
    uint32_t a;
    asm("{ .reg .u64 t; cvta.to.shared.u64 t, %1; cvt.u32.u64 %0, t; }"
        : "=r"(a) : "l"(p));
    return a;
}

__device__ __forceinline__ uint32_t pack_h2(float lo, float hi) {
    __half2 h = __floats2half2_rn(lo, hi);
    return *(uint32_t*)&h;
}

__device__ __forceinline__ uint32_t exp2_h2(float lo, float hi) {
    __half2 h = h2exp2(__floats2half2_rn(lo, hi));
    return *(uint32_t*)&h;
}

__device__ __forceinline__ void cp_async16(uint32_t dst, const void* src) {
    asm volatile("cp.async.cg.shared.global [%0], [%1], 16;"
                 :: "r"(dst), "l"(src));
}

__device__ __forceinline__ void ldsm4(uint32_t& r0, uint32_t& r1,
                                      uint32_t& r2, uint32_t& r3, uint32_t addr) {
    asm volatile("ldmatrix.sync.aligned.m8n8.x4.shared.b16 {%0,%1,%2,%3}, [%4];"
                 : "=r"(r0), "=r"(r1), "=r"(r2), "=r"(r3) : "r"(addr));
}

__device__ __forceinline__ void ldsm4t(uint32_t& r0, uint32_t& r1,
                                       uint32_t& r2, uint32_t& r3, uint32_t addr) {
    asm volatile("ldmatrix.sync.aligned.m8n8.x4.trans.shared.b16 {%0,%1,%2,%3}, [%4];"
                 : "=r"(r0), "=r"(r1), "=r"(r2), "=r"(r3) : "r"(addr));
}

__device__ __forceinline__ void mma_f16(float* c, const uint32_t* a, const uint32_t* b) {
    asm volatile(
        "mma.sync.aligned.m16n8k16.row.col.f32.f16.f16.f32 "
        "{%0,%1,%2,%3}, {%4,%5,%6,%7}, {%8,%9}, {%0,%1,%2,%3};"
        : "+f"(c[0]), "+f"(c[1]), "+f"(c[2]), "+f"(c[3])
        : "r"(a[0]), "r"(a[1]), "r"(a[2]), "r"(a[3]), "r"(b[0]), "r"(b[1]));
}

// swizzled smem address: row of RS bytes, 16B chunk c16, XOR low3 with row&7
__device__ __forceinline__ uint32_t swz(uint32_t base, int row, int c16, int rs_bytes) {
    return base + (uint32_t)row * (uint32_t)rs_bytes
                + ((uint32_t)(c16 ^ (row & 7)) << 4);
}

// ---- mbarrier primitives (base ISA) ----
#define MBARRIER_INIT(mbar, cnt) \
    asm volatile("mbarrier.init.shared.b64 [%0], %1;" \
        :: "r"((uint32_t)(mbar)), "r"((uint32_t)(cnt)) : "memory")

#define MBARRIER_ARRIVE(mbar) \
    asm volatile("mbarrier.arrive.shared.b64 _, [%0];" \
        :: "r"((uint32_t)(mbar)) : "memory")

#define CPASYNC_MBAR_ARRIVE(mbar) \
    asm volatile("cp.async.mbarrier.arrive.noinc.shared.b64 [%0];" \
        :: "r"((uint32_t)(mbar)) : "memory")

#define MBARRIER_WAIT_PARITY(mbar, parity) do { \
    uint32_t _m = (uint32_t)(mbar); \
    uint32_t _p = (uint32_t)(parity); \
    uint32_t _done; \
    asm volatile( \
        "{\n\t.reg .pred p;\n\t" \
        "mbarrier.try_wait.parity.acquire.cta.shared::cta.b64 p, [%1], %2;\n\t" \
        "selp.b32 %0, 1, 0, p;\n\t}" \
        : "=r"(_done) : "r"(_m), "r"(_p) : "memory"); \
    if (!_done) { \
        asm volatile( \
            "{\n\t.reg .pred P1;\n\t" \
            "WAIT_LOOP_%=:\n\t" \
            "mbarrier.try_wait.parity.acquire.cta.shared::cta.b64 P1, [%0], %1, 0x989680;\n\t" \
            "@P1 bra.uni WAIT_DONE_%=;\n\t" \
            "bra.uni WAIT_LOOP_%=;\n\t" \
            "WAIT_DONE_%=:\n\t}" \
            :: "r"(_m), "r"(_p) : "memory"); \
    } \
} while (0)

// ===========================================================================
// fp16 mma GEMM (R7 config): C[M,N] = A[M,K] @ Bt[N,K]^T (half, K-major).
// 128x128 CTA tile, BK=64 (128B rows), 3-stage cp.async, 256 threads (4x2).
// OUT_HALF: store half, else float.
// ===========================================================================
#define GEMM_STAGES 3
#define STAGE_BYTES 32768            // A 16KB + B 16KB
#define GEMM_SMEM (GEMM_STAGES * STAGE_BYTES)  // 98304

template<int OUT_HALF>
__global__ __launch_bounds__(256) void gemm_f16_mma(
    const __half* __restrict__ A, const __half* __restrict__ Bt,
    void* __restrict__ Cv, int M, int N, int K)
{
    extern __shared__ __align__(1024) char smem[];
    const uint32_t sb = smem_u32(smem);

    const int tid  = threadIdx.x;
    const int lane = tid & 31;
    const int wid  = tid >> 5;
    const int wm   = (wid & 3) * 32;
    const int wn   = (wid >> 2) * 64;

    const int m0 = blockIdx.y * 128;
    const int n0 = blockIdx.x * 128;
    const __half* Ag = A  + (size_t)m0 * K;
    const __half* Bg = Bt + (size_t)n0 * K;
    const int T = K / 64;

    auto load_stage = [&](int t, int s) {
        if (t < T) {
            const uint32_t baseA = sb + (uint32_t)s * STAGE_BYTES;
            const uint32_t baseB = baseA + 16384;
            const int k0 = t * 64;
            #pragma unroll
            for (int i = 0; i < 4; i++) {
                int slot = i * 256 + tid;
                int row = slot >> 3, c = slot & 7;       // 128 rows x 8 chunks
                cp_async16(swz(baseA, row, c, 128),
                           Ag + (size_t)row * K + k0 + c * 8);
                cp_async16(swz(baseB, row, c, 128),
                           Bg + (size_t)row * K + k0 + c * 8);
            }
        }
        asm volatile("cp.async.commit_group;" ::: "memory");
    };

    float acc[2][8][4];
    #pragma unroll
    for (int mt = 0; mt < 2; mt++)
        #pragma unroll
        for (int nt = 0; nt < 8; nt++)
            #pragma unroll
            for (int q = 0; q < 4; q++) acc[mt][nt][q] = 0.f;

    load_stage(0, 0);
    load_stage(1, 1);

    const int a_row16 = lane & 15;
    const int a_ch    = lane >> 4;
    const int b_row   = (lane & 7) + (lane >> 4) * 8;
    const int b_ch    = (lane >> 3) & 1;

    for (int t = 0; t < T; t++) {
        const int s = t % GEMM_STAGES;
        asm volatile("cp.async.wait_group 1;" ::: "memory");
        __syncthreads();

        load_stage(t + 2, (t + 2) % GEMM_STAGES);

        const uint32_t baseA = sb + (uint32_t)s * STAGE_BYTES;
        const uint32_t baseB = baseA + 16384;

        #pragma unroll
        for (int k16 = 0; k16 < 4; k16++) {
            uint32_t afr[2][4], bfr[4][4];
            #pragma unroll
            for (int mt = 0; mt < 2; mt++)
                ldsm4(afr[mt][0], afr[mt][1], afr[mt][2], afr[mt][3],
                      swz(baseA, wm + mt * 16 + a_row16, k16 * 2 + a_ch, 128));
            #pragma unroll
            for (int np = 0; np < 4; np++)
                ldsm4(bfr[np][0], bfr[np][1], bfr[np][2], bfr[np][3],
                      swz(baseB, wn + np * 16 + b_row, k16 * 2 + b_ch, 128));
            #pragma unroll
            for (int mt = 0; mt < 2; mt++)
                #pragma unroll
                for (int nt = 0; nt < 8; nt++) {
                    uint32_t b2[2] = { bfr[nt >> 1][(nt & 1) * 2],
                                       bfr[nt >> 1][(nt & 1) * 2 + 1] };
                    mma_f16(acc[mt][nt], afr[mt], b2);
                }
        }
    }

    const int g = lane >> 2;
    const int tg = lane & 3;
    #pragma unroll
    for (int mt = 0; mt < 2; mt++) {
        int row0 = m0 + wm + mt * 16 + g;
        #pragma unroll
        for (int nt = 0; nt < 8; nt++) {
            int col = n0 + wn + nt * 8 + tg * 2;
            if (OUT_HALF) {
                __half* C = (__half*)Cv;
                *(uint32_t*)(C + (size_t)row0 * N + col) =
                    pack_h2(acc[mt][nt][0], acc[mt][nt][1]);
                *(uint32_t*)(C + (size_t)(row0 + 8) * N + col) =
                    pack_h2(acc[mt][nt][2], acc[mt][nt][3]);
            } else {
                float* C = (float*)Cv;
                *(float2*)(C + (size_t)row0 * N + col) =
                    make_float2(acc[mt][nt][0], acc[mt][nt][1]);
                *(float2*)(C + (size_t)(row0 + 8) * N + col) =
                    make_float2(acc[mt][nt][2], acc[mt][nt][3]);
            }
        }
    }
}

// ===========================================================================
// Pre-passes
// ===========================================================================
__global__ __launch_bounds__(256) void conv_half_kernel(
    const float* __restrict__ in, __half* __restrict__ out, size_t n4)
{
    size_t i = (size_t)blockIdx.x * blockDim.x + threadIdx.x;
    size_t stride = (size_t)gridDim.x * blockDim.x;
    for (; i < n4; i += stride) {
        float4 v = ((const float4*)in)[i];
        uint2 o;
        o.x = pack_h2(v.x, v.y);
        o.y = pack_h2(v.z, v.w);
        ((uint2*)out)[i] = o;
    }
}

__global__ __launch_bounds__(256) void transpose_h_kernel(
    const float* __restrict__ in, __half* __restrict__ out, int R, int C)
{
    __shared__ float tile[32][33];
    const int bx = blockIdx.x * 32, by = blockIdx.y * 32;
    const int tx = threadIdx.x, ty = threadIdx.y;
    #pragma unroll
    for (int i = 0; i < 32; i += 8)
        tile[ty + i][tx] = in[(size_t)(by + ty + i) * C + bx + tx];
    __syncthreads();
    #pragma unroll
    for (int i = 0; i < 32; i += 8)
        out[(size_t)(bx + ty + i) * R + by + tx] = __float2half_rn(tile[tx][ty + i]);
}

// ===========================================================================
// Flash attention, fp16 mma. Register-fed PV + rowsum-by-mma + h2exp2 +
// direct-V via ldsm.trans (no V transpose buffer).
// 256 threads (8 warps), 128 queries x 1 head per CTA, 64-key tiles.
// K tile: 64 rows x 256B; V tile: 64 rows (keys) x 256B (128 cols) direct
// from qkv; PV B-fragments via ldmatrix.trans.
// 3 K+V stages of 32KB each + mbarrier ring. smem: 3*32768 + 64 = 98368 B
// ===========================================================================
#define FLASH_SMEM 98368

__global__ __launch_bounds__(256, 1) void flash_mma_kernel(
    const __half* __restrict__ qkv, __half* __restrict__ O)
{
    extern __shared__ __align__(1024) char smem[];
    const uint32_t sb  = smem_u32(smem);
    const uint32_t MB  = sb + 98304u;            // full[s]=MB+8s, empty[s]=MB+24+8s

    const int tid  = threadIdx.x;
    const int lane = tid & 31;
    const int wid  = tid >> 5;
    const int qb   = 31 - blockIdx.x;   // heavy blocks first
    const int h    = blockIdx.y;
    const float scale2 = 0.12751879652672068f;   // (1/sqrt(128)) * log2(e)
    const uint32_t ONES2 = 0x3C003C00u;          // half2(1,1)

    const int a_row16 = lane & 15;
    const int a_ch    = lane >> 4;
    const int b_row   = (lane & 7) + (lane >> 4) * 8;   // K (non-trans)
    const int b_ch    = (lane >> 3) & 1;
    const int bt_row  = ((lane >> 3) & 1) * 8 + (lane & 7);  // V (trans): k row
    const int bt_ch   = lane >> 4;                            // n chunk select
    const int g       = lane >> 2;
    const int tg      = lane & 3;

    // ---- Stage Q tile (128 x 256B rows, 32KB) into stage0 region
    {
        const __half* Qg = qkv + (size_t)(qb * 128) * QKVW + h * HD;
        #pragma unroll
        for (int i = 0; i < 8; i++) {
            int slot = i * 256 + tid;
            int r = slot >> 4, c = slot & 15;
            cp_async16(swz(sb, r, c, 256), Qg + (size_t)r * QKVW + c * 8);
        }
        asm volatile("cp.async.commit_group;" ::: "memory");
        asm volatile("cp.async.wait_group 0;" ::: "memory");
        __syncthreads();
    }
    uint32_t qf[8][4];
    #pragma unroll
    for (int k16 = 0; k16 < 8; k16++)
        ldsm4(qf[k16][0], qf[k16][1], qf[k16][2], qf[k16][3],
              swz(sb, wid * 16 + a_row16, k16 * 2 + a_ch, 256));
    __syncthreads();   // Q extraction done before stage0 overwritten

    if (tid == 0) {
        #pragma unroll
        for (int s = 0; s < 3; s++) {
            MBARRIER_INIT(MB + 8 * s, 256);        // full[s]
            MBARRIER_INIT(MB + 24 + 8 * s, 256);   // empty[s]
        }
    }
    __syncthreads();

    float oacc[16][4];
    #pragma unroll
    for (int nt = 0; nt < 16; nt++)
        #pragma unroll
        for (int q = 0; q < 4; q++) oacc[nt][q] = 0.f;
    float lacc[4] = {0.f, 0.f, 0.f, 0.f};       // rowsum fragment (l)
    float m0 = -1e30f, m1 = -1e30f;

    const int kb_end = min(2 * qb + 2, 63);   // always >= 2
    const int qi0 = qb * 128 + wid * 16;

    // Load K+V tile t into stage st (8 cp.async per thread). Both 64x256B.
    auto load_tile = [&](int t, int st) {
        const uint32_t KSb = sb + (uint32_t)st * 32768u;
        const uint32_t VSb = KSb + 16384u;
        const __half* Kg = qkv + (size_t)(t * 64) * QKVW + DIM + h * HD;
        const __half* Vg = Kg + DIM;
        #pragma unroll
        for (int i = 0; i < 4; i++) {
            int slot = i * 256 + tid;
            int r = slot >> 4, c = slot & 15;            // 64 rows x 16 chunks
            cp_async16(swz(KSb, r, c, 256), Kg + (size_t)r * QKVW + c * 8);
        }
        #pragma unroll
        for (int i = 0; i < 4; i++) {
            int slot = i * 256 + tid;
            int r = slot >> 4, c = slot & 15;
            cp_async16(swz(VSb, r, c, 256), Vg + (size_t)r * QKVW + c * 8);
        }
    };

    // prologue: tiles 0 and 1 (generation 0 — no empty wait needed)
    load_tile(0, 0); CPASYNC_MBAR_ARRIVE(MB + 0);
    load_tile(1, 1); CPASYNC_MBAR_ARRIVE(MB + 8);

    for (int kb = 0; kb <= kb_end; kb++) {
        // ---- producer: tile kb+2 into stage (kb+2)%3
        {
            const int t = kb + 2;
            if (t <= kb_end) {
                const int st = t % 3;
                if (t >= 3)
                    MBARRIER_WAIT_PARITY(MB + 24 + 8 * st, (uint32_t)((t / 3 - 1) & 1));
                load_tile(t, st);
                CPASYNC_MBAR_ARRIVE(MB + 8 * st);
            }
        }

        const int s  = kb % 3;
        const int ph = (kb / 3) & 1;
        MBARRIER_WAIT_PARITY(MB + 8 * s, (uint32_t)ph);   // K+V tile kb resident

        const bool skipw = (kb * 64 > qi0 + 16);   // fully masked for this warp
        if (!skipw) {
            const uint32_t KSb = sb + (uint32_t)s * 32768u;
            const uint32_t VSb = KSb + 16384u;

            // ---- S = Q @ K^T  (m16 per warp, n64, k128)
            float sacc[8][4];
            #pragma unroll
            for (int nt = 0; nt < 8; nt++)
                #pragma unroll
                for (int q = 0; q < 4; q++) sacc[nt][q] = 0.f;

            #pragma unroll
            for (int k16 = 0; k16 < 8; k16++) {
                uint32_t bfr[4][4];
                #pragma unroll
                for (int np = 0; np < 4; np++)
                    ldsm4(bfr[np][0], bfr[np][1], bfr[np][2], bfr[np][3],
                          swz(KSb, np * 16 + b_row, k16 * 2 + b_ch, 256));
                #pragma unroll
                for (int nt = 0; nt < 8; nt++) {
                    uint32_t b2[2] = { bfr[nt >> 1][(nt & 1) * 2],
                                       bfr[nt >> 1][(nt & 1) * 2 + 1] };
                    mma_f16(sacc[nt], qf[k16], b2);
                }
            }

            // ---- softmax (exp2 domain): scale+mask, rowmax, P in half2
            const int row0 = qi0 + g, row1 = qi0 + g + 8;
            const bool nomask = (kb * 64 + 63 <= qi0 + 1);
            float mx0 = -1e30f, mx1 = -1e30f;
            if (nomask) {
                #pragma unroll
                for (int nt = 0; nt < 8; nt++)
                    #pragma unroll
                    for (int c = 0; c < 2; c++) {
                        float v0 = sacc[nt][c] * scale2;
                        float v1 = sacc[nt][c + 2] * scale2;
                        sacc[nt][c] = v0; sacc[nt][c + 2] = v1;
                        mx0 = fmaxf(mx0, v0); mx1 = fmaxf(mx1, v1);
                    }
            } else {
                #pragma unroll
                for (int nt = 0; nt < 8; nt++)
                    #pragma unroll
                    for (int c = 0; c < 2; c++) {
                        int kj = kb * 64 + nt * 8 + tg * 2 + c;
                        float v0 = (kj <= row0 + 1) ? sacc[nt][c] * scale2 : -1e30f;
                        float v1 = (kj <= row1 + 1) ? sacc[nt][c + 2] * scale2 : -1e30f;
                        sacc[nt][c] = v0; sacc[nt][c + 2] = v1;
                        mx0 = fmaxf(mx0, v0); mx1 = fmaxf(mx1, v1);
                    }
            }
            mx0 = fmaxf(mx0, __shfl_xor_sync(0xffffffffu, mx0, 1));
            mx0 = fmaxf(mx0, __shfl_xor_sync(0xffffffffu, mx0, 2));
            mx1 = fmaxf(mx1, __shfl_xor_sync(0xffffffffu, mx1, 1));
            mx1 = fmaxf(mx1, __shfl_xor_sync(0xffffffffu, mx1, 2));

            float newm0 = fmaxf(m0, mx0), newm1 = fmaxf(m1, mx1);
            float f0 = exp2f(m0 - newm0), f1 = exp2f(m1 - newm1);
            m0 = newm0; m1 = newm1;

            // P directly as half2 (one ex2.f16x2 per pair)
            uint32_t parr[8][2];
            #pragma unroll
            for (int nt = 0; nt < 8; nt++) {
                parr[nt][0] = exp2_h2(sacc[nt][0] - newm0, sacc[nt][1] - newm0);
                parr[nt][1] = exp2_h2(sacc[nt][2] - newm1, sacc[nt][3] - newm1);
            }

            // rescale O and l accumulators
            #pragma unroll
            for (int nt = 0; nt < 16; nt++) {
                oacc[nt][0] *= f0; oacc[nt][1] *= f0;
                oacc[nt][2] *= f1; oacc[nt][3] *= f1;
            }
            lacc[0] *= f0; lacc[1] *= f0; lacc[2] *= f1; lacc[3] *= f1;

            // ---- O += P @ V ; l += P @ 1  (V fragments via ldsm.trans)
            #pragma unroll
            for (int k16 = 0; k16 < 4; k16++) {
                uint32_t afr[4] = { parr[2 * k16][0],     parr[2 * k16][1],
                                    parr[2 * k16 + 1][0], parr[2 * k16 + 1][1] };
                uint32_t onesb[2] = { ONES2, ONES2 };
                mma_f16(lacc, afr, onesb);
                #pragma unroll
                for (int np = 0; np < 8; np++) {
                    uint32_t bfr[4];
                    ldsm4t(bfr[0], bfr[1], bfr[2], bfr[3],
                           swz(VSb, k16 * 16 + bt_row, np * 2 + bt_ch, 256));
                    uint32_t b2a[2] = { bfr[0], bfr[1] };
                    uint32_t b2b[2] = { bfr[2], bfr[3] };
                    mma_f16(oacc[np * 2 + 0], afr, b2a);
                    mma_f16(oacc[np * 2 + 1], afr, b2b);
                }
            }
        }

        MBARRIER_ARRIVE(MB + 24 + 8 * s);   // done with stage s this generation
    }

    // ---- epilogue: normalize by l (lacc[0]=rowsum(g), lacc[2]=rowsum(g+8))
    const float inv0 = 1.f / lacc[0], inv1 = 1.f / lacc[2];
    const int row0 = qb * 128 + wid * 16 + g;
    __half* Og = O + (size_t)row0 * DIM + h * HD;
    #pragma unroll
    for (int nt = 0; nt < 16; nt++) {
        int col = nt * 8 + tg * 2;
        *(uint32_t*)(Og + col) = pack_h2(oacc[nt][0] * inv0, oacc[nt][1] * inv0);
        *(uint32_t*)(Og + (size_t)8 * DIM + col) =
            pack_h2(oacc[nt][2] * inv1, oacc[nt][3] * inv1);
    }
}

// ===========================================================================
// Launch
// ===========================================================================
extern "C" void kernel_launch(void* const* d_in, const int* in_sizes, int n_in,
                              void* d_out, int out_size)
{
    const float* x     = (const float*)d_in[0];  // (4096, 2048)
    const float* w_qkv = (const float*)d_in[1];  // (2048, 6144)
    const float* w_o   = (const float*)d_in[2];  // (2048, 2048)
    float* out = (float*)d_out;                  // (4096, 2048)

    __half *qkvh, *oh, *xh, *wqkvT, *woT;
    cudaGetSymbolAddress((void**)&qkvh,  g_qkvh);
    cudaGetSymbolAddress((void**)&oh,    g_oh);
    cudaGetSymbolAddress((void**)&xh,    g_xh);
    cudaGetSymbolAddress((void**)&wqkvT, g_wqkvT);
    cudaGetSymbolAddress((void**)&woT,   g_woT);

    cudaFuncSetAttribute(gemm_f16_mma<1>,
                         cudaFuncAttributeMaxDynamicSharedMemorySize, GEMM_SMEM);
    cudaFuncSetAttribute(gemm_f16_mma<0>,
                         cudaFuncAttributeMaxDynamicSharedMemorySize, GEMM_SMEM);
    cudaFuncSetAttribute(flash_mma_kernel,
                         cudaFuncAttributeMaxDynamicSharedMemorySize, FLASH_SMEM);

    // 0) convert x; transpose+convert weights
    conv_half_kernel<<<2048, 256>>>(x, xh, (size_t)SEQ * DIM / 4);
    transpose_h_kernel<<<dim3(QKVW / 32, DIM / 32), dim3(32, 8)>>>(w_qkv, wqkvT, DIM, QKVW);
    transpose_h_kernel<<<dim3(DIM / 32, DIM / 32), dim3(32, 8)>>>(w_o, woT, DIM, DIM);

    // 1) QKV projection (fp16 mma, half output)
    gemm_f16_mma<1><<<dim3(QKVW / 128, SEQ / 128), 256, GEMM_SMEM>>>(
        xh, wqkvT, qkvh, SEQ, QKVW, DIM);

    // 2) Attention (fp16 mma flash, direct V)
    flash_mma_kernel<<<dim3(SEQ / 128, NH), 256, FLASH_SMEM>>>(qkvh, oh);

    // 3) Output projection (fp16 mma, float output)
    gemm_f16_mma<0><<<dim3(DIM / 128, SEQ / 128), 256, GEMM_SMEM>>>(
        oh, woT, out, SEQ, DIM, DIM);
}

// round 12
// speedup vs baseline: 1.2305x; 1.0445x over previous
#include <cuda_runtime.h>
#include <cuda_fp16.h>
#include <cstdint>
#include <cstddef>

// Problem constants
#define SEQ   4096
#define DIM   2048
#define NH    16
#define HD    128
#define QKVW  (3 * DIM)   // 6144

// Scratch (device globals: allocation-free per harness rules)
__device__ __half g_qkvh [(size_t)SEQ * QKVW];  // (S, 3*dim) fp16
__device__ __half g_oh   [(size_t)SEQ * DIM];   // attention out fp16
__device__ __half g_xh   [(size_t)SEQ * DIM];   // x fp16
__device__ __half g_wqkvT[(size_t)QKVW * DIM];  // w_qkv^T fp16 (6144, 2048)
__device__ __half g_woT  [(size_t)DIM * DIM];   // w_o^T fp16

// ===========================================================================
// Helpers
// ===========================================================================
__device__ __forceinline__ uint32_t smem_u32(const void* p) {
    uint32_t a;
    asm("{ .reg .u64 t; cvta.to.shared.u64 t, %1; cvt.u32.u64 %0, t; }"
        : "=r"(a) : "l"(p));
    return a;
}

__device__ __forceinline__ uint32_t pack_h2(float lo, float hi) {
    __half2 h = __floats2half2_rn(lo, hi);
    return *(uint32_t*)&h;
}

__device__ __forceinline__ uint32_t exp2_h2(float lo, float hi) {
    __half2 h = h2exp2(__floats2half2_rn(lo, hi));
    return *(uint32_t*)&h;
}

__device__ __forceinline__ void cp_async16(uint32_t dst, const void* src) {
    asm volatile("cp.async.cg.shared.global [%0], [%1], 16;"
                 :: "r"(dst), "l"(src));
}

__device__ __forceinline__ void ldsm4(uint32_t& r0, uint32_t& r1,
                                      uint32_t& r2, uint32_t& r3, uint32_t addr) {
    asm volatile("ldmatrix.sync.aligned.m8n8.x4.shared.b16 {%0,%1,%2,%3}, [%4];"
                 : "=r"(r0), "=r"(r1), "=r"(r2), "=r"(r3) : "r"(addr));
}

__device__ __forceinline__ void ldsm4t(uint32_t& r0, uint32_t& r1,
                                       uint32_t& r2, uint32_t& r3, uint32_t addr) {
    asm volatile("ldmatrix.sync.aligned.m8n8.x4.trans.shared.b16 {%0,%1,%2,%3}, [%4];"
                 : "=r"(r0), "=r"(r1), "=r"(r2), "=r"(r3) : "r"(addr));
}

__device__ __forceinline__ void mma_f16(float* c, const uint32_t* a, const uint32_t* b) {
    asm volatile(
        "mma.sync.aligned.m16n8k16.row.col.f32.f16.f16.f32 "
        "{%0,%1,%2,%3}, {%4,%5,%6,%7}, {%8,%9}, {%0,%1,%2,%3};"
        : "+f"(c[0]), "+f"(c[1]), "+f"(c[2]), "+f"(c[3])
        : "r"(a[0]), "r"(a[1]), "r"(a[2]), "r"(a[3]), "r"(b[0]), "r"(b[1]));
}

// swizzled smem address: row of RS bytes, 16B chunk c16, XOR low3 with row&7
__device__ __forceinline__ uint32_t swz(uint32_t base, int row, int c16, int rs_bytes) {
    return base + (uint32_t)row * (uint32_t)rs_bytes
                + ((uint32_t)(c16 ^ (row & 7)) << 4);
}

// ---- mbarrier primitives (base ISA) ----
#define MBARRIER_INIT(mbar, cnt) \
    asm volatile("mbarrier.init.shared.b64 [%0], %1;" \
        :: "r"((uint32_t)(mbar)), "r"((uint32_t)(cnt)) : "memory")

#define MBARRIER_ARRIVE(mbar) \
    asm volatile("mbarrier.arrive.shared.b64 _, [%0];" \
        :: "r"((uint32_t)(mbar)) : "memory")

#define CPASYNC_MBAR_ARRIVE(mbar) \
    asm volatile("cp.async.mbarrier.arrive.noinc.shared.b64 [%0];" \
        :: "r"((uint32_t)(mbar)) : "memory")

#define MBARRIER_WAIT_PARITY(mbar, parity) do { \
    uint32_t _m = (uint32_t)(mbar); \
    uint32_t _p = (uint32_t)(parity); \
    uint32_t _done; \
    asm volatile( \
        "{\n\t.reg .pred p;\n\t" \
        "mbarrier.try_wait.parity.acquire.cta.shared::cta.b64 p, [%1], %2;\n\t" \
        "selp.b32 %0, 1, 0, p;\n\t}" \
        : "=r"(_done) : "r"(_m), "r"(_p) : "memory"); \
    if (!_done) { \
        asm volatile( \
            "{\n\t.reg .pred P1;\n\t" \
            "WAIT_LOOP_%=:\n\t" \
            "mbarrier.try_wait.parity.acquire.cta.shared::cta.b64 P1, [%0], %1, 0x989680;\n\t" \
            "@P1 bra.uni WAIT_DONE_%=;\n\t" \
            "bra.uni WAIT_LOOP_%=;\n\t" \
            "WAIT_DONE_%=:\n\t}" \
            :: "r"(_m), "r"(_p) : "memory"); \
    } \
} while (0)

// ===========================================================================
// fp16 mma GEMM with FREE-RUNNING mbarrier ring (no per-tile __syncthreads).
// C[M,N] = A[M,K] @ Bt[N,K]^T (half, K-major).
// 128x128 CTA tile, BK=64 (128B rows), 3 stages, 256 threads (4x2 warps).
// full[s]/empty[s] mbarriers, 256 arrivals each; warps skew <= 1 stage.
// OUT_HALF: store half, else float. K/64 >= 2.
// ===========================================================================
#define GEMM_STAGES 3
#define STAGE_BYTES 32768            // A 16KB + B 16KB
#define GEMM_SMEM (GEMM_STAGES * STAGE_BYTES + 64)  // 98368

template<int OUT_HALF>
__global__ __launch_bounds__(256) void gemm_f16_mma(
    const __half* __restrict__ A, const __half* __restrict__ Bt,
    void* __restrict__ Cv, int M, int N, int K)
{
    extern __shared__ __align__(1024) char smem[];
    const uint32_t sb = smem_u32(smem);
    const uint32_t MB = sb + (uint32_t)(GEMM_STAGES * STAGE_BYTES);
    // full[s] = MB + 8s, empty[s] = MB + 24 + 8s

    const int tid  = threadIdx.x;
    const int lane = tid & 31;
    const int wid  = tid >> 5;
    const int wm   = (wid & 3) * 32;
    const int wn   = (wid >> 2) * 64;

    const int m0 = blockIdx.y * 128;
    const int n0 = blockIdx.x * 128;
    const __half* Ag = A  + (size_t)m0 * K;
    const __half* Bg = Bt + (size_t)n0 * K;
    const int T = K / 64;

    if (tid == 0) {
        #pragma unroll
        for (int s = 0; s < GEMM_STAGES; s++) {
            MBARRIER_INIT(MB + 8 * s, 256);        // full[s]
            MBARRIER_INIT(MB + 24 + 8 * s, 256);   // empty[s]
        }
    }
    __syncthreads();

    auto load_stage = [&](int t, int s) {
        const uint32_t baseA = sb + (uint32_t)s * STAGE_BYTES;
        const uint32_t baseB = baseA + 16384;
        const int k0 = t * 64;
        #pragma unroll
        for (int i = 0; i < 4; i++) {
            int slot = i * 256 + tid;
            int row = slot >> 3, c = slot & 7;       // 128 rows x 8 chunks
            cp_async16(swz(baseA, row, c, 128),
                       Ag + (size_t)row * K + k0 + c * 8);
            cp_async16(swz(baseB, row, c, 128),
                       Bg + (size_t)row * K + k0 + c * 8);
        }
    };

    float acc[2][8][4];
    #pragma unroll
    for (int mt = 0; mt < 2; mt++)
        #pragma unroll
        for (int nt = 0; nt < 8; nt++)
            #pragma unroll
            for (int q = 0; q < 4; q++) acc[mt][nt][q] = 0.f;

    // prologue: tiles 0, 1 (generation 0 — no empty wait)
    load_stage(0, 0); CPASYNC_MBAR_ARRIVE(MB + 0);
    load_stage(1, 1); CPASYNC_MBAR_ARRIVE(MB + 8);

    const int a_row16 = lane & 15;
    const int a_ch    = lane >> 4;
    const int b_row   = (lane & 7) + (lane >> 4) * 8;
    const int b_ch    = (lane >> 3) & 1;

    for (int t = 0; t < T; t++) {
        // producer: tile t+2 into stage (t+2)%3
        {
            const int tt = t + 2;
            if (tt < T) {
                const int st = tt % GEMM_STAGES;
                if (tt >= GEMM_STAGES)
                    MBARRIER_WAIT_PARITY(MB + 24 + 8 * st,
                                         (uint32_t)((tt / GEMM_STAGES - 1) & 1));
                load_stage(tt, st);
                CPASYNC_MBAR_ARRIVE(MB + 8 * st);
            }
        }

        const int s  = t % GEMM_STAGES;
        const int ph = (t / GEMM_STAGES) & 1;
        MBARRIER_WAIT_PARITY(MB + 8 * s, (uint32_t)ph);   // tile t resident

        const uint32_t baseA = sb + (uint32_t)s * STAGE_BYTES;
        const uint32_t baseB = baseA + 16384;

        #pragma unroll
        for (int k16 = 0; k16 < 4; k16++) {
            uint32_t afr[2][4], bfr[4][4];
            #pragma unroll
            for (int mt = 0; mt < 2; mt++)
                ldsm4(afr[mt][0], afr[mt][1], afr[mt][2], afr[mt][3],
                      swz(baseA, wm + mt * 16 + a_row16, k16 * 2 + a_ch, 128));
            #pragma unroll
            for (int np = 0; np < 4; np++)
                ldsm4(bfr[np][0], bfr[np][1], bfr[np][2], bfr[np][3],
                      swz(baseB, wn + np * 16 + b_row, k16 * 2 + b_ch, 128));
            #pragma unroll
            for (int mt = 0; mt < 2; mt++)
                #pragma unroll
                for (int nt = 0; nt < 8; nt++) {
                    uint32_t b2[2] = { bfr[nt >> 1][(nt & 1) * 2],
                                       bfr[nt >> 1][(nt & 1) * 2 + 1] };
                    mma_f16(acc[mt][nt], afr[mt], b2);
                }
        }

        MBARRIER_ARRIVE(MB + 24 + 8 * s);   // done reading stage s this gen
    }

    const int g = lane >> 2;
    const int tg = lane & 3;
    #pragma unroll
    for (int mt = 0; mt < 2; mt++) {
        int row0 = m0 + wm + mt * 16 + g;
        #pragma unroll
        for (int nt = 0; nt < 8; nt++) {
            int col = n0 + wn + nt * 8 + tg * 2;
            if (OUT_HALF) {
                __half* C = (__half*)Cv;
                *(uint32_t*)(C + (size_t)row0 * N + col) =
                    pack_h2(acc[mt][nt][0], acc[mt][nt][1]);
                *(uint32_t*)(C + (size_t)(row0 + 8) * N + col) =
                    pack_h2(acc[mt][nt][2], acc[mt][nt][3]);
            } else {
                float* C = (float*)Cv;
                *(float2*)(C + (size_t)row0 * N + col) =
                    make_float2(acc[mt][nt][0], acc[mt][nt][1]);
                *(float2*)(C + (size_t)(row0 + 8) * N + col) =
                    make_float2(acc[mt][nt][2], acc[mt][nt][3]);
            }
        }
    }
}

// ===========================================================================
// Pre-passes
// ===========================================================================
__global__ __launch_bounds__(256) void conv_half_kernel(
    const float* __restrict__ in, __half* __restrict__ out, size_t n4)
{
    size_t i = (size_t)blockIdx.x * blockDim.x + threadIdx.x;
    size_t stride = (size_t)gridDim.x * blockDim.x;
    for (; i < n4; i += stride) {
        float4 v = ((const float4*)in)[i];
        uint2 o;
        o.x = pack_h2(v.x, v.y);
        o.y = pack_h2(v.z, v.w);
        ((uint2*)out)[i] = o;
    }
}

__global__ __launch_bounds__(256) void transpose_h_kernel(
    const float* __restrict__ in, __half* __restrict__ out, int R, int C)
{
    __shared__ float tile[32][33];
    const int bx = blockIdx.x * 32, by = blockIdx.y * 32;
    const int tx = threadIdx.x, ty = threadIdx.y;
    #pragma unroll
    for (int i = 0; i < 32; i += 8)
        tile[ty + i][tx] = in[(size_t)(by + ty + i) * C + bx + tx];
    __syncthreads();
    #pragma unroll
    for (int i = 0; i < 32; i += 8)
        out[(size_t)(bx + ty + i) * R + by + tx] = __float2half_rn(tile[tx][ty + i]);
}

// ===========================================================================
// Flash attention (R11 config, unchanged): fp16 mma, register-fed PV,
// rowsum-by-mma, h2exp2, direct-V via ldsm.trans, mbarrier ring.
// smem: 3*32768 + 64 = 98368 B
// ===========================================================================
#define FLASH_SMEM 98368

__global__ __launch_bounds__(256, 1) void flash_mma_kernel(
    const __half* __restrict__ qkv, __half* __restrict__ O)
{
    extern __shared__ __align__(1024) char smem[];
    const uint32_t sb  = smem_u32(smem);
    const uint32_t MB  = sb + 98304u;            // full[s]=MB+8s, empty[s]=MB+24+8s

    const int tid  = threadIdx.x;
    const int lane = tid & 31;
    const int wid  = tid >> 5;
    const int qb   = 31 - blockIdx.x;   // heavy blocks first
    const int h    = blockIdx.y;
    const float scale2 = 0.12751879652672068f;   // (1/sqrt(128)) * log2(e)
    const uint32_t ONES2 = 0x3C003C00u;          // half2(1,1)

    const int a_row16 = lane & 15;
    const int a_ch    = lane >> 4;
    const int b_row   = (lane & 7) + (lane >> 4) * 8;   // K (non-trans)
    const int b_ch    = (lane >> 3) & 1;
    const int bt_row  = ((lane >> 3) & 1) * 8 + (lane & 7);  // V (trans): k row
    const int bt_ch   = lane >> 4;                            // n chunk select
    const int g       = lane >> 2;
    const int tg      = lane & 3;

    // ---- Stage Q tile (128 x 256B rows, 32KB) into stage0 region
    {
        const __half* Qg = qkv + (size_t)(qb * 128) * QKVW + h * HD;
        #pragma unroll
        for (int i = 0; i < 8; i++) {
            int slot = i * 256 + tid;
            int r = slot >> 4, c = slot & 15;
            cp_async16(swz(sb, r, c, 256), Qg + (size_t)r * QKVW + c * 8);
        }
        asm volatile("cp.async.commit_group;" ::: "memory");
        asm volatile("cp.async.wait_group 0;" ::: "memory");
        __syncthreads();
    }
    uint32_t qf[8][4];
    #pragma unroll
    for (int k16 = 0; k16 < 8; k16++)
        ldsm4(qf[k16][0], qf[k16][1], qf[k16][2], qf[k16][3],
              swz(sb, wid * 16 + a_row16, k16 * 2 + a_ch, 256));
    __syncthreads();   // Q extraction done before stage0 overwritten

    if (tid == 0) {
        #pragma unroll
        for (int s = 0; s < 3; s++) {
            MBARRIER_INIT(MB + 8 * s, 256);        // full[s]
            MBARRIER_INIT(MB + 24 + 8 * s, 256);   // empty[s]
        }
    }
    __syncthreads();

    float oacc[16][4];
    #pragma unroll
    for (int nt = 0; nt < 16; nt++)
        #pragma unroll
        for (int q = 0; q < 4; q++) oacc[nt][q] = 0.f;
    float lacc[4] = {0.f, 0.f, 0.f, 0.f};       // rowsum fragment (l)
    float m0 = -1e30f, m1 = -1e30f;

    const int kb_end = min(2 * qb + 2, 63);   // always >= 2
    const int qi0 = qb * 128 + wid * 16;

    // Load K+V tile t into stage st (8 cp.async per thread). Both 64x256B.
    auto load_tile = [&](int t, int st) {
        const uint32_t KSb = sb + (uint32_t)st * 32768u;
        const uint32_t VSb = KSb + 16384u;
        const __half* Kg = qkv + (size_t)(t * 64) * QKVW + DIM + h * HD;
        const __half* Vg = Kg + DIM;
        #pragma unroll
        for (int i = 0; i < 4; i++) {
            int slot = i * 256 + tid;
            int r = slot >> 4, c = slot & 15;            // 64 rows x 16 chunks
            cp_async16(swz(KSb, r, c, 256), Kg + (size_t)r * QKVW + c * 8);
        }
        #pragma unroll
        for (int i = 0; i < 4; i++) {
            int slot = i * 256 + tid;
            int r = slot >> 4, c = slot & 15;
            cp_async16(swz(VSb, r, c, 256), Vg + (size_t)r * QKVW + c * 8);
        }
    };

    // prologue: tiles 0 and 1 (generation 0 — no empty wait needed)
    load_tile(0, 0); CPASYNC_MBAR_ARRIVE(MB + 0);
    load_tile(1, 1); CPASYNC_MBAR_ARRIVE(MB + 8);

    for (int kb = 0; kb <= kb_end; kb++) {
        // ---- producer: tile kb+2 into stage (kb+2)%3
        {
            const int t = kb + 2;
            if (t <= kb_end) {
                const int st = t % 3;
                if (t >= 3)
                    MBARRIER_WAIT_PARITY(MB + 24 + 8 * st, (uint32_t)((t / 3 - 1) & 1));
                load_tile(t, st);
                CPASYNC_MBAR_ARRIVE(MB + 8 * st);
            }
        }

        const int s  = kb % 3;
        const int ph = (kb / 3) & 1;
        MBARRIER_WAIT_PARITY(MB + 8 * s, (uint32_t)ph);   // K+V tile kb resident

        const bool skipw = (kb * 64 > qi0 + 16);   // fully masked for this warp
        if (!skipw) {
            const uint32_t KSb = sb + (uint32_t)s * 32768u;
            const uint32_t VSb = KSb + 16384u;

            // ---- S = Q @ K^T  (m16 per warp, n64, k128)
            float sacc[8][4];
            #pragma unroll
            for (int nt = 0; nt < 8; nt++)
                #pragma unroll
                for (int q = 0; q < 4; q++) sacc[nt][q] = 0.f;

            #pragma unroll
            for (int k16 = 0; k16 < 8; k16++) {
                uint32_t bfr[4][4];
                #pragma unroll
                for (int np = 0; np < 4; np++)
                    ldsm4(bfr[np][0], bfr[np][1], bfr[np][2], bfr[np][3],
                          swz(KSb, np * 16 + b_row, k16 * 2 + b_ch, 256));
                #pragma unroll
                for (int nt = 0; nt < 8; nt++) {
                    uint32_t b2[2] = { bfr[nt >> 1][(nt & 1) * 2],
                                       bfr[nt >> 1][(nt & 1) * 2 + 1] };
                    mma_f16(sacc[nt], qf[k16], b2);
                }
            }

            // ---- softmax (exp2 domain): scale+mask, rowmax, P in half2
            const int row0 = qi0 + g, row1 = qi0 + g + 8;
            const bool nomask = (kb * 64 + 63 <= qi0 + 1);
            float mx0 = -1e30f, mx1 = -1e30f;
            if (nomask) {
                #pragma unroll
                for (int nt = 0; nt < 8; nt++)
                    #pragma unroll
                    for (int c = 0; c < 2; c++) {
                        float v0 = sacc[nt][c] * scale2;
                        float v1 = sacc[nt][c + 2] * scale2;
                        sacc[nt][c] = v0; sacc[nt][c + 2] = v1;
                        mx0 = fmaxf(mx0, v0); mx1 = fmaxf(mx1, v1);
                    }
            } else {
                #pragma unroll
                for (int nt = 0; nt < 8; nt++)
                    #pragma unroll
                    for (int c = 0; c < 2; c++) {
                        int kj = kb * 64 + nt * 8 + tg * 2 + c;
                        float v0 = (kj <= row0 + 1) ? sacc[nt][c] * scale2 : -1e30f;
                        float v1 = (kj <= row1 + 1) ? sacc[nt][c + 2] * scale2 : -1e30f;
                        sacc[nt][c] = v0; sacc[nt][c + 2] = v1;
                        mx0 = fmaxf(mx0, v0); mx1 = fmaxf(mx1, v1);
                    }
            }
            mx0 = fmaxf(mx0, __shfl_xor_sync(0xffffffffu, mx0, 1));
            mx0 = fmaxf(mx0, __shfl_xor_sync(0xffffffffu, mx0, 2));
            mx1 = fmaxf(mx1, __shfl_xor_sync(0xffffffffu, mx1, 1));
            mx1 = fmaxf(mx1, __shfl_xor_sync(0xffffffffu, mx1, 2));

            float newm0 = fmaxf(m0, mx0), newm1 = fmaxf(m1, mx1);
            float f0 = exp2f(m0 - newm0), f1 = exp2f(m1 - newm1);
            m0 = newm0; m1 = newm1;

            // P directly as half2 (one ex2.f16x2 per pair)
            uint32_t parr[8][2];
            #pragma unroll
            for (int nt = 0; nt < 8; nt++) {
                parr[nt][0] = exp2_h2(sacc[nt][0] - newm0, sacc[nt][1] - newm0);
                parr[nt][1] = exp2_h2(sacc[nt][2] - newm1, sacc[nt][3] - newm1);
            }

            // rescale O and l accumulators
            #pragma unroll
            for (int nt = 0; nt < 16; nt++) {
                oacc[nt][0] *= f0; oacc[nt][1] *= f0;
                oacc[nt][2] *= f1; oacc[nt][3] *= f1;
            }
            lacc[0] *= f0; lacc[1] *= f0; lacc[2] *= f1; lacc[3] *= f1;

            // ---- O += P @ V ; l += P @ 1  (V fragments via ldsm.trans)
            #pragma unroll
            for (int k16 = 0; k16 < 4; k16++) {
                uint32_t afr[4] = { parr[2 * k16][0],     parr[2 * k16][1],
                                    parr[2 * k16 + 1][0], parr[2 * k16 + 1][1] };
                uint32_t onesb[2] = { ONES2, ONES2 };
                mma_f16(lacc, afr, onesb);
                #pragma unroll
                for (int np = 0; np < 8; np++) {
                    uint32_t bfr[4];
                    ldsm4t(bfr[0], bfr[1], bfr[2], bfr[3],
                           swz(VSb, k16 * 16 + bt_row, np * 2 + bt_ch, 256));
                    uint32_t b2a[2] = { bfr[0], bfr[1] };
                    uint32_t b2b[2] = { bfr[2], bfr[3] };
                    mma_f16(oacc[np * 2 + 0], afr, b2a);
                    mma_f16(oacc[np * 2 + 1], afr, b2b);
                }
            }
        }

        MBARRIER_ARRIVE(MB + 24 + 8 * s);   // done with stage s this generation
    }

    // ---- epilogue: normalize by l (lacc[0]=rowsum(g), lacc[2]=rowsum(g+8))
    const float inv0 = 1.f / lacc[0], inv1 = 1.f / lacc[2];
    const int row0 = qb * 128 + wid * 16 + g;
    __half* Og = O + (size_t)row0 * DIM + h * HD;
    #pragma unroll
    for (int nt = 0; nt < 16; nt++) {
        int col = nt * 8 + tg * 2;
        *(uint32_t*)(Og + col) = pack_h2(oacc[nt][0] * inv0, oacc[nt][1] * inv0);
        *(uint32_t*)(Og + (size_t)8 * DIM + col) =
            pack_h2(oacc[nt][2] * inv1, oacc[nt][3] * inv1);
    }
}

// ===========================================================================
// Launch
// ===========================================================================
extern "C" void kernel_launch(void* const* d_in, const int* in_sizes, int n_in,
                              void* d_out, int out_size)
{
    const float* x     = (const float*)d_in[0];  // (4096, 2048)
    const float* w_qkv = (const float*)d_in[1];  // (2048, 6144)
    const float* w_o   = (const float*)d_in[2];  // (2048, 2048)
    float* out = (float*)d_out;                  // (4096, 2048)

    __half *qkvh, *oh, *xh, *wqkvT, *woT;
    cudaGetSymbolAddress((void**)&qkvh,  g_qkvh);
    cudaGetSymbolAddress((void**)&oh,    g_oh);
    cudaGetSymbolAddress((void**)&xh,    g_xh);
    cudaGetSymbolAddress((void**)&wqkvT, g_wqkvT);
    cudaGetSymbolAddress((void**)&woT,   g_woT);

    cudaFuncSetAttribute(gemm_f16_mma<1>,
                         cudaFuncAttributeMaxDynamicSharedMemorySize, GEMM_SMEM);
    cudaFuncSetAttribute(gemm_f16_mma<0>,
                         cudaFuncAttributeMaxDynamicSharedMemorySize, GEMM_SMEM);
    cudaFuncSetAttribute(flash_mma_kernel,
                         cudaFuncAttributeMaxDynamicSharedMemorySize, FLASH_SMEM);

    // 0) convert x; transpose+convert weights
    conv_half_kernel<<<2048, 256>>>(x, xh, (size_t)SEQ * DIM / 4);
    transpose_h_kernel<<<dim3(QKVW / 32, DIM / 32), dim3(32, 8)>>>(w_qkv, wqkvT, DIM, QKVW);
    transpose_h_kernel<<<dim3(DIM / 32, DIM / 32), dim3(32, 8)>>>(w_o, woT, DIM, DIM);

    // 1) QKV projection (fp16 mma, half output, free-running ring)
    gemm_f16_mma<1><<<dim3(QKVW / 128, SEQ / 128), 256, GEMM_SMEM>>>(
        xh, wqkvT, qkvh, SEQ, QKVW, DIM);

    // 2) Attention (fp16 mma flash, direct V)
    flash_mma_kernel<<<dim3(SEQ / 128, NH), 256, FLASH_SMEM>>>(qkvh, oh);

    // 3) Output projection (fp16 mma, float output, free-running ring)
    gemm_f16_mma<0><<<dim3(DIM / 128, SEQ / 128), 256, GEMM_SMEM>>>(
        oh, woT, out, SEQ, DIM, DIM);
}

// round 13
// speedup vs baseline: 1.2344x; 1.0031x over previous
#include <cuda_runtime.h>
#include <cuda_fp16.h>
#include <cstdint>
#include <cstddef>

// Problem constants
#define SEQ   4096
#define DIM   2048
#define NH    16
#define HD    128
#define QKVW  (3 * DIM)   // 6144

// Scratch (device globals: allocation-free per harness rules)
__device__ __half g_qkvh [(size_t)SEQ * QKVW];  // (S, 3*dim) fp16
__device__ __half g_oh   [(size_t)SEQ * DIM];   // attention out fp16
__device__ __half g_xh   [(size_t)SEQ * DIM];   // x fp16
__device__ __half g_wqkvh[(size_t)DIM * QKVW];  // w_qkv fp16 (2048, 6144) row-major
__device__ __half g_woh  [(size_t)DIM * DIM];   // w_o fp16 (2048, 2048) row-major

// ===========================================================================
// Helpers
// ===========================================================================
__device__ __forceinline__ uint32_t smem_u32(const void* p) {
    uint32_t a;
    asm("{ .reg .u64 t; cvta.to.shared.u64 t, %1; cvt.u32.u64 %0, t; }"
        : "=r"(a) : "l"(p));
    return a;
}

__device__ __forceinline__ uint32_t pack_h2(float lo, float hi) {
    __half2 h = __floats2half2_rn(lo, hi);
    return *(uint32_t*)&h;
}

__device__ __forceinline__ uint32_t exp2_h2(float lo, float hi) {
    __half2 h = h2exp2(__floats2half2_rn(lo, hi));
    return *(uint32_t*)&h;
}

__device__ __forceinline__ void cp_async16(uint32_t dst, const void* src) {
    asm volatile("cp.async.cg.shared.global [%0], [%1], 16;"
                 :: "r"(dst), "l"(src));
}

__device__ __forceinline__ void ldsm4(uint32_t& r0, uint32_t& r1,
                                      uint32_t& r2, uint32_t& r3, uint32_t addr) {
    asm volatile("ldmatrix.sync.aligned.m8n8.x4.shared.b16 {%0,%1,%2,%3}, [%4];"
                 : "=r"(r0), "=r"(r1), "=r"(r2), "=r"(r3) : "r"(addr));
}

__device__ __forceinline__ void ldsm4t(uint32_t& r0, uint32_t& r1,
                                       uint32_t& r2, uint32_t& r3, uint32_t addr) {
    asm volatile("ldmatrix.sync.aligned.m8n8.x4.trans.shared.b16 {%0,%1,%2,%3}, [%4];"
                 : "=r"(r0), "=r"(r1), "=r"(r2), "=r"(r3) : "r"(addr));
}

__device__ __forceinline__ void mma_f16(float* c, const uint32_t* a, const uint32_t* b) {
    asm volatile(
        "mma.sync.aligned.m16n8k16.row.col.f32.f16.f16.f32 "
        "{%0,%1,%2,%3}, {%4,%5,%6,%7}, {%8,%9}, {%0,%1,%2,%3};"
        : "+f"(c[0]), "+f"(c[1]), "+f"(c[2]), "+f"(c[3])
        : "r"(a[0]), "r"(a[1]), "r"(a[2]), "r"(a[3]), "r"(b[0]), "r"(b[1]));
}

// swizzled smem address: row of RS bytes, 16B chunk c16, XOR low3 with row&7
__device__ __forceinline__ uint32_t swz(uint32_t base, int row, int c16, int rs_bytes) {
    return base + (uint32_t)row * (uint32_t)rs_bytes
                + ((uint32_t)(c16 ^ (row & 7)) << 4);
}

// ---- mbarrier primitives (base ISA) ----
#define MBARRIER_INIT(mbar, cnt) \
    asm volatile("mbarrier.init.shared.b64 [%0], %1;" \
        :: "r"((uint32_t)(mbar)), "r"((uint32_t)(cnt)) : "memory")

#define MBARRIER_ARRIVE(mbar) \
    asm volatile("mbarrier.arrive.shared.b64 _, [%0];" \
        :: "r"((uint32_t)(mbar)) : "memory")

#define CPASYNC_MBAR_ARRIVE(mbar) \
    asm volatile("cp.async.mbarrier.arrive.noinc.shared.b64 [%0];" \
        :: "r"((uint32_t)(mbar)) : "memory")

#define MBARRIER_WAIT_PARITY(mbar, parity) do { \
    uint32_t _m = (uint32_t)(mbar); \
    uint32_t _p = (uint32_t)(parity); \
    uint32_t _done; \
    asm volatile( \
        "{\n\t.reg .pred p;\n\t" \
        "mbarrier.try_wait.parity.acquire.cta.shared::cta.b64 p, [%1], %2;\n\t" \
        "selp.b32 %0, 1, 0, p;\n\t}" \
        : "=r"(_done) : "r"(_m), "r"(_p) : "memory"); \
    if (!_done) { \
        asm volatile( \
            "{\n\t.reg .pred P1;\n\t" \
            "WAIT_LOOP_%=:\n\t" \
            "mbarrier.try_wait.parity.acquire.cta.shared::cta.b64 P1, [%0], %1, 0x989680;\n\t" \
            "@P1 bra.uni WAIT_DONE_%=;\n\t" \
            "bra.uni WAIT_LOOP_%=;\n\t" \
            "WAIT_DONE_%=:\n\t}" \
            :: "r"(_m), "r"(_p) : "memory"); \
    } \
} while (0)

// ===========================================================================
// fp16 mma GEMM, free-running mbarrier ring, B row-major via ldsm.trans.
// C[M,N] = A[M,K] @ B[K,N]. A K-major [M,K]; B row-major [K,N].
// 128x128 CTA tile, BK=64, 3 stages, 256 threads (4x2 warps).
// OUT_HALF: store half, else float. K/64 >= 2.
// ===========================================================================
#define GEMM_STAGES 3
#define STAGE_BYTES 32768            // A 16KB (128x128B) + B 16KB (64x256B)
#define GEMM_SMEM (GEMM_STAGES * STAGE_BYTES + 64)  // 98368

template<int OUT_HALF>
__global__ __launch_bounds__(256) void gemm_f16_mma(
    const __half* __restrict__ A, const __half* __restrict__ B,
    void* __restrict__ Cv, int M, int N, int K)
{
    extern __shared__ __align__(1024) char smem[];
    const uint32_t sb = smem_u32(smem);
    const uint32_t MB = sb + (uint32_t)(GEMM_STAGES * STAGE_BYTES);

    const int tid  = threadIdx.x;
    const int lane = tid & 31;
    const int wid  = tid >> 5;
    const int wm   = (wid & 3) * 32;
    const int wn   = (wid >> 2) * 64;

    const int m0 = blockIdx.y * 128;
    const int n0 = blockIdx.x * 128;
    const __half* Ag = A + (size_t)m0 * K;
    const __half* Bg = B + n0;              // row-major [K, N]
    const int T = K / 64;

    if (tid == 0) {
        #pragma unroll
        for (int s = 0; s < GEMM_STAGES; s++) {
            MBARRIER_INIT(MB + 8 * s, 256);        // full[s]
            MBARRIER_INIT(MB + 24 + 8 * s, 256);   // empty[s]
        }
    }
    __syncthreads();

    auto load_stage = [&](int t, int s) {
        const uint32_t baseA = sb + (uint32_t)s * STAGE_BYTES;
        const uint32_t baseB = baseA + 16384;
        const int k0 = t * 64;
        #pragma unroll
        for (int i = 0; i < 4; i++) {        // A: 128 rows x 8 chunks (128B rows)
            int slot = i * 256 + tid;
            int row = slot >> 3, c = slot & 7;
            cp_async16(swz(baseA, row, c, 128),
                       Ag + (size_t)row * K + k0 + c * 8);
        }
        #pragma unroll
        for (int i = 0; i < 4; i++) {        // B: 64 k-rows x 16 chunks (256B rows)
            int slot = i * 256 + tid;
            int r = slot >> 4, c = slot & 15;
            cp_async16(swz(baseB, r, c, 256),
                       Bg + (size_t)(k0 + r) * N + c * 8);
        }
    };

    float acc[2][8][4];
    #pragma unroll
    for (int mt = 0; mt < 2; mt++)
        #pragma unroll
        for (int nt = 0; nt < 8; nt++)
            #pragma unroll
            for (int q = 0; q < 4; q++) acc[mt][nt][q] = 0.f;

    load_stage(0, 0); CPASYNC_MBAR_ARRIVE(MB + 0);
    load_stage(1, 1); CPASYNC_MBAR_ARRIVE(MB + 8);

    const int a_row16 = lane & 15;
    const int a_ch    = lane >> 4;
    const int bt_row  = ((lane >> 3) & 1) * 8 + (lane & 7);  // trans: k row
    const int bt_ch   = lane >> 4;                            // n chunk select

    for (int t = 0; t < T; t++) {
        // producer: tile t+2 into stage (t+2)%3
        {
            const int tt = t + 2;
            if (tt < T) {
                const int st = tt % GEMM_STAGES;
                if (tt >= GEMM_STAGES)
                    MBARRIER_WAIT_PARITY(MB + 24 + 8 * st,
                                         (uint32_t)((tt / GEMM_STAGES - 1) & 1));
                load_stage(tt, st);
                CPASYNC_MBAR_ARRIVE(MB + 8 * st);
            }
        }

        const int s  = t % GEMM_STAGES;
        const int ph = (t / GEMM_STAGES) & 1;
        MBARRIER_WAIT_PARITY(MB + 8 * s, (uint32_t)ph);   // tile t resident

        const uint32_t baseA = sb + (uint32_t)s * STAGE_BYTES;
        const uint32_t baseB = baseA + 16384;

        #pragma unroll
        for (int k16 = 0; k16 < 4; k16++) {
            uint32_t afr[2][4], bfr[4][4];
            #pragma unroll
            for (int mt = 0; mt < 2; mt++)
                ldsm4(afr[mt][0], afr[mt][1], afr[mt][2], afr[mt][3],
                      swz(baseA, wm + mt * 16 + a_row16, k16 * 2 + a_ch, 128));
            #pragma unroll
            for (int np = 0; np < 4; np++)
                ldsm4t(bfr[np][0], bfr[np][1], bfr[np][2], bfr[np][3],
                       swz(baseB, k16 * 16 + bt_row,
                           (wn >> 3) + np * 2 + bt_ch, 256));
            #pragma unroll
            for (int mt = 0; mt < 2; mt++)
                #pragma unroll
                for (int nt = 0; nt < 8; nt++) {
                    uint32_t b2[2] = { bfr[nt >> 1][(nt & 1) * 2],
                                       bfr[nt >> 1][(nt & 1) * 2 + 1] };
                    mma_f16(acc[mt][nt], afr[mt], b2);
                }
        }

        MBARRIER_ARRIVE(MB + 24 + 8 * s);   // done reading stage s this gen
    }

    const int g = lane >> 2;
    const int tg = lane & 3;
    #pragma unroll
    for (int mt = 0; mt < 2; mt++) {
        int row0 = m0 + wm + mt * 16 + g;
        #pragma unroll
        for (int nt = 0; nt < 8; nt++) {
            int col = n0 + wn + nt * 8 + tg * 2;
            if (OUT_HALF) {
                __half* C = (__half*)Cv;
                *(uint32_t*)(C + (size_t)row0 * N + col) =
                    pack_h2(acc[mt][nt][0], acc[mt][nt][1]);
                *(uint32_t*)(C + (size_t)(row0 + 8) * N + col) =
                    pack_h2(acc[mt][nt][2], acc[mt][nt][3]);
            } else {
                float* C = (float*)Cv;
                *(float2*)(C + (size_t)row0 * N + col) =
                    make_float2(acc[mt][nt][0], acc[mt][nt][1]);
                *(float2*)(C + (size_t)(row0 + 8) * N + col) =
                    make_float2(acc[mt][nt][2], acc[mt][nt][3]);
            }
        }
    }
}

// ===========================================================================
// Pre-pass: float -> half elementwise (n4 = count/4)
// ===========================================================================
__global__ __launch_bounds__(256) void conv_half_kernel(
    const float* __restrict__ in, __half* __restrict__ out, size_t n4)
{
    size_t i = (size_t)blockIdx.x * blockDim.x + threadIdx.x;
    size_t stride = (size_t)gridDim.x * blockDim.x;
    for (; i < n4; i += stride) {
        float4 v = ((const float4*)in)[i];
        uint2 o;
        o.x = pack_h2(v.x, v.y);
        o.y = pack_h2(v.z, v.w);
        ((uint2*)out)[i] = o;
    }
}

// ===========================================================================
// Flash attention, fp16 mma. 64-query-row CTAs (128 threads, 4 warps) so
// 2 CTAs/SM co-reside (4 warps/SMSP for latency hiding).
// Register-fed PV + rowsum-by-mma + h2exp2 + direct-V via ldsm.trans.
// 3 K+V stages of 32KB each + mbarrier ring. smem: 3*32768 + 64 = 98368 B.
// ===========================================================================
#define FLASH_SMEM 98368

__global__ __launch_bounds__(128, 2) void flash_mma_kernel(
    const __half* __restrict__ qkv, __half* __restrict__ O)
{
    extern __shared__ __align__(1024) char smem[];
    const uint32_t sb  = smem_u32(smem);
    const uint32_t MB  = sb + 98304u;            // full[s]=MB+8s, empty[s]=MB+24+8s

    const int tid  = threadIdx.x;
    const int lane = tid & 31;
    const int wid  = tid >> 5;          // 0..3
    const int qb   = 63 - blockIdx.x;   // 64-row block; heavy first
    const int h    = blockIdx.y;
    const float scale2 = 0.12751879652672068f;   // (1/sqrt(128)) * log2(e)
    const uint32_t ONES2 = 0x3C003C00u;          // half2(1,1)

    const int a_row16 = lane & 15;
    const int a_ch    = lane >> 4;
    const int b_row   = (lane & 7) + (lane >> 4) * 8;   // K (non-trans)
    const int b_ch    = (lane >> 3) & 1;
    const int bt_row  = ((lane >> 3) & 1) * 8 + (lane & 7);  // V (trans): k row
    const int bt_ch   = lane >> 4;                            // n chunk select
    const int g       = lane >> 2;
    const int tg      = lane & 3;

    // ---- Stage Q tile (64 x 256B rows, 16KB) into stage0 region
    {
        const __half* Qg = qkv + (size_t)(qb * 64) * QKVW + h * HD;
        #pragma unroll
        for (int i = 0; i < 8; i++) {
            int slot = i * 128 + tid;
            int r = slot >> 4, c = slot & 15;        // 64 rows x 16 chunks
            cp_async16(swz(sb, r, c, 256), Qg + (size_t)r * QKVW + c * 8);
        }
        asm volatile("cp.async.commit_group;" ::: "memory");
        asm volatile("cp.async.wait_group 0;" ::: "memory");
        __syncthreads();
    }
    uint32_t qf[8][4];
    #pragma unroll
    for (int k16 = 0; k16 < 8; k16++)
        ldsm4(qf[k16][0], qf[k16][1], qf[k16][2], qf[k16][3],
              swz(sb, wid * 16 + a_row16, k16 * 2 + a_ch, 256));
    __syncthreads();   // Q extraction done before stage0 overwritten

    if (tid == 0) {
        #pragma unroll
        for (int s = 0; s < 3; s++) {
            MBARRIER_INIT(MB + 8 * s, 128);        // full[s]
            MBARRIER_INIT(MB + 24 + 8 * s, 128);   // empty[s]
        }
    }
    __syncthreads();

    float oacc[16][4];
    #pragma unroll
    for (int nt = 0; nt < 16; nt++)
        #pragma unroll
        for (int q = 0; q < 4; q++) oacc[nt][q] = 0.f;
    float lacc[4] = {0.f, 0.f, 0.f, 0.f};       // rowsum fragment (l)
    float m0 = -1e30f, m1 = -1e30f;

    const int kb_end = min(qb + 1, 63);   // always >= 1
    const int qi0 = qb * 64 + wid * 16;

    // Load K+V tile t into stage st (16 cp.async per thread). Both 64x256B.
    auto load_tile = [&](int t, int st) {
        const uint32_t KSb = sb + (uint32_t)st * 32768u;
        const uint32_t VSb = KSb + 16384u;
        const __half* Kg = qkv + (size_t)(t * 64) * QKVW + DIM + h * HD;
        const __half* Vg = Kg + DIM;
        #pragma unroll
        for (int i = 0; i < 8; i++) {
            int slot = i * 128 + tid;
            int r = slot >> 4, c = slot & 15;            // 64 rows x 16 chunks
            cp_async16(swz(KSb, r, c, 256), Kg + (size_t)r * QKVW + c * 8);
        }
        #pragma unroll
        for (int i = 0; i < 8; i++) {
            int slot = i * 128 + tid;
            int r = slot >> 4, c = slot & 15;
            cp_async16(swz(VSb, r, c, 256), Vg + (size_t)r * QKVW + c * 8);
        }
    };

    // prologue: tiles 0 and 1 (generation 0 — no empty wait needed)
    load_tile(0, 0); CPASYNC_MBAR_ARRIVE(MB + 0);
    load_tile(1, 1); CPASYNC_MBAR_ARRIVE(MB + 8);

    for (int kb = 0; kb <= kb_end; kb++) {
        // ---- producer: tile kb+2 into stage (kb+2)%3
        {
            const int t = kb + 2;
            if (t <= kb_end) {
                const int st = t % 3;
                if (t >= 3)
                    MBARRIER_WAIT_PARITY(MB + 24 + 8 * st, (uint32_t)((t / 3 - 1) & 1));
                load_tile(t, st);
                CPASYNC_MBAR_ARRIVE(MB + 8 * st);
            }
        }

        const int s  = kb % 3;
        const int ph = (kb / 3) & 1;
        MBARRIER_WAIT_PARITY(MB + 8 * s, (uint32_t)ph);   // K+V tile kb resident

        const bool skipw = (kb * 64 > qi0 + 16);   // fully masked for this warp
        if (!skipw) {
            const uint32_t KSb = sb + (uint32_t)s * 32768u;
            const uint32_t VSb = KSb + 16384u;

            // ---- S = Q @ K^T  (m16 per warp, n64, k128)
            float sacc[8][4];
            #pragma unroll
            for (int nt = 0; nt < 8; nt++)
                #pragma unroll
                for (int q = 0; q < 4; q++) sacc[nt][q] = 0.f;

            #pragma unroll
            for (int k16 = 0; k16 < 8; k16++) {
                uint32_t bfr[4][4];
                #pragma unroll
                for (int np = 0; np < 4; np++)
                    ldsm4(bfr[np][0], bfr[np][1], bfr[np][2], bfr[np][3],
                          swz(KSb, np * 16 + b_row, k16 * 2 + b_ch, 256));
                #pragma unroll
                for (int nt = 0; nt < 8; nt++) {
                    uint32_t b2[2] = { bfr[nt >> 1][(nt & 1) * 2],
                                       bfr[nt >> 1][(nt & 1) * 2 + 1] };
                    mma_f16(sacc[nt], qf[k16], b2);
                }
            }

            // ---- softmax (exp2 domain): scale+mask, rowmax, P in half2
            const int row0 = qi0 + g, row1 = qi0 + g + 8;
            const bool nomask = (kb * 64 + 63 <= qi0 + 1);
            float mx0 = -1e30f, mx1 = -1e30f;
            if (nomask) {
                #pragma unroll
                for (int nt = 0; nt < 8; nt++)
                    #pragma unroll
                    for (int c = 0; c < 2; c++) {
                        float v0 = sacc[nt][c] * scale2;
                        float v1 = sacc[nt][c + 2] * scale2;
                        sacc[nt][c] = v0; sacc[nt][c + 2] = v1;
                        mx0 = fmaxf(mx0, v0); mx1 = fmaxf(mx1, v1);
                    }
            } else {
                #pragma unroll
                for (int nt = 0; nt < 8; nt++)
                    #pragma unroll
                    for (int c = 0; c < 2; c++) {
                        int kj = kb * 64 + nt * 8 + tg * 2 + c;
                        float v0 = (kj <= row0 + 1) ? sacc[nt][c] * scale2 : -1e30f;
                        float v1 = (kj <= row1 + 1) ? sacc[nt][c + 2] * scale2 : -1e30f;
                        sacc[nt][c] = v0; sacc[nt][c + 2] = v1;
                        mx0 = fmaxf(mx0, v0); mx1 = fmaxf(mx1, v1);
                    }
            }
            mx0 = fmaxf(mx0, __shfl_xor_sync(0xffffffffu, mx0, 1));
            mx0 = fmaxf(mx0, __shfl_xor_sync(0xffffffffu, mx0, 2));
            mx1 = fmaxf(mx1, __shfl_xor_sync(0xffffffffu, mx1, 1));
            mx1 = fmaxf(mx1, __shfl_xor_sync(0xffffffffu, mx1, 2));

            float newm0 = fmaxf(m0, mx0), newm1 = fmaxf(m1, mx1);
            float f0 = exp2f(m0 - newm0), f1 = exp2f(m1 - newm1);
            m0 = newm0; m1 = newm1;

            // P directly as half2 (one ex2.f16x2 per pair)
            uint32_t parr[8][2];
            #pragma unroll
            for (int nt = 0; nt < 8; nt++) {
                parr[nt][0] = exp2_h2(sacc[nt][0] - newm0, sacc[nt][1] - newm0);
                parr[nt][1] = exp2_h2(sacc[nt][2] - newm1, sacc[nt][3] - newm1);
            }

            // rescale O and l accumulators
            #pragma unroll
            for (int nt = 0; nt < 16; nt++) {
                oacc[nt][0] *= f0; oacc[nt][1] *= f0;
                oacc[nt][2] *= f1; oacc[nt][3] *= f1;
            }
            lacc[0] *= f0; lacc[1] *= f0; lacc[2] *= f1; lacc[3] *= f1;

            // ---- O += P @ V ; l += P @ 1  (V fragments via ldsm.trans)
            #pragma unroll
            for (int k16 = 0; k16 < 4; k16++) {
                uint32_t afr[4] = { parr[2 * k16][0],     parr[2 * k16][1],
                                    parr[2 * k16 + 1][0], parr[2 * k16 + 1][1] };
                uint32_t onesb[2] = { ONES2, ONES2 };
                mma_f16(lacc, afr, onesb);
                #pragma unroll
                for (int np = 0; np < 8; np++) {
                    uint32_t bfr[4];
                    ldsm4t(bfr[0], bfr[1], bfr[2], bfr[3],
                           swz(VSb, k16 * 16 + bt_row, np * 2 + bt_ch, 256));
                    uint32_t b2a[2] = { bfr[0], bfr[1] };
                    uint32_t b2b[2] = { bfr[2], bfr[3] };
                    mma_f16(oacc[np * 2 + 0], afr, b2a);
                    mma_f16(oacc[np * 2 + 1], afr, b2b);
                }
            }
        }

        MBARRIER_ARRIVE(MB + 24 + 8 * s);   // done with stage s this generation
    }

    // ---- epilogue: normalize by l (lacc[0]=rowsum(g), lacc[2]=rowsum(g+8))
    const float inv0 = 1.f / lacc[0], inv1 = 1.f / lacc[2];
    const int row0 = qb * 64 + wid * 16 + g;
    __half* Og = O + (size_t)row0 * DIM + h * HD;
    #pragma unroll
    for (int nt = 0; nt < 16; nt++) {
        int col = nt * 8 + tg * 2;
        *(uint32_t*)(Og + col) = pack_h2(oacc[nt][0] * inv0, oacc[nt][1] * inv0);
        *(uint32_t*)(Og + (size_t)8 * DIM + col) =
            pack_h2(oacc[nt][2] * inv1, oacc[nt][3] * inv1);
    }
}

// ===========================================================================
// Launch
// ===========================================================================
extern "C" void kernel_launch(void* const* d_in, const int* in_sizes, int n_in,
                              void* d_out, int out_size)
{
    const float* x     = (const float*)d_in[0];  // (4096, 2048)
    const float* w_qkv = (const float*)d_in[1];  // (2048, 6144)
    const float* w_o   = (const float*)d_in[2];  // (2048, 2048)
    float* out = (float*)d_out;                  // (4096, 2048)

    __half *qkvh, *oh, *xh, *wqkvh, *woh;
    cudaGetSymbolAddress((void**)&qkvh,  g_qkvh);
    cudaGetSymbolAddress((void**)&oh,    g_oh);
    cudaGetSymbolAddress((void**)&xh,    g_xh);
    cudaGetSymbolAddress((void**)&wqkvh, g_wqkvh);
    cudaGetSymbolAddress((void**)&woh,   g_woh);

    cudaFuncSetAttribute(gemm_f16_mma<1>,
                         cudaFuncAttributeMaxDynamicSharedMemorySize, GEMM_SMEM);
    cudaFuncSetAttribute(gemm_f16_mma<0>,
                         cudaFuncAttributeMaxDynamicSharedMemorySize, GEMM_SMEM);
    cudaFuncSetAttribute(flash_mma_kernel,
                         cudaFuncAttributeMaxDynamicSharedMemorySize, FLASH_SMEM);

    // 0) convert inputs to fp16 (no transposes needed — GEMM B is row-major)
    conv_half_kernel<<<2048, 256>>>(x, xh, (size_t)SEQ * DIM / 4);
    conv_half_kernel<<<4096, 256>>>(w_qkv, wqkvh, (size_t)DIM * QKVW / 4);
    conv_half_kernel<<<1024, 256>>>(w_o, woh, (size_t)DIM * DIM / 4);

    // 1) QKV projection (fp16 mma, half output)
    gemm_f16_mma<1><<<dim3(QKVW / 128, SEQ / 128), 256, GEMM_SMEM>>>(
        xh, wqkvh, qkvh, SEQ, QKVW, DIM);

    // 2) Attention (fp16 mma flash, 64-row CTAs, 2 CTAs/SM)
    flash_mma_kernel<<<dim3(SEQ / 64, NH), 128, FLASH_SMEM>>>(qkvh, oh);

    // 3) Output projection (fp16 mma, float output)
    gemm_f16_mma<0><<<dim3(DIM / 128, SEQ / 128), 256, GEMM_SMEM>>>(
        oh, woh, out, SEQ, DIM, DIM);
}

// round 14
// speedup vs baseline: 1.2797x; 1.0367x over previous
#include <cuda_runtime.h>
#include <cuda_fp16.h>
#include <cstdint>
#include <cstddef>

// Problem constants
#define SEQ   4096
#define DIM   2048
#define NH    16
#define HD    128
#define QKVW  (3 * DIM)   // 6144

// Scratch (device globals: allocation-free per harness rules)
__device__ __half g_qkvh [(size_t)SEQ * QKVW];  // (S, 3*dim) fp16
__device__ __half g_oh   [(size_t)SEQ * DIM];   // attention out fp16
__device__ __half g_xh   [(size_t)SEQ * DIM];   // x fp16
__device__ __half g_wqkvT[(size_t)QKVW * DIM];  // w_qkv^T fp16 (6144, 2048)
__device__ __half g_woT  [(size_t)DIM * DIM];   // w_o^T fp16

// ===========================================================================
// Helpers
// ===========================================================================
__device__ __forceinline__ uint32_t smem_u32(const void* p) {
    uint32_t a;
    asm("{ .reg .u64 t; cvta.to.shared.u64 t, %1; cvt.u32.u64 %0, t; }"
        : "=r"(a) : "l"(p));
    return a;
}

__device__ __forceinline__ uint32_t pack_h2(float lo, float hi) {
    __half2 h = __floats2half2_rn(lo, hi);
    return *(uint32_t*)&h;
}

__device__ __forceinline__ uint32_t exp2_h2(float lo, float hi) {
    __half2 h = h2exp2(__floats2half2_rn(lo, hi));
    return *(uint32_t*)&h;
}

__device__ __forceinline__ void cp_async16(uint32_t dst, const void* src) {
    asm volatile("cp.async.cg.shared.global [%0], [%1], 16;"
                 :: "r"(dst), "l"(src));
}

__device__ __forceinline__ void ldsm4(uint32_t& r0, uint32_t& r1,
                                      uint32_t& r2, uint32_t& r3, uint32_t addr) {
    asm volatile("ldmatrix.sync.aligned.m8n8.x4.shared.b16 {%0,%1,%2,%3}, [%4];"
                 : "=r"(r0), "=r"(r1), "=r"(r2), "=r"(r3) : "r"(addr));
}

__device__ __forceinline__ void ldsm4t(uint32_t& r0, uint32_t& r1,
                                       uint32_t& r2, uint32_t& r3, uint32_t addr) {
    asm volatile("ldmatrix.sync.aligned.m8n8.x4.trans.shared.b16 {%0,%1,%2,%3}, [%4];"
                 : "=r"(r0), "=r"(r1), "=r"(r2), "=r"(r3) : "r"(addr));
}

__device__ __forceinline__ void mma_f16(float* c, const uint32_t* a, const uint32_t* b) {
    asm volatile(
        "mma.sync.aligned.m16n8k16.row.col.f32.f16.f16.f32 "
        "{%0,%1,%2,%3}, {%4,%5,%6,%7}, {%8,%9}, {%0,%1,%2,%3};"
        : "+f"(c[0]), "+f"(c[1]), "+f"(c[2]), "+f"(c[3])
        : "r"(a[0]), "r"(a[1]), "r"(a[2]), "r"(a[3]), "r"(b[0]), "r"(b[1]));
}

// swizzled smem address: row of RS bytes, 16B chunk c16, XOR low3 with row&7
__device__ __forceinline__ uint32_t swz(uint32_t base, int row, int c16, int rs_bytes) {
    return base + (uint32_t)row * (uint32_t)rs_bytes
                + ((uint32_t)(c16 ^ (row & 7)) << 4);
}

// ---- mbarrier primitives (base ISA) ----
#define MBARRIER_INIT(mbar, cnt) \
    asm volatile("mbarrier.init.shared.b64 [%0], %1;" \
        :: "r"((uint32_t)(mbar)), "r"((uint32_t)(cnt)) : "memory")

#define MBARRIER_ARRIVE(mbar) \
    asm volatile("mbarrier.arrive.shared.b64 _, [%0];" \
        :: "r"((uint32_t)(mbar)) : "memory")

#define CPASYNC_MBAR_ARRIVE(mbar) \
    asm volatile("cp.async.mbarrier.arrive.noinc.shared.b64 [%0];" \
        :: "r"((uint32_t)(mbar)) : "memory")

#define MBARRIER_WAIT_PARITY(mbar, parity) do { \
    uint32_t _m = (uint32_t)(mbar); \
    uint32_t _p = (uint32_t)(parity); \
    uint32_t _done; \
    asm volatile( \
        "{\n\t.reg .pred p;\n\t" \
        "mbarrier.try_wait.parity.acquire.cta.shared::cta.b64 p, [%1], %2;\n\t" \
        "selp.b32 %0, 1, 0, p;\n\t}" \
        : "=r"(_done) : "r"(_m), "r"(_p) : "memory"); \
    if (!_done) { \
        asm volatile( \
            "{\n\t.reg .pred P1;\n\t" \
            "WAIT_LOOP_%=:\n\t" \
            "mbarrier.try_wait.parity.acquire.cta.shared::cta.b64 P1, [%0], %1, 0x989680;\n\t" \
            "@P1 bra.uni WAIT_DONE_%=;\n\t" \
            "bra.uni WAIT_LOOP_%=;\n\t" \
            "WAIT_DONE_%=:\n\t}" \
            :: "r"(_m), "r"(_p) : "memory"); \
    } \
} while (0)

// ===========================================================================
// fp16 mma GEMM (R12 config): free-running mbarrier ring, K-major B.
// C[M,N] = A[M,K] @ Bt[N,K]^T (half, both K-major).
// 128x128 CTA tile, BK=64 (128B rows), 3 stages, 256 threads (4x2 warps).
// OUT_HALF: store half, else float. K/64 >= 2.
// ===========================================================================
#define GEMM_STAGES 3
#define STAGE_BYTES 32768            // A 16KB + B 16KB
#define GEMM_SMEM (GEMM_STAGES * STAGE_BYTES + 64)  // 98368

template<int OUT_HALF>
__global__ __launch_bounds__(256) void gemm_f16_mma(
    const __half* __restrict__ A, const __half* __restrict__ Bt,
    void* __restrict__ Cv, int M, int N, int K)
{
    extern __shared__ __align__(1024) char smem[];
    const uint32_t sb = smem_u32(smem);
    const uint32_t MB = sb + (uint32_t)(GEMM_STAGES * STAGE_BYTES);

    const int tid  = threadIdx.x;
    const int lane = tid & 31;
    const int wid  = tid >> 5;
    const int wm   = (wid & 3) * 32;
    const int wn   = (wid >> 2) * 64;

    const int m0 = blockIdx.y * 128;
    const int n0 = blockIdx.x * 128;
    const __half* Ag = A  + (size_t)m0 * K;
    const __half* Bg = Bt + (size_t)n0 * K;
    const int T = K / 64;

    if (tid == 0) {
        #pragma unroll
        for (int s = 0; s < GEMM_STAGES; s++) {
            MBARRIER_INIT(MB + 8 * s, 256);        // full[s]
            MBARRIER_INIT(MB + 24 + 8 * s, 256);   // empty[s]
        }
    }
    __syncthreads();

    auto load_stage = [&](int t, int s) {
        const uint32_t baseA = sb + (uint32_t)s * STAGE_BYTES;
        const uint32_t baseB = baseA + 16384;
        const int k0 = t * 64;
        #pragma unroll
        for (int i = 0; i < 4; i++) {
            int slot = i * 256 + tid;
            int row = slot >> 3, c = slot & 7;       // 128 rows x 8 chunks
            cp_async16(swz(baseA, row, c, 128),
                       Ag + (size_t)row * K + k0 + c * 8);
            cp_async16(swz(baseB, row, c, 128),
                       Bg + (size_t)row * K + k0 + c * 8);
        }
    };

    float acc[2][8][4];
    #pragma unroll
    for (int mt = 0; mt < 2; mt++)
        #pragma unroll
        for (int nt = 0; nt < 8; nt++)
            #pragma unroll
            for (int q = 0; q < 4; q++) acc[mt][nt][q] = 0.f;

    load_stage(0, 0); CPASYNC_MBAR_ARRIVE(MB + 0);
    load_stage(1, 1); CPASYNC_MBAR_ARRIVE(MB + 8);

    const int a_row16 = lane & 15;
    const int a_ch    = lane >> 4;
    const int b_row   = (lane & 7) + (lane >> 4) * 8;
    const int b_ch    = (lane >> 3) & 1;

    for (int t = 0; t < T; t++) {
        // producer: tile t+2 into stage (t+2)%3
        {
            const int tt = t + 2;
            if (tt < T) {
                const int st = tt % GEMM_STAGES;
                if (tt >= GEMM_STAGES)
                    MBARRIER_WAIT_PARITY(MB + 24 + 8 * st,
                                         (uint32_t)((tt / GEMM_STAGES - 1) & 1));
                load_stage(tt, st);
                CPASYNC_MBAR_ARRIVE(MB + 8 * st);
            }
        }

        const int s  = t % GEMM_STAGES;
        const int ph = (t / GEMM_STAGES) & 1;
        MBARRIER_WAIT_PARITY(MB + 8 * s, (uint32_t)ph);   // tile t resident

        const uint32_t baseA = sb + (uint32_t)s * STAGE_BYTES;
        const uint32_t baseB = baseA + 16384;

        #pragma unroll
        for (int k16 = 0; k16 < 4; k16++) {
            uint32_t afr[2][4], bfr[4][4];
            #pragma unroll
            for (int mt = 0; mt < 2; mt++)
                ldsm4(afr[mt][0], afr[mt][1], afr[mt][2], afr[mt][3],
                      swz(baseA, wm + mt * 16 + a_row16, k16 * 2 + a_ch, 128));
            #pragma unroll
            for (int np = 0; np < 4; np++)
                ldsm4(bfr[np][0], bfr[np][1], bfr[np][2], bfr[np][3],
                      swz(baseB, wn + np * 16 + b_row, k16 * 2 + b_ch, 128));
            #pragma unroll
            for (int mt = 0; mt < 2; mt++)
                #pragma unroll
                for (int nt = 0; nt < 8; nt++) {
                    uint32_t b2[2] = { bfr[nt >> 1][(nt & 1) * 2],
                                       bfr[nt >> 1][(nt & 1) * 2 + 1] };
                    mma_f16(acc[mt][nt], afr[mt], b2);
                }
        }

        MBARRIER_ARRIVE(MB + 24 + 8 * s);   // done reading stage s this gen
    }

    const int g = lane >> 2;
    const int tg = lane & 3;
    #pragma unroll
    for (int mt = 0; mt < 2; mt++) {
        int row0 = m0 + wm + mt * 16 + g;
        #pragma unroll
        for (int nt = 0; nt < 8; nt++) {
            int col = n0 + wn + nt * 8 + tg * 2;
            if (OUT_HALF) {
                __half* C = (__half*)Cv;
                *(uint32_t*)(C + (size_t)row0 * N + col) =
                    pack_h2(acc[mt][nt][0], acc[mt][nt][1]);
                *(uint32_t*)(C + (size_t)(row0 + 8) * N + col) =
                    pack_h2(acc[mt][nt][2], acc[mt][nt][3]);
            } else {
                float* C = (float*)Cv;
                *(float2*)(C + (size_t)row0 * N + col) =
                    make_float2(acc[mt][nt][0], acc[mt][nt][1]);
                *(float2*)(C + (size_t)(row0 + 8) * N + col) =
                    make_float2(acc[mt][nt][2], acc[mt][nt][3]);
            }
        }
    }
}

// ===========================================================================
// Pre-passes
// ===========================================================================
__global__ __launch_bounds__(256) void conv_half_kernel(
    const float* __restrict__ in, __half* __restrict__ out, size_t n4)
{
    size_t i = (size_t)blockIdx.x * blockDim.x + threadIdx.x;
    size_t stride = (size_t)gridDim.x * blockDim.x;
    for (; i < n4; i += stride) {
        float4 v = ((const float4*)in)[i];
        uint2 o;
        o.x = pack_h2(v.x, v.y);
        o.y = pack_h2(v.z, v.w);
        ((uint2*)out)[i] = o;
    }
}

__global__ __launch_bounds__(256) void transpose_h_kernel(
    const float* __restrict__ in, __half* __restrict__ out, int R, int C)
{
    __shared__ float tile[32][33];
    const int bx = blockIdx.x * 32, by = blockIdx.y * 32;
    const int tx = threadIdx.x, ty = threadIdx.y;
    #pragma unroll
    for (int i = 0; i < 32; i += 8)
        tile[ty + i][tx] = in[(size_t)(by + ty + i) * C + bx + tx];
    __syncthreads();
    #pragma unroll
    for (int i = 0; i < 32; i += 8)
        out[(size_t)(bx + ty + i) * R + by + tx] = __float2half_rn(tile[tx][ty + i]);
}

// ===========================================================================
// Flash attention (R13 config): fp16 mma, 64-query-row CTAs (128 threads,
// 4 warps), 2 CTAs/SM. Register-fed PV + rowsum-by-mma + h2exp2 +
// direct-V via ldsm.trans. 3 K+V stages of 32KB + mbarrier ring.
// smem: 3*32768 + 64 = 98368 B.
// ===========================================================================
#define FLASH_SMEM 98368

__global__ __launch_bounds__(128, 2) void flash_mma_kernel(
    const __half* __restrict__ qkv, __half* __restrict__ O)
{
    extern __shared__ __align__(1024) char smem[];
    const uint32_t sb  = smem_u32(smem);
    const uint32_t MB  = sb + 98304u;            // full[s]=MB+8s, empty[s]=MB+24+8s

    const int tid  = threadIdx.x;
    const int lane = tid & 31;
    const int wid  = tid >> 5;          // 0..3
    const int qb   = 63 - blockIdx.x;   // 64-row block; heavy first
    const int h    = blockIdx.y;
    const float scale2 = 0.12751879652672068f;   // (1/sqrt(128)) * log2(e)
    const uint32_t ONES2 = 0x3C003C00u;          // half2(1,1)

    const int a_row16 = lane & 15;
    const int a_ch    = lane >> 4;
    const int b_row   = (lane & 7) + (lane >> 4) * 8;   // K (non-trans)
    const int b_ch    = (lane >> 3) & 1;
    const int bt_row  = ((lane >> 3) & 1) * 8 + (lane & 7);  // V (trans): k row
    const int bt_ch   = lane >> 4;                            // n chunk select
    const int g       = lane >> 2;
    const int tg      = lane & 3;

    // ---- Stage Q tile (64 x 256B rows, 16KB) into stage0 region
    {
        const __half* Qg = qkv + (size_t)(qb * 64) * QKVW + h * HD;
        #pragma unroll
        for (int i = 0; i < 8; i++) {
            int slot = i * 128 + tid;
            int r = slot >> 4, c = slot & 15;        // 64 rows x 16 chunks
            cp_async16(swz(sb, r, c, 256), Qg + (size_t)r * QKVW + c * 8);
        }
        asm volatile("cp.async.commit_group;" ::: "memory");
        asm volatile("cp.async.wait_group 0;" ::: "memory");
        __syncthreads();
    }
    uint32_t qf[8][4];
    #pragma unroll
    for (int k16 = 0; k16 < 8; k16++)
        ldsm4(qf[k16][0], qf[k16][1], qf[k16][2], qf[k16][3],
              swz(sb, wid * 16 + a_row16, k16 * 2 + a_ch, 256));
    __syncthreads();   // Q extraction done before stage0 overwritten

    if (tid == 0) {
        #pragma unroll
        for (int s = 0; s < 3; s++) {
            MBARRIER_INIT(MB + 8 * s, 128);        // full[s]
            MBARRIER_INIT(MB + 24 + 8 * s, 128);   // empty[s]
        }
    }
    __syncthreads();

    float oacc[16][4];
    #pragma unroll
    for (int nt = 0; nt < 16; nt++)
        #pragma unroll
        for (int q = 0; q < 4; q++) oacc[nt][q] = 0.f;
    float lacc[4] = {0.f, 0.f, 0.f, 0.f};       // rowsum fragment (l)
    float m0 = -1e30f, m1 = -1e30f;

    const int kb_end = min(qb + 1, 63);   // always >= 1
    const int qi0 = qb * 64 + wid * 16;

    // Load K+V tile t into stage st (16 cp.async per thread). Both 64x256B.
    auto load_tile = [&](int t, int st) {
        const uint32_t KSb = sb + (uint32_t)st * 32768u;
        const uint32_t VSb = KSb + 16384u;
        const __half* Kg = qkv + (size_t)(t * 64) * QKVW + DIM + h * HD;
        const __half* Vg = Kg + DIM;
        #pragma unroll
        for (int i = 0; i < 8; i++) {
            int slot = i * 128 + tid;
            int r = slot >> 4, c = slot & 15;            // 64 rows x 16 chunks
            cp_async16(swz(KSb, r, c, 256), Kg + (size_t)r * QKVW + c * 8);
        }
        #pragma unroll
        for (int i = 0; i < 8; i++) {
            int slot = i * 128 + tid;
            int r = slot >> 4, c = slot & 15;
            cp_async16(swz(VSb, r, c, 256), Vg + (size_t)r * QKVW + c * 8);
        }
    };

    // prologue: tiles 0 and 1 (generation 0 — no empty wait needed)
    load_tile(0, 0); CPASYNC_MBAR_ARRIVE(MB + 0);
    load_tile(1, 1); CPASYNC_MBAR_ARRIVE(MB + 8);

    for (int kb = 0; kb <= kb_end; kb++) {
        // ---- producer: tile kb+2 into stage (kb+2)%3
        {
            const int t = kb + 2;
            if (t <= kb_end) {
                const int st = t % 3;
                if (t >= 3)
                    MBARRIER_WAIT_PARITY(MB + 24 + 8 * st, (uint32_t)((t / 3 - 1) & 1));
                load_tile(t, st);
                CPASYNC_MBAR_ARRIVE(MB + 8 * st);
            }
        }

        const int s  = kb % 3;
        const int ph = (kb / 3) & 1;
        MBARRIER_WAIT_PARITY(MB + 8 * s, (uint32_t)ph);   // K+V tile kb resident

        const bool skipw = (kb * 64 > qi0 + 16);   // fully masked for this warp
        if (!skipw) {
            const uint32_t KSb = sb + (uint32_t)s * 32768u;
            const uint32_t VSb = KSb + 16384u;

            // ---- S = Q @ K^T  (m16 per warp, n64, k128)
            float sacc[8][4];
            #pragma unroll
            for (int nt = 0; nt < 8; nt++)
                #pragma unroll
                for (int q = 0; q < 4; q++) sacc[nt][q] = 0.f;

            #pragma unroll
            for (int k16 = 0; k16 < 8; k16++) {
                uint32_t bfr[4][4];
                #pragma unroll
                for (int np = 0; np < 4; np++)
                    ldsm4(bfr[np][0], bfr[np][1], bfr[np][2], bfr[np][3],
                          swz(KSb, np * 16 + b_row, k16 * 2 + b_ch, 256));
                #pragma unroll
                for (int nt = 0; nt < 8; nt++) {
                    uint32_t b2[2] = { bfr[nt >> 1][(nt & 1) * 2],
                                       bfr[nt >> 1][(nt & 1) * 2 + 1] };
                    mma_f16(sacc[nt], qf[k16], b2);
                }
            }

            // ---- softmax (exp2 domain): scale+mask, rowmax, P in half2
            const int row0 = qi0 + g, row1 = qi0 + g + 8;
            const bool nomask = (kb * 64 + 63 <= qi0 + 1);
            float mx0 = -1e30f, mx1 = -1e30f;
            if (nomask) {
                #pragma unroll
                for (int nt = 0; nt < 8; nt++)
                    #pragma unroll
                    for (int c = 0; c < 2; c++) {
                        float v0 = sacc[nt][c] * scale2;
                        float v1 = sacc[nt][c + 2] * scale2;
                        sacc[nt][c] = v0; sacc[nt][c + 2] = v1;
                        mx0 = fmaxf(mx0, v0); mx1 = fmaxf(mx1, v1);
                    }
            } else {
                #pragma unroll
                for (int nt = 0; nt < 8; nt++)
                    #pragma unroll
                    for (int c = 0; c < 2; c++) {
                        int kj = kb * 64 + nt * 8 + tg * 2 + c;
                        float v0 = (kj <= row0 + 1) ? sacc[nt][c] * scale2 : -1e30f;
                        float v1 = (kj <= row1 + 1) ? sacc[nt][c + 2] * scale2 : -1e30f;
                        sacc[nt][c] = v0; sacc[nt][c + 2] = v1;
                        mx0 = fmaxf(mx0, v0); mx1 = fmaxf(mx1, v1);
                    }
            }
            mx0 = fmaxf(mx0, __shfl_xor_sync(0xffffffffu, mx0, 1));
            mx0 = fmaxf(mx0, __shfl_xor_sync(0xffffffffu, mx0, 2));
            mx1 = fmaxf(mx1, __shfl_xor_sync(0xffffffffu, mx1, 1));
            mx1 = fmaxf(mx1, __shfl_xor_sync(0xffffffffu, mx1, 2));

            float newm0 = fmaxf(m0, mx0), newm1 = fmaxf(m1, mx1);
            float f0 = exp2f(m0 - newm0), f1 = exp2f(m1 - newm1);
            m0 = newm0; m1 = newm1;

            // P directly as half2 (one ex2.f16x2 per pair)
            uint32_t parr[8][2];
            #pragma unroll
            for (int nt = 0; nt < 8; nt++) {
                parr[nt][0] = exp2_h2(sacc[nt][0] - newm0, sacc[nt][1] - newm0);
                parr[nt][1] = exp2_h2(sacc[nt][2] - newm1, sacc[nt][3] - newm1);
            }

            // rescale O and l accumulators
            #pragma unroll
            for (int nt = 0; nt < 16; nt++) {
                oacc[nt][0] *= f0; oacc[nt][1] *= f0;
                oacc[nt][2] *= f1; oacc[nt][3] *= f1;
            }
            lacc[0] *= f0; lacc[1] *= f0; lacc[2] *= f1; lacc[3] *= f1;

            // ---- O += P @ V ; l += P @ 1  (V fragments via ldsm.trans)
            #pragma unroll
            for (int k16 = 0; k16 < 4; k16++) {
                uint32_t afr[4] = { parr[2 * k16][0],     parr[2 * k16][1],
                                    parr[2 * k16 + 1][0], parr[2 * k16 + 1][1] };
                uint32_t onesb[2] = { ONES2, ONES2 };
                mma_f16(lacc, afr, onesb);
                #pragma unroll
                for (int np = 0; np < 8; np++) {
                    uint32_t bfr[4];
                    ldsm4t(bfr[0], bfr[1], bfr[2], bfr[3],
                           swz(VSb, k16 * 16 + bt_row, np * 2 + bt_ch, 256));
                    uint32_t b2a[2] = { bfr[0], bfr[1] };
                    uint32_t b2b[2] = { bfr[2], bfr[3] };
                    mma_f16(oacc[np * 2 + 0], afr, b2a);
                    mma_f16(oacc[np * 2 + 1], afr, b2b);
                }
            }
        }

        MBARRIER_ARRIVE(MB + 24 + 8 * s);   // done with stage s this generation
    }

    // ---- epilogue: normalize by l (lacc[0]=rowsum(g), lacc[2]=rowsum(g+8))
    const float inv0 = 1.f / lacc[0], inv1 = 1.f / lacc[2];
    const int row0 = qb * 64 + wid * 16 + g;
    __half* Og = O + (size_t)row0 * DIM + h * HD;
    #pragma unroll
    for (int nt = 0; nt < 16; nt++) {
        int col = nt * 8 + tg * 2;
        *(uint32_t*)(Og + col) = pack_h2(oacc[nt][0] * inv0, oacc[nt][1] * inv0);
        *(uint32_t*)(Og + (size_t)8 * DIM + col) =
            pack_h2(oacc[nt][2] * inv1, oacc[nt][3] * inv1);
    }
}

// ===========================================================================
// Launch
// ===========================================================================
extern "C" void kernel_launch(void* const* d_in, const int* in_sizes, int n_in,
                              void* d_out, int out_size)
{
    const float* x     = (const float*)d_in[0];  // (4096, 2048)
    const float* w_qkv = (const float*)d_in[1];  // (2048, 6144)
    const float* w_o   = (const float*)d_in[2];  // (2048, 2048)
    float* out = (float*)d_out;                  // (4096, 2048)

    __half *qkvh, *oh, *xh, *wqkvT, *woT;
    cudaGetSymbolAddress((void**)&qkvh,  g_qkvh);
    cudaGetSymbolAddress((void**)&oh,    g_oh);
    cudaGetSymbolAddress((void**)&xh,    g_xh);
    cudaGetSymbolAddress((void**)&wqkvT, g_wqkvT);
    cudaGetSymbolAddress((void**)&woT,   g_woT);

    cudaFuncSetAttribute(gemm_f16_mma<1>,
                         cudaFuncAttributeMaxDynamicSharedMemorySize, GEMM_SMEM);
    cudaFuncSetAttribute(gemm_f16_mma<0>,
                         cudaFuncAttributeMaxDynamicSharedMemorySize, GEMM_SMEM);
    cudaFuncSetAttribute(flash_mma_kernel,
                         cudaFuncAttributeMaxDynamicSharedMemorySize, FLASH_SMEM);

    // 0) convert x; transpose+convert weights (K-major B for the GEMMs)
    conv_half_kernel<<<2048, 256>>>(x, xh, (size_t)SEQ * DIM / 4);
    transpose_h_kernel<<<dim3(QKVW / 32, DIM / 32), dim3(32, 8)>>>(w_qkv, wqkvT, DIM, QKVW);
    transpose_h_kernel<<<dim3(DIM / 32, DIM / 32), dim3(32, 8)>>>(w_o, woT, DIM, DIM);

    // 1) QKV projection (fp16 mma, half output)
    gemm_f16_mma<1><<<dim3(QKVW / 128, SEQ / 128), 256, GEMM_SMEM>>>(
        xh, wqkvT, qkvh, SEQ, QKVW, DIM);

    // 2) Attention (fp16 mma flash, 64-row CTAs, 2 CTAs/SM)
    flash_mma_kernel<<<dim3(SEQ / 64, NH), 128, FLASH_SMEM>>>(qkvh, oh);

    // 3) Output projection (fp16 mma, float output)
    gemm_f16_mma<0><<<dim3(DIM / 128, SEQ / 128), 256, GEMM_SMEM>>>(
        oh, woT, out, SEQ, DIM, DIM);
}

// round 15
// speedup vs baseline: 1.3274x; 1.0373x over previous
#include <cuda_runtime.h>
#include <cuda_fp16.h>
#include <cstdint>
#include <cstddef>

// Problem constants
#define SEQ   4096
#define DIM   2048
#define NH    16
#define HD    128
#define QKVW  (3 * DIM)   // 6144

// Scratch (device globals: allocation-free per harness rules)
__device__ __half g_qkvh [(size_t)SEQ * QKVW];  // (S, 3*dim) fp16
__device__ __half g_oh   [(size_t)SEQ * DIM];   // attention out fp16
__device__ __half g_xh   [(size_t)SEQ * DIM];   // x fp16
__device__ __half g_wqkvT[(size_t)QKVW * DIM];  // w_qkv^T fp16 (6144, 2048)
__device__ __half g_woT  [(size_t)DIM * DIM];   // w_o^T fp16

// ===========================================================================
// Helpers
// ===========================================================================
__device__ __forceinline__ uint32_t smem_u32(const void* p) {
    uint32_t a;
    asm("{ .reg .u64 t; cvta.to.shared.u64 t, %1; cvt.u32.u64 %0, t; }"
        : "=r"(a) : "l"(p));
    return a;
}

__device__ __forceinline__ uint32_t pack_h2(float lo, float hi) {
    __half2 h = __floats2half2_rn(lo, hi);
    return *(uint32_t*)&h;
}

__device__ __forceinline__ uint32_t exp2_h2(float lo, float hi) {
    __half2 h = h2exp2(__floats2half2_rn(lo, hi));
    return *(uint32_t*)&h;
}

__device__ __forceinline__ void cp_async16(uint32_t dst, const void* src) {
    asm volatile("cp.async.cg.shared.global [%0], [%1], 16;"
                 :: "r"(dst), "l"(src));
}

__device__ __forceinline__ void ldsm4(uint32_t& r0, uint32_t& r1,
                                      uint32_t& r2, uint32_t& r3, uint32_t addr) {
    asm volatile("ldmatrix.sync.aligned.m8n8.x4.shared.b16 {%0,%1,%2,%3}, [%4];"
                 : "=r"(r0), "=r"(r1), "=r"(r2), "=r"(r3) : "r"(addr));
}

__device__ __forceinline__ void ldsm4t(uint32_t& r0, uint32_t& r1,
                                       uint32_t& r2, uint32_t& r3, uint32_t addr) {
    asm volatile("ldmatrix.sync.aligned.m8n8.x4.trans.shared.b16 {%0,%1,%2,%3}, [%4];"
                 : "=r"(r0), "=r"(r1), "=r"(r2), "=r"(r3) : "r"(addr));
}

__device__ __forceinline__ void mma_f16(float* c, const uint32_t* a, const uint32_t* b) {
    asm volatile(
        "mma.sync.aligned.m16n8k16.row.col.f32.f16.f16.f32 "
        "{%0,%1,%2,%3}, {%4,%5,%6,%7}, {%8,%9}, {%0,%1,%2,%3};"
        : "+f"(c[0]), "+f"(c[1]), "+f"(c[2]), "+f"(c[3])
        : "r"(a[0]), "r"(a[1]), "r"(a[2]), "r"(a[3]), "r"(b[0]), "r"(b[1]));
}

// swizzled smem address: row of RS bytes, 16B chunk c16, XOR low3 with row&7
__device__ __forceinline__ uint32_t swz(uint32_t base, int row, int c16, int rs_bytes) {
    return base + (uint32_t)row * (uint32_t)rs_bytes
                + ((uint32_t)(c16 ^ (row & 7)) << 4);
}

// ---- mbarrier primitives (base ISA) ----
#define MBARRIER_INIT(mbar, cnt) \
    asm volatile("mbarrier.init.shared.b64 [%0], %1;" \
        :: "r"((uint32_t)(mbar)), "r"((uint32_t)(cnt)) : "memory")

#define MBARRIER_ARRIVE(mbar) \
    asm volatile("mbarrier.arrive.shared.b64 _, [%0];" \
        :: "r"((uint32_t)(mbar)) : "memory")

#define CPASYNC_MBAR_ARRIVE(mbar) \
    asm volatile("cp.async.mbarrier.arrive.noinc.shared.b64 [%0];" \
        :: "r"((uint32_t)(mbar)) : "memory")

#define MBARRIER_WAIT_PARITY(mbar, parity) do { \
    uint32_t _m = (uint32_t)(mbar); \
    uint32_t _p = (uint32_t)(parity); \
    uint32_t _done; \
    asm volatile( \
        "{\n\t.reg .pred p;\n\t" \
        "mbarrier.try_wait.parity.acquire.cta.shared::cta.b64 p, [%1], %2;\n\t" \
        "selp.b32 %0, 1, 0, p;\n\t}" \
        : "=r"(_done) : "r"(_m), "r"(_p) : "memory"); \
    if (!_done) { \
        asm volatile( \
            "{\n\t.reg .pred P1;\n\t" \
            "WAIT_LOOP_%=:\n\t" \
            "mbarrier.try_wait.parity.acquire.cta.shared::cta.b64 P1, [%0], %1, 0x989680;\n\t" \
            "@P1 bra.uni WAIT_DONE_%=;\n\t" \
            "bra.uni WAIT_LOOP_%=;\n\t" \
            "WAIT_DONE_%=:\n\t}" \
            :: "r"(_m), "r"(_p) : "memory"); \
    } \
} while (0)

// ===========================================================================
// fp16 mma GEMM (R12/R14 config): free-running mbarrier ring, K-major B.
// C[M,N] = A[M,K] @ Bt[N,K]^T (half, both K-major).
// 128x128 CTA tile, BK=64 (128B rows), 3 stages, 256 threads (4x2 warps).
// OUT_HALF: store half, else float. K/64 >= 2.
// ===========================================================================
#define GEMM_STAGES 3
#define STAGE_BYTES 32768            // A 16KB + B 16KB
#define GEMM_SMEM (GEMM_STAGES * STAGE_BYTES + 64)  // 98368

template<int OUT_HALF>
__global__ __launch_bounds__(256) void gemm_f16_mma(
    const __half* __restrict__ A, const __half* __restrict__ Bt,
    void* __restrict__ Cv, int M, int N, int K)
{
    extern __shared__ __align__(1024) char smem[];
    const uint32_t sb = smem_u32(smem);
    const uint32_t MB = sb + (uint32_t)(GEMM_STAGES * STAGE_BYTES);

    const int tid  = threadIdx.x;
    const int lane = tid & 31;
    const int wid  = tid >> 5;
    const int wm   = (wid & 3) * 32;
    const int wn   = (wid >> 2) * 64;

    const int m0 = blockIdx.y * 128;
    const int n0 = blockIdx.x * 128;
    const __half* Ag = A  + (size_t)m0 * K;
    const __half* Bg = Bt + (size_t)n0 * K;
    const int T = K / 64;

    if (tid == 0) {
        #pragma unroll
        for (int s = 0; s < GEMM_STAGES; s++) {
            MBARRIER_INIT(MB + 8 * s, 256);        // full[s]
            MBARRIER_INIT(MB + 24 + 8 * s, 256);   // empty[s]
        }
    }
    __syncthreads();

    auto load_stage = [&](int t, int s) {
        const uint32_t baseA = sb + (uint32_t)s * STAGE_BYTES;
        const uint32_t baseB = baseA + 16384;
        const int k0 = t * 64;
        #pragma unroll
        for (int i = 0; i < 4; i++) {
            int slot = i * 256 + tid;
            int row = slot >> 3, c = slot & 7;       // 128 rows x 8 chunks
            cp_async16(swz(baseA, row, c, 128),
                       Ag + (size_t)row * K + k0 + c * 8);
            cp_async16(swz(baseB, row, c, 128),
                       Bg + (size_t)row * K + k0 + c * 8);
        }
    };

    float acc[2][8][4];
    #pragma unroll
    for (int mt = 0; mt < 2; mt++)
        #pragma unroll
        for (int nt = 0; nt < 8; nt++)
            #pragma unroll
            for (int q = 0; q < 4; q++) acc[mt][nt][q] = 0.f;

    load_stage(0, 0); CPASYNC_MBAR_ARRIVE(MB + 0);
    load_stage(1, 1); CPASYNC_MBAR_ARRIVE(MB + 8);

    const int a_row16 = lane & 15;
    const int a_ch    = lane >> 4;
    const int b_row   = (lane & 7) + (lane >> 4) * 8;
    const int b_ch    = (lane >> 3) & 1;

    for (int t = 0; t < T; t++) {
        // producer: tile t+2 into stage (t+2)%3
        {
            const int tt = t + 2;
            if (tt < T) {
                const int st = tt % GEMM_STAGES;
                if (tt >= GEMM_STAGES)
                    MBARRIER_WAIT_PARITY(MB + 24 + 8 * st,
                                         (uint32_t)((tt / GEMM_STAGES - 1) & 1));
                load_stage(tt, st);
                CPASYNC_MBAR_ARRIVE(MB + 8 * st);
            }
        }

        const int s  = t % GEMM_STAGES;
        const int ph = (t / GEMM_STAGES) & 1;
        MBARRIER_WAIT_PARITY(MB + 8 * s, (uint32_t)ph);   // tile t resident

        const uint32_t baseA = sb + (uint32_t)s * STAGE_BYTES;
        const uint32_t baseB = baseA + 16384;

        #pragma unroll
        for (int k16 = 0; k16 < 4; k16++) {
            uint32_t afr[2][4], bfr[4][4];
            #pragma unroll
            for (int mt = 0; mt < 2; mt++)
                ldsm4(afr[mt][0], afr[mt][1], afr[mt][2], afr[mt][3],
                      swz(baseA, wm + mt * 16 + a_row16, k16 * 2 + a_ch, 128));
            #pragma unroll
            for (int np = 0; np < 4; np++)
                ldsm4(bfr[np][0], bfr[np][1], bfr[np][2], bfr[np][3],
                      swz(baseB, wn + np * 16 + b_row, k16 * 2 + b_ch, 128));
            #pragma unroll
            for (int mt = 0; mt < 2; mt++)
                #pragma unroll
                for (int nt = 0; nt < 8; nt++) {
                    uint32_t b2[2] = { bfr[nt >> 1][(nt & 1) * 2],
                                       bfr[nt >> 1][(nt & 1) * 2 + 1] };
                    mma_f16(acc[mt][nt], afr[mt], b2);
                }
        }

        MBARRIER_ARRIVE(MB + 24 + 8 * s);   // done reading stage s this gen
    }

    const int g = lane >> 2;
    const int tg = lane & 3;
    #pragma unroll
    for (int mt = 0; mt < 2; mt++) {
        int row0 = m0 + wm + mt * 16 + g;
        #pragma unroll
        for (int nt = 0; nt < 8; nt++) {
            int col = n0 + wn + nt * 8 + tg * 2;
            if (OUT_HALF) {
                __half* C = (__half*)Cv;
                *(uint32_t*)(C + (size_t)row0 * N + col) =
                    pack_h2(acc[mt][nt][0], acc[mt][nt][1]);
                *(uint32_t*)(C + (size_t)(row0 + 8) * N + col) =
                    pack_h2(acc[mt][nt][2], acc[mt][nt][3]);
            } else {
                float* C = (float*)Cv;
                *(float2*)(C + (size_t)row0 * N + col) =
                    make_float2(acc[mt][nt][0], acc[mt][nt][1]);
                *(float2*)(C + (size_t)(row0 + 8) * N + col) =
                    make_float2(acc[mt][nt][2], acc[mt][nt][3]);
            }
        }
    }
}

// ===========================================================================
// Pre-passes
// ===========================================================================
__global__ __launch_bounds__(256) void conv_half_kernel(
    const float* __restrict__ in, __half* __restrict__ out, size_t n4)
{
    size_t i = (size_t)blockIdx.x * blockDim.x + threadIdx.x;
    size_t stride = (size_t)gridDim.x * blockDim.x;
    for (; i < n4; i += stride) {
        float4 v = ((const float4*)in)[i];
        uint2 o;
        o.x = pack_h2(v.x, v.y);
        o.y = pack_h2(v.z, v.w);
        ((uint2*)out)[i] = o;
    }
}

__global__ __launch_bounds__(256) void transpose_h_kernel(
    const float* __restrict__ in, __half* __restrict__ out, int R, int C)
{
    __shared__ float tile[32][33];
    const int bx = blockIdx.x * 32, by = blockIdx.y * 32;
    const int tx = threadIdx.x, ty = threadIdx.y;
    #pragma unroll
    for (int i = 0; i < 32; i += 8)
        tile[ty + i][tx] = in[(size_t)(by + ty + i) * C + bx + tx];
    __syncthreads();
    #pragma unroll
    for (int i = 0; i < 32; i += 8)
        out[(size_t)(bx + ty + i) * R + by + tx] = __float2half_rn(tile[tx][ty + i]);
}

// ===========================================================================
// Flash attention, fp16 mma, SOFTWARE-PIPELINED tiles:
// S(kb+1) is computed BEFORE softmax(kb) so the 64 independent mma of the
// next tile hide the serial softmax chain (we are capped at 2 warps/SMSP).
// 64-query-row CTAs (128 threads, 4 warps), 2 CTAs/SM (<=256 regs/thread).
// Register-fed PV + rowsum-by-mma + h2exp2 + direct-V via ldsm.trans.
// 3 K+V stages of 32KB + mbarrier ring. smem: 3*32768 + 64 = 98368 B.
// Grid: (NH, SEQ/64) with qb = 63 - blockIdx.y  ->  heavy blocks first globally.
// ===========================================================================
#define FLASH_SMEM 98368

__global__ __launch_bounds__(128, 2) void flash_mma_kernel(
    const __half* __restrict__ qkv, __half* __restrict__ O)
{
    extern __shared__ __align__(1024) char smem[];
    const uint32_t sb  = smem_u32(smem);
    const uint32_t MB  = sb + 98304u;            // full[s]=MB+8s, empty[s]=MB+24+8s

    const int tid  = threadIdx.x;
    const int lane = tid & 31;
    const int wid  = tid >> 5;          // 0..3
    const int h    = blockIdx.x;
    const int qb   = 63 - blockIdx.y;   // heavy blocks first (global)
    const float scale2 = 0.12751879652672068f;   // (1/sqrt(128)) * log2(e)
    const uint32_t ONES2 = 0x3C003C00u;          // half2(1,1)

    const int a_row16 = lane & 15;
    const int a_ch    = lane >> 4;
    const int b_row   = (lane & 7) + (lane >> 4) * 8;   // K (non-trans)
    const int b_ch    = (lane >> 3) & 1;
    const int bt_row  = ((lane >> 3) & 1) * 8 + (lane & 7);  // V (trans): k row
    const int bt_ch   = lane >> 4;                            // n chunk select
    const int g       = lane >> 2;
    const int tg      = lane & 3;

    // ---- Stage Q tile (64 x 256B rows, 16KB) into stage0 region
    {
        const __half* Qg = qkv + (size_t)(qb * 64) * QKVW + h * HD;
        #pragma unroll
        for (int i = 0; i < 8; i++) {
            int slot = i * 128 + tid;
            int r = slot >> 4, c = slot & 15;        // 64 rows x 16 chunks
            cp_async16(swz(sb, r, c, 256), Qg + (size_t)r * QKVW + c * 8);
        }
        asm volatile("cp.async.commit_group;" ::: "memory");
        asm volatile("cp.async.wait_group 0;" ::: "memory");
        __syncthreads();
    }
    uint32_t qf[8][4];
    #pragma unroll
    for (int k16 = 0; k16 < 8; k16++)
        ldsm4(qf[k16][0], qf[k16][1], qf[k16][2], qf[k16][3],
              swz(sb, wid * 16 + a_row16, k16 * 2 + a_ch, 256));
    __syncthreads();   // Q extraction done before stage0 overwritten

    if (tid == 0) {
        #pragma unroll
        for (int s = 0; s < 3; s++) {
            MBARRIER_INIT(MB + 8 * s, 128);        // full[s]
            MBARRIER_INIT(MB + 24 + 8 * s, 128);   // empty[s]
        }
    }
    __syncthreads();

    float oacc[16][4];
    #pragma unroll
    for (int nt = 0; nt < 16; nt++)
        #pragma unroll
        for (int q = 0; q < 4; q++) oacc[nt][q] = 0.f;
    float lacc[4] = {0.f, 0.f, 0.f, 0.f};       // rowsum fragment (l)
    float m0 = -1e30f, m1 = -1e30f;

    const int kb_end = min(qb + 1, 63);   // always >= 1
    const int qi0 = qb * 64 + wid * 16;

    // Load K+V tile t into stage st (16 cp.async per thread). Both 64x256B.
    auto load_tile = [&](int t, int st) {
        const uint32_t KSb = sb + (uint32_t)st * 32768u;
        const uint32_t VSb = KSb + 16384u;
        const __half* Kg = qkv + (size_t)(t * 64) * QKVW + DIM + h * HD;
        const __half* Vg = Kg + DIM;
        #pragma unroll
        for (int i = 0; i < 8; i++) {
            int slot = i * 128 + tid;
            int r = slot >> 4, c = slot & 15;            // 64 rows x 16 chunks
            cp_async16(swz(KSb, r, c, 256), Kg + (size_t)r * QKVW + c * 8);
        }
        #pragma unroll
        for (int i = 0; i < 8; i++) {
            int slot = i * 128 + tid;
            int r = slot >> 4, c = slot & 15;
            cp_async16(swz(VSb, r, c, 256), Vg + (size_t)r * QKVW + c * 8);
        }
    };

    // S = Q @ K(tile t)^T into sacc (m16 per warp, n64, k128)
    auto compute_S = [&](float (&sacc)[8][4], int t) {
        const uint32_t KSb = sb + (uint32_t)(t % 3) * 32768u;
        #pragma unroll
        for (int nt = 0; nt < 8; nt++)
            #pragma unroll
            for (int q = 0; q < 4; q++) sacc[nt][q] = 0.f;
        #pragma unroll
        for (int k16 = 0; k16 < 8; k16++) {
            uint32_t bfr[4][4];
            #pragma unroll
            for (int np = 0; np < 4; np++)
                ldsm4(bfr[np][0], bfr[np][1], bfr[np][2], bfr[np][3],
                      swz(KSb, np * 16 + b_row, k16 * 2 + b_ch, 256));
            #pragma unroll
            for (int nt = 0; nt < 8; nt++) {
                uint32_t b2[2] = { bfr[nt >> 1][(nt & 1) * 2],
                                   bfr[nt >> 1][(nt & 1) * 2 + 1] };
                mma_f16(sacc[nt], qf[k16], b2);
            }
        }
    };

    // softmax(kb) on cur + PV(kb); assumes stage kb%3 full already waited.
    auto softmax_pv = [&](float (&cur)[8][4], int kb) {
        const uint32_t VSb = sb + (uint32_t)(kb % 3) * 32768u + 16384u;
        const int row0 = qi0 + g, row1 = qi0 + g + 8;
        const bool nomask = (kb * 64 + 63 <= qi0 + 1);
        float mx0 = -1e30f, mx1 = -1e30f;
        if (nomask) {
            #pragma unroll
            for (int nt = 0; nt < 8; nt++)
                #pragma unroll
                for (int c = 0; c < 2; c++) {
                    float v0 = cur[nt][c] * scale2;
                    float v1 = cur[nt][c + 2] * scale2;
                    cur[nt][c] = v0; cur[nt][c + 2] = v1;
                    mx0 = fmaxf(mx0, v0); mx1 = fmaxf(mx1, v1);
                }
        } else {
            #pragma unroll
            for (int nt = 0; nt < 8; nt++)
                #pragma unroll
                for (int c = 0; c < 2; c++) {
                    int kj = kb * 64 + nt * 8 + tg * 2 + c;
                    float v0 = (kj <= row0 + 1) ? cur[nt][c] * scale2 : -1e30f;
                    float v1 = (kj <= row1 + 1) ? cur[nt][c + 2] * scale2 : -1e30f;
                    cur[nt][c] = v0; cur[nt][c + 2] = v1;
                    mx0 = fmaxf(mx0, v0); mx1 = fmaxf(mx1, v1);
                }
        }
        mx0 = fmaxf(mx0, __shfl_xor_sync(0xffffffffu, mx0, 1));
        mx0 = fmaxf(mx0, __shfl_xor_sync(0xffffffffu, mx0, 2));
        mx1 = fmaxf(mx1, __shfl_xor_sync(0xffffffffu, mx1, 1));
        mx1 = fmaxf(mx1, __shfl_xor_sync(0xffffffffu, mx1, 2));

        float newm0 = fmaxf(m0, mx0), newm1 = fmaxf(m1, mx1);
        float f0 = exp2f(m0 - newm0), f1 = exp2f(m1 - newm1);
        m0 = newm0; m1 = newm1;

        uint32_t parr[8][2];
        #pragma unroll
        for (int nt = 0; nt < 8; nt++) {
            parr[nt][0] = exp2_h2(cur[nt][0] - newm0, cur[nt][1] - newm0);
            parr[nt][1] = exp2_h2(cur[nt][2] - newm1, cur[nt][3] - newm1);
        }

        #pragma unroll
        for (int nt = 0; nt < 16; nt++) {
            oacc[nt][0] *= f0; oacc[nt][1] *= f0;
            oacc[nt][2] *= f1; oacc[nt][3] *= f1;
        }
        lacc[0] *= f0; lacc[1] *= f0; lacc[2] *= f1; lacc[3] *= f1;

        #pragma unroll
        for (int k16 = 0; k16 < 4; k16++) {
            uint32_t afr[4] = { parr[2 * k16][0],     parr[2 * k16][1],
                                parr[2 * k16 + 1][0], parr[2 * k16 + 1][1] };
            uint32_t onesb[2] = { ONES2, ONES2 };
            mma_f16(lacc, afr, onesb);
            #pragma unroll
            for (int np = 0; np < 8; np++) {
                uint32_t bfr[4];
                ldsm4t(bfr[0], bfr[1], bfr[2], bfr[3],
                       swz(VSb, k16 * 16 + bt_row, np * 2 + bt_ch, 256));
                uint32_t b2a[2] = { bfr[0], bfr[1] };
                uint32_t b2b[2] = { bfr[2], bfr[3] };
                mma_f16(oacc[np * 2 + 0], afr, b2a);
                mma_f16(oacc[np * 2 + 1], afr, b2b);
            }
        }
    };

    // One pipeline step: producer(kb+2); S(kb+1) -> nxt; softmax+PV(kb) on cur.
    // Returns skip flag for tile kb+1.
    auto step = [&](float (&cur)[8][4], bool curskip,
                    float (&nxt)[8][4], int kb) -> bool {
        // producer: tile kb+2 into stage (kb+2)%3
        {
            const int t = kb + 2;
            if (t <= kb_end) {
                const int st = t % 3;
                if (t >= 3)
                    MBARRIER_WAIT_PARITY(MB + 24 + 8 * st, (uint32_t)((t / 3 - 1) & 1));
                load_tile(t, st);
                CPASYNC_MBAR_ARRIVE(MB + 8 * st);
            }
        }
        // S for tile kb+1 (issue its mma/ldsm before current softmax)
        bool skipn = true;
        if (kb + 1 <= kb_end) {
            const int t  = kb + 1;
            MBARRIER_WAIT_PARITY(MB + 8 * (t % 3), (uint32_t)((t / 3) & 1));
            skipn = (t * 64 > qi0 + 16);
            if (!skipn) compute_S(nxt, t);
        }
        // softmax + PV for tile kb
        if (!curskip) softmax_pv(cur, kb);
        MBARRIER_ARRIVE(MB + 24 + 8 * (kb % 3));
        return skipn;
    };

    // prologue: tiles 0 and 1 resident targets; S(0)
    load_tile(0, 0); CPASYNC_MBAR_ARRIVE(MB + 0);
    load_tile(1, 1); CPASYNC_MBAR_ARRIVE(MB + 8);

    float sacc_a[8][4], sacc_b[8][4];
    MBARRIER_WAIT_PARITY(MB + 0, 0u);        // tile 0 resident
    compute_S(sacc_a, 0);                    // kb=0 never masked-out

    {
        bool skip_cur = false;
        int kb = 0;
        for (;;) {
            bool sk = step(sacc_a, skip_cur, sacc_b, kb);
            kb++;
            if (kb > kb_end) break;
            skip_cur = sk;
            sk = step(sacc_b, skip_cur, sacc_a, kb);
            kb++;
            if (kb > kb_end) break;
            skip_cur = sk;
        }
    }

    // ---- epilogue: normalize by l (lacc[0]=rowsum(g), lacc[2]=rowsum(g+8))
    const float inv0 = 1.f / lacc[0], inv1 = 1.f / lacc[2];
    const int row0 = qb * 64 + wid * 16 + g;
    __half* Og = O + (size_t)row0 * DIM + h * HD;
    #pragma unroll
    for (int nt = 0; nt < 16; nt++) {
        int col = nt * 8 + tg * 2;
        *(uint32_t*)(Og + col) = pack_h2(oacc[nt][0] * inv0, oacc[nt][1] * inv0);
        *(uint32_t*)(Og + (size_t)8 * DIM + col) =
            pack_h2(oacc[nt][2] * inv1, oacc[nt][3] * inv1);
    }
}

// ===========================================================================
// Launch
// ===========================================================================
extern "C" void kernel_launch(void* const* d_in, const int* in_sizes, int n_in,
                              void* d_out, int out_size)
{
    const float* x     = (const float*)d_in[0];  // (4096, 2048)
    const float* w_qkv = (const float*)d_in[1];  // (2048, 6144)
    const float* w_o   = (const float*)d_in[2];  // (2048, 2048)
    float* out = (float*)d_out;                  // (4096, 2048)

    __half *qkvh, *oh, *xh, *wqkvT, *woT;
    cudaGetSymbolAddress((void**)&qkvh,  g_qkvh);
    cudaGetSymbolAddress((void**)&oh,    g_oh);
    cudaGetSymbolAddress((void**)&xh,    g_xh);
    cudaGetSymbolAddress((void**)&wqkvT, g_wqkvT);
    cudaGetSymbolAddress((void**)&woT,   g_woT);

    cudaFuncSetAttribute(gemm_f16_mma<1>,
                         cudaFuncAttributeMaxDynamicSharedMemorySize, GEMM_SMEM);
    cudaFuncSetAttribute(gemm_f16_mma<0>,
                         cudaFuncAttributeMaxDynamicSharedMemorySize, GEMM_SMEM);
    cudaFuncSetAttribute(flash_mma_kernel,
                         cudaFuncAttributeMaxDynamicSharedMemorySize, FLASH_SMEM);

    // 0) convert x; transpose+convert weights (K-major B for the GEMMs)
    conv_half_kernel<<<2048, 256>>>(x, xh, (size_t)SEQ * DIM / 4);
    transpose_h_kernel<<<dim3(QKVW / 32, DIM / 32), dim3(32, 8)>>>(w_qkv, wqkvT, DIM, QKVW);
    transpose_h_kernel<<<dim3(DIM / 32, DIM / 32), dim3(32, 8)>>>(w_o, woT, DIM, DIM);

    // 1) QKV projection (fp16 mma, half output)
    gemm_f16_mma<1><<<dim3(QKVW / 128, SEQ / 128), 256, GEMM_SMEM>>>(
        xh, wqkvT, qkvh, SEQ, QKVW, DIM);

    // 2) Attention (fp16 mma flash, software-pipelined S/softmax/PV)
    flash_mma_kernel<<<dim3(NH, SEQ / 64), 128, FLASH_SMEM>>>(qkvh, oh);

    // 3) Output projection (fp16 mma, float output)
    gemm_f16_mma<0><<<dim3(DIM / 128, SEQ / 128), 256, GEMM_SMEM>>>(
        oh, woT, out, SEQ, DIM, DIM);
}

// round 16
// speedup vs baseline: 1.3514x; 1.0180x over previous
#include <cuda_runtime.h>
#include <cuda_fp16.h>
#include <cstdint>
#include <cstddef>

// Problem constants
#define SEQ   4096
#define DIM   2048
#define NH    16
#define HD    128
#define QKVW  (3 * DIM)   // 6144

// Scratch (device globals: allocation-free per harness rules)
__device__ __half g_qkvh [(size_t)SEQ * QKVW];  // (S, 3*dim) fp16
__device__ __half g_oh   [(size_t)SEQ * DIM];   // attention out fp16
__device__ __half g_xh   [(size_t)SEQ * DIM];   // x fp16
__device__ __half g_wqkvT[(size_t)QKVW * DIM];  // w_qkv^T fp16 (6144, 2048)
__device__ __half g_woT  [(size_t)DIM * DIM];   // w_o^T fp16

// ===========================================================================
// Helpers
// ===========================================================================
__device__ __forceinline__ uint32_t smem_u32(const void* p) {
    uint32_t a;
    asm("{ .reg .u64 t; cvta.to.shared.u64 t, %1; cvt.u32.u64 %0, t; }"
        : "=r"(a) : "l"(p));
    return a;
}

__device__ __forceinline__ uint32_t pack_h2(float lo, float hi) {
    __half2 h = __floats2half2_rn(lo, hi);
    return *(uint32_t*)&h;
}

__device__ __forceinline__ uint32_t exp2_h2(float lo, float hi) {
    __half2 h = h2exp2(__floats2half2_rn(lo, hi));
    return *(uint32_t*)&h;
}

__device__ __forceinline__ void cp_async16(uint32_t dst, const void* src) {
    asm volatile("cp.async.cg.shared.global [%0], [%1], 16;"
                 :: "r"(dst), "l"(src));
}

__device__ __forceinline__ void ldsm4(uint32_t& r0, uint32_t& r1,
                                      uint32_t& r2, uint32_t& r3, uint32_t addr) {
    asm volatile("ldmatrix.sync.aligned.m8n8.x4.shared.b16 {%0,%1,%2,%3}, [%4];"
                 : "=r"(r0), "=r"(r1), "=r"(r2), "=r"(r3) : "r"(addr));
}

__device__ __forceinline__ void ldsm4t(uint32_t& r0, uint32_t& r1,
                                       uint32_t& r2, uint32_t& r3, uint32_t addr) {
    asm volatile("ldmatrix.sync.aligned.m8n8.x4.trans.shared.b16 {%0,%1,%2,%3}, [%4];"
                 : "=r"(r0), "=r"(r1), "=r"(r2), "=r"(r3) : "r"(addr));
}

__device__ __forceinline__ void mma_f16(float* c, const uint32_t* a, const uint32_t* b) {
    asm volatile(
        "mma.sync.aligned.m16n8k16.row.col.f32.f16.f16.f32 "
        "{%0,%1,%2,%3}, {%4,%5,%6,%7}, {%8,%9}, {%0,%1,%2,%3};"
        : "+f"(c[0]), "+f"(c[1]), "+f"(c[2]), "+f"(c[3])
        : "r"(a[0]), "r"(a[1]), "r"(a[2]), "r"(a[3]), "r"(b[0]), "r"(b[1]));
}

// swizzled smem address: row of RS bytes, 16B chunk c16, XOR low3 with row&7
__device__ __forceinline__ uint32_t swz(uint32_t base, int row, int c16, int rs_bytes) {
    return base + (uint32_t)row * (uint32_t)rs_bytes
                + ((uint32_t)(c16 ^ (row & 7)) << 4);
}

// ---- mbarrier primitives (base ISA) ----
#define MBARRIER_INIT(mbar, cnt) \
    asm volatile("mbarrier.init.shared.b64 [%0], %1;" \
        :: "r"((uint32_t)(mbar)), "r"((uint32_t)(cnt)) : "memory")

#define MBARRIER_ARRIVE(mbar) \
    asm volatile("mbarrier.arrive.shared.b64 _, [%0];" \
        :: "r"((uint32_t)(mbar)) : "memory")

#define CPASYNC_MBAR_ARRIVE(mbar) \
    asm volatile("cp.async.mbarrier.arrive.noinc.shared.b64 [%0];" \
        :: "r"((uint32_t)(mbar)) : "memory")

#define MBARRIER_WAIT_PARITY(mbar, parity) do { \
    uint32_t _m = (uint32_t)(mbar); \
    uint32_t _p = (uint32_t)(parity); \
    uint32_t _done; \
    asm volatile( \
        "{\n\t.reg .pred p;\n\t" \
        "mbarrier.try_wait.parity.acquire.cta.shared::cta.b64 p, [%1], %2;\n\t" \
        "selp.b32 %0, 1, 0, p;\n\t}" \
        : "=r"(_done) : "r"(_m), "r"(_p) : "memory"); \
    if (!_done) { \
        asm volatile( \
            "{\n\t.reg .pred P1;\n\t" \
            "WAIT_LOOP_%=:\n\t" \
            "mbarrier.try_wait.parity.acquire.cta.shared::cta.b64 P1, [%0], %1, 0x989680;\n\t" \
            "@P1 bra.uni WAIT_DONE_%=;\n\t" \
            "bra.uni WAIT_LOOP_%=;\n\t" \
            "WAIT_DONE_%=:\n\t}" \
            :: "r"(_m), "r"(_p) : "memory"); \
    } \
} while (0)

// ===========================================================================
// fp16 mma GEMM, 64x64 WARP TILES: 128 threads (4 warps, 2x2), 2 CTAs/SM.
// C[M,N] = A[M,K] @ Bt[N,K]^T (half, both K-major).
// 128x128 CTA tile, BK=64 (128B rows), 3-stage free-running mbarrier ring.
// Fragment duplication A x2, B x2 (was x2/x4) -> 25% less smem traffic.
// OUT_HALF: store half, else float. K/64 >= 2.
// ===========================================================================
#define GEMM_STAGES 3
#define STAGE_BYTES 32768            // A 16KB + B 16KB
#define GEMM_SMEM (GEMM_STAGES * STAGE_BYTES + 64)  // 98368

template<int OUT_HALF>
__global__ __launch_bounds__(128, 2) void gemm_f16_mma(
    const __half* __restrict__ A, const __half* __restrict__ Bt,
    void* __restrict__ Cv, int M, int N, int K)
{
    extern __shared__ __align__(1024) char smem[];
    const uint32_t sb = smem_u32(smem);
    const uint32_t MB = sb + (uint32_t)(GEMM_STAGES * STAGE_BYTES);

    const int tid  = threadIdx.x;
    const int lane = tid & 31;
    const int wid  = tid >> 5;          // 0..3
    const int wm   = (wid & 1) * 64;    // warp M offset
    const int wn   = (wid >> 1) * 64;   // warp N offset

    const int m0 = blockIdx.y * 128;
    const int n0 = blockIdx.x * 128;
    const __half* Ag = A  + (size_t)m0 * K;
    const __half* Bg = Bt + (size_t)n0 * K;
    const int T = K / 64;

    if (tid == 0) {
        #pragma unroll
        for (int s = 0; s < GEMM_STAGES; s++) {
            MBARRIER_INIT(MB + 8 * s, 128);        // full[s]
            MBARRIER_INIT(MB + 24 + 8 * s, 128);   // empty[s]
        }
    }
    __syncthreads();

    auto load_stage = [&](int t, int s) {
        const uint32_t baseA = sb + (uint32_t)s * STAGE_BYTES;
        const uint32_t baseB = baseA + 16384;
        const int k0 = t * 64;
        #pragma unroll
        for (int i = 0; i < 8; i++) {
            int slot = i * 128 + tid;
            int row = slot >> 3, c = slot & 7;       // 128 rows x 8 chunks
            cp_async16(swz(baseA, row, c, 128),
                       Ag + (size_t)row * K + k0 + c * 8);
            cp_async16(swz(baseB, row, c, 128),
                       Bg + (size_t)row * K + k0 + c * 8);
        }
    };

    float acc[4][8][4];
    #pragma unroll
    for (int mt = 0; mt < 4; mt++)
        #pragma unroll
        for (int nt = 0; nt < 8; nt++)
            #pragma unroll
            for (int q = 0; q < 4; q++) acc[mt][nt][q] = 0.f;

    load_stage(0, 0); CPASYNC_MBAR_ARRIVE(MB + 0);
    load_stage(1, 1); CPASYNC_MBAR_ARRIVE(MB + 8);

    const int a_row16 = lane & 15;
    const int a_ch    = lane >> 4;
    const int b_row   = (lane & 7) + (lane >> 4) * 8;
    const int b_ch    = (lane >> 3) & 1;

    for (int t = 0; t < T; t++) {
        // producer: tile t+2 into stage (t+2)%3
        {
            const int tt = t + 2;
            if (tt < T) {
                const int st = tt % GEMM_STAGES;
                if (tt >= GEMM_STAGES)
                    MBARRIER_WAIT_PARITY(MB + 24 + 8 * st,
                                         (uint32_t)((tt / GEMM_STAGES - 1) & 1));
                load_stage(tt, st);
                CPASYNC_MBAR_ARRIVE(MB + 8 * st);
            }
        }

        const int s  = t % GEMM_STAGES;
        const int ph = (t / GEMM_STAGES) & 1;
        MBARRIER_WAIT_PARITY(MB + 8 * s, (uint32_t)ph);   // tile t resident

        const uint32_t baseA = sb + (uint32_t)s * STAGE_BYTES;
        const uint32_t baseB = baseA + 16384;

        #pragma unroll
        for (int k16 = 0; k16 < 4; k16++) {
            uint32_t afr[4][4], bfr[4][4];
            #pragma unroll
            for (int mt = 0; mt < 4; mt++)
                ldsm4(afr[mt][0], afr[mt][1], afr[mt][2], afr[mt][3],
                      swz(baseA, wm + mt * 16 + a_row16, k16 * 2 + a_ch, 128));
            #pragma unroll
            for (int np = 0; np < 4; np++)
                ldsm4(bfr[np][0], bfr[np][1], bfr[np][2], bfr[np][3],
                      swz(baseB, wn + np * 16 + b_row, k16 * 2 + b_ch, 128));
            #pragma unroll
            for (int mt = 0; mt < 4; mt++)
                #pragma unroll
                for (int nt = 0; nt < 8; nt++) {
                    uint32_t b2[2] = { bfr[nt >> 1][(nt & 1) * 2],
                                       bfr[nt >> 1][(nt & 1) * 2 + 1] };
                    mma_f16(acc[mt][nt], afr[mt], b2);
                }
        }

        MBARRIER_ARRIVE(MB + 24 + 8 * s);   // done reading stage s this gen
    }

    const int g = lane >> 2;
    const int tg = lane & 3;
    #pragma unroll
    for (int mt = 0; mt < 4; mt++) {
        int row0 = m0 + wm + mt * 16 + g;
        #pragma unroll
        for (int nt = 0; nt < 8; nt++) {
            int col = n0 + wn + nt * 8 + tg * 2;
            if (OUT_HALF) {
                __half* C = (__half*)Cv;
                *(uint32_t*)(C + (size_t)row0 * N + col) =
                    pack_h2(acc[mt][nt][0], acc[mt][nt][1]);
                *(uint32_t*)(C + (size_t)(row0 + 8) * N + col) =
                    pack_h2(acc[mt][nt][2], acc[mt][nt][3]);
            } else {
                float* C = (float*)Cv;
                *(float2*)(C + (size_t)row0 * N + col) =
                    make_float2(acc[mt][nt][0], acc[mt][nt][1]);
                *(float2*)(C + (size_t)(row0 + 8) * N + col) =
                    make_float2(acc[mt][nt][2], acc[mt][nt][3]);
            }
        }
    }
}

// ===========================================================================
// Pre-passes
// ===========================================================================
__global__ __launch_bounds__(256) void conv_half_kernel(
    const float* __restrict__ in, __half* __restrict__ out, size_t n4)
{
    size_t i = (size_t)blockIdx.x * blockDim.x + threadIdx.x;
    size_t stride = (size_t)gridDim.x * blockDim.x;
    for (; i < n4; i += stride) {
        float4 v = ((const float4*)in)[i];
        uint2 o;
        o.x = pack_h2(v.x, v.y);
        o.y = pack_h2(v.z, v.w);
        ((uint2*)out)[i] = o;
    }
}

__global__ __launch_bounds__(256) void transpose_h_kernel(
    const float* __restrict__ in, __half* __restrict__ out, int R, int C)
{
    __shared__ float tile[32][33];
    const int bx = blockIdx.x * 32, by = blockIdx.y * 32;
    const int tx = threadIdx.x, ty = threadIdx.y;
    #pragma unroll
    for (int i = 0; i < 32; i += 8)
        tile[ty + i][tx] = in[(size_t)(by + ty + i) * C + bx + tx];
    __syncthreads();
    #pragma unroll
    for (int i = 0; i < 32; i += 8)
        out[(size_t)(bx + ty + i) * R + by + tx] = __float2half_rn(tile[tx][ty + i]);
}

// ===========================================================================
// Flash attention (R15 config, unchanged): fp16 mma, software-pipelined
// S(kb+1) before softmax(kb). 64-query-row CTAs (128 threads, 4 warps),
// 2 CTAs/SM. Register-fed PV + rowsum-by-mma + h2exp2 + direct-V ldsm.trans.
// 3 K+V stages of 32KB + mbarrier ring. smem: 3*32768 + 64 = 98368 B.
// ===========================================================================
#define FLASH_SMEM 98368

__global__ __launch_bounds__(128, 2) void flash_mma_kernel(
    const __half* __restrict__ qkv, __half* __restrict__ O)
{
    extern __shared__ __align__(1024) char smem[];
    const uint32_t sb  = smem_u32(smem);
    const uint32_t MB  = sb + 98304u;            // full[s]=MB+8s, empty[s]=MB+24+8s

    const int tid  = threadIdx.x;
    const int lane = tid & 31;
    const int wid  = tid >> 5;          // 0..3
    const int h    = blockIdx.x;
    const int qb   = 63 - blockIdx.y;   // heavy blocks first (global)
    const float scale2 = 0.12751879652672068f;   // (1/sqrt(128)) * log2(e)
    const uint32_t ONES2 = 0x3C003C00u;          // half2(1,1)

    const int a_row16 = lane & 15;
    const int a_ch    = lane >> 4;
    const int b_row   = (lane & 7) + (lane >> 4) * 8;   // K (non-trans)
    const int b_ch    = (lane >> 3) & 1;
    const int bt_row  = ((lane >> 3) & 1) * 8 + (lane & 7);  // V (trans): k row
    const int bt_ch   = lane >> 4;                            // n chunk select
    const int g       = lane >> 2;
    const int tg      = lane & 3;

    // ---- Stage Q tile (64 x 256B rows, 16KB) into stage0 region
    {
        const __half* Qg = qkv + (size_t)(qb * 64) * QKVW + h * HD;
        #pragma unroll
        for (int i = 0; i < 8; i++) {
            int slot = i * 128 + tid;
            int r = slot >> 4, c = slot & 15;        // 64 rows x 16 chunks
            cp_async16(swz(sb, r, c, 256), Qg + (size_t)r * QKVW + c * 8);
        }
        asm volatile("cp.async.commit_group;" ::: "memory");
        asm volatile("cp.async.wait_group 0;" ::: "memory");
        __syncthreads();
    }
    uint32_t qf[8][4];
    #pragma unroll
    for (int k16 = 0; k16 < 8; k16++)
        ldsm4(qf[k16][0], qf[k16][1], qf[k16][2], qf[k16][3],
              swz(sb, wid * 16 + a_row16, k16 * 2 + a_ch, 256));
    __syncthreads();   // Q extraction done before stage0 overwritten

    if (tid == 0) {
        #pragma unroll
        for (int s = 0; s < 3; s++) {
            MBARRIER_INIT(MB + 8 * s, 128);        // full[s]
            MBARRIER_INIT(MB + 24 + 8 * s, 128);   // empty[s]
        }
    }
    __syncthreads();

    float oacc[16][4];
    #pragma unroll
    for (int nt = 0; nt < 16; nt++)
        #pragma unroll
        for (int q = 0; q < 4; q++) oacc[nt][q] = 0.f;
    float lacc[4] = {0.f, 0.f, 0.f, 0.f};       // rowsum fragment (l)
    float m0 = -1e30f, m1 = -1e30f;

    const int kb_end = min(qb + 1, 63);   // always >= 1
    const int qi0 = qb * 64 + wid * 16;

    // Load K+V tile t into stage st (16 cp.async per thread). Both 64x256B.
    auto load_tile = [&](int t, int st) {
        const uint32_t KSb = sb + (uint32_t)st * 32768u;
        const uint32_t VSb = KSb + 16384u;
        const __half* Kg = qkv + (size_t)(t * 64) * QKVW + DIM + h * HD;
        const __half* Vg = Kg + DIM;
        #pragma unroll
        for (int i = 0; i < 8; i++) {
            int slot = i * 128 + tid;
            int r = slot >> 4, c = slot & 15;            // 64 rows x 16 chunks
            cp_async16(swz(KSb, r, c, 256), Kg + (size_t)r * QKVW + c * 8);
        }
        #pragma unroll
        for (int i = 0; i < 8; i++) {
            int slot = i * 128 + tid;
            int r = slot >> 4, c = slot & 15;
            cp_async16(swz(VSb, r, c, 256), Vg + (size_t)r * QKVW + c * 8);
        }
    };

    // S = Q @ K(tile t)^T into sacc (m16 per warp, n64, k128)
    auto compute_S = [&](float (&sacc)[8][4], int t) {
        const uint32_t KSb = sb + (uint32_t)(t % 3) * 32768u;
        #pragma unroll
        for (int nt = 0; nt < 8; nt++)
            #pragma unroll
            for (int q = 0; q < 4; q++) sacc[nt][q] = 0.f;
        #pragma unroll
        for (int k16 = 0; k16 < 8; k16++) {
            uint32_t bfr[4][4];
            #pragma unroll
            for (int np = 0; np < 4; np++)
                ldsm4(bfr[np][0], bfr[np][1], bfr[np][2], bfr[np][3],
                      swz(KSb, np * 16 + b_row, k16 * 2 + b_ch, 256));
            #pragma unroll
            for (int nt = 0; nt < 8; nt++) {
                uint32_t b2[2] = { bfr[nt >> 1][(nt & 1) * 2],
                                   bfr[nt >> 1][(nt & 1) * 2 + 1] };
                mma_f16(sacc[nt], qf[k16], b2);
            }
        }
    };

    // softmax(kb) on cur + PV(kb); assumes stage kb%3 full already waited.
    auto softmax_pv = [&](float (&cur)[8][4], int kb) {
        const uint32_t VSb = sb + (uint32_t)(kb % 3) * 32768u + 16384u;
        const int row0 = qi0 + g, row1 = qi0 + g + 8;
        const bool nomask = (kb * 64 + 63 <= qi0 + 1);
        float mx0 = -1e30f, mx1 = -1e30f;
        if (nomask) {
            #pragma unroll
            for (int nt = 0; nt < 8; nt++)
                #pragma unroll
                for (int c = 0; c < 2; c++) {
                    float v0 = cur[nt][c] * scale2;
                    float v1 = cur[nt][c + 2] * scale2;
                    cur[nt][c] = v0; cur[nt][c + 2] = v1;
                    mx0 = fmaxf(mx0, v0); mx1 = fmaxf(mx1, v1);
                }
        } else {
            #pragma unroll
            for (int nt = 0; nt < 8; nt++)
                #pragma unroll
                for (int c = 0; c < 2; c++) {
                    int kj = kb * 64 + nt * 8 + tg * 2 + c;
                    float v0 = (kj <= row0 + 1) ? cur[nt][c] * scale2 : -1e30f;
                    float v1 = (kj <= row1 + 1) ? cur[nt][c + 2] * scale2 : -1e30f;
                    cur[nt][c] = v0; cur[nt][c + 2] = v1;
                    mx0 = fmaxf(mx0, v0); mx1 = fmaxf(mx1, v1);
                }
        }
        mx0 = fmaxf(mx0, __shfl_xor_sync(0xffffffffu, mx0, 1));
        mx0 = fmaxf(mx0, __shfl_xor_sync(0xffffffffu, mx0, 2));
        mx1 = fmaxf(mx1, __shfl_xor_sync(0xffffffffu, mx1, 1));
        mx1 = fmaxf(mx1, __shfl_xor_sync(0xffffffffu, mx1, 2));

        float newm0 = fmaxf(m0, mx0), newm1 = fmaxf(m1, mx1);
        float f0 = exp2f(m0 - newm0), f1 = exp2f(m1 - newm1);
        m0 = newm0; m1 = newm1;

        uint32_t parr[8][2];
        #pragma unroll
        for (int nt = 0; nt < 8; nt++) {
            parr[nt][0] = exp2_h2(cur[nt][0] - newm0, cur[nt][1] - newm0);
            parr[nt][1] = exp2_h2(cur[nt][2] - newm1, cur[nt][3] - newm1);
        }

        #pragma unroll
        for (int nt = 0; nt < 16; nt++) {
            oacc[nt][0] *= f0; oacc[nt][1] *= f0;
            oacc[nt][2] *= f1; oacc[nt][3] *= f1;
        }
        lacc[0] *= f0; lacc[1] *= f0; lacc[2] *= f1; lacc[3] *= f1;

        #pragma unroll
        for (int k16 = 0; k16 < 4; k16++) {
            uint32_t afr[4] = { parr[2 * k16][0],     parr[2 * k16][1],
                                parr[2 * k16 + 1][0], parr[2 * k16 + 1][1] };
            uint32_t onesb[2] = { ONES2, ONES2 };
            mma_f16(lacc, afr, onesb);
            #pragma unroll
            for (int np = 0; np < 8; np++) {
                uint32_t bfr[4];
                ldsm4t(bfr[0], bfr[1], bfr[2], bfr[3],
                       swz(VSb, k16 * 16 + bt_row, np * 2 + bt_ch, 256));
                uint32_t b2a[2] = { bfr[0], bfr[1] };
                uint32_t b2b[2] = { bfr[2], bfr[3] };
                mma_f16(oacc[np * 2 + 0], afr, b2a);
                mma_f16(oacc[np * 2 + 1], afr, b2b);
            }
        }
    };

    // One pipeline step: producer(kb+2); S(kb+1) -> nxt; softmax+PV(kb) on cur.
    auto step = [&](float (&cur)[8][4], bool curskip,
                    float (&nxt)[8][4], int kb) -> bool {
        {
            const int t = kb + 2;
            if (t <= kb_end) {
                const int st = t % 3;
                if (t >= 3)
                    MBARRIER_WAIT_PARITY(MB + 24 + 8 * st, (uint32_t)((t / 3 - 1) & 1));
                load_tile(t, st);
                CPASYNC_MBAR_ARRIVE(MB + 8 * st);
            }
        }
        bool skipn = true;
        if (kb + 1 <= kb_end) {
            const int t  = kb + 1;
            MBARRIER_WAIT_PARITY(MB + 8 * (t % 3), (uint32_t)((t / 3) & 1));
            skipn = (t * 64 > qi0 + 16);
            if (!skipn) compute_S(nxt, t);
        }
        if (!curskip) softmax_pv(cur, kb);
        MBARRIER_ARRIVE(MB + 24 + 8 * (kb % 3));
        return skipn;
    };

    // prologue
    load_tile(0, 0); CPASYNC_MBAR_ARRIVE(MB + 0);
    load_tile(1, 1); CPASYNC_MBAR_ARRIVE(MB + 8);

    float sacc_a[8][4], sacc_b[8][4];
    MBARRIER_WAIT_PARITY(MB + 0, 0u);        // tile 0 resident
    compute_S(sacc_a, 0);                    // kb=0 never masked-out

    {
        bool skip_cur = false;
        int kb = 0;
        for (;;) {
            bool sk = step(sacc_a, skip_cur, sacc_b, kb);
            kb++;
            if (kb > kb_end) break;
            skip_cur = sk;
            sk = step(sacc_b, skip_cur, sacc_a, kb);
            kb++;
            if (kb > kb_end) break;
            skip_cur = sk;
        }
    }

    // ---- epilogue: normalize by l (lacc[0]=rowsum(g), lacc[2]=rowsum(g+8))
    const float inv0 = 1.f / lacc[0], inv1 = 1.f / lacc[2];
    const int row0 = qb * 64 + wid * 16 + g;
    __half* Og = O + (size_t)row0 * DIM + h * HD;
    #pragma unroll
    for (int nt = 0; nt < 16; nt++) {
        int col = nt * 8 + tg * 2;
        *(uint32_t*)(Og + col) = pack_h2(oacc[nt][0] * inv0, oacc[nt][1] * inv0);
        *(uint32_t*)(Og + (size_t)8 * DIM + col) =
            pack_h2(oacc[nt][2] * inv1, oacc[nt][3] * inv1);
    }
}

// ===========================================================================
// Launch
// ===========================================================================
extern "C" void kernel_launch(void* const* d_in, const int* in_sizes, int n_in,
                              void* d_out, int out_size)
{
    const float* x     = (const float*)d_in[0];  // (4096, 2048)
    const float* w_qkv = (const float*)d_in[1];  // (2048, 6144)
    const float* w_o   = (const float*)d_in[2];  // (2048, 2048)
    float* out = (float*)d_out;                  // (4096, 2048)

    __half *qkvh, *oh, *xh, *wqkvT, *woT;
    cudaGetSymbolAddress((void**)&qkvh,  g_qkvh);
    cudaGetSymbolAddress((void**)&oh,    g_oh);
    cudaGetSymbolAddress((void**)&xh,    g_xh);
    cudaGetSymbolAddress((void**)&wqkvT, g_wqkvT);
    cudaGetSymbolAddress((void**)&woT,   g_woT);

    cudaFuncSetAttribute(gemm_f16_mma<1>,
                         cudaFuncAttributeMaxDynamicSharedMemorySize, GEMM_SMEM);
    cudaFuncSetAttribute(gemm_f16_mma<0>,
                         cudaFuncAttributeMaxDynamicSharedMemorySize, GEMM_SMEM);
    cudaFuncSetAttribute(flash_mma_kernel,
                         cudaFuncAttributeMaxDynamicSharedMemorySize, FLASH_SMEM);

    // 0) convert x; transpose+convert weights (K-major B for the GEMMs)
    conv_half_kernel<<<2048, 256>>>(x, xh, (size_t)SEQ * DIM / 4);
    transpose_h_kernel<<<dim3(QKVW / 32, DIM / 32), dim3(32, 8)>>>(w_qkv, wqkvT, DIM, QKVW);
    transpose_h_kernel<<<dim3(DIM / 32, DIM / 32), dim3(32, 8)>>>(w_o, woT, DIM, DIM);

    // 1) QKV projection (fp16 mma, half output, 64x64 warp tiles)
    gemm_f16_mma<1><<<dim3(QKVW / 128, SEQ / 128), 128, GEMM_SMEM>>>(
        xh, wqkvT, qkvh, SEQ, QKVW, DIM);

    // 2) Attention (fp16 mma flash, software-pipelined)
    flash_mma_kernel<<<dim3(NH, SEQ / 64), 128, FLASH_SMEM>>>(qkvh, oh);

    // 3) Output projection (fp16 mma, float output, 64x64 warp tiles)
    gemm_f16_mma<0><<<dim3(DIM / 128, SEQ / 128), 128, GEMM_SMEM>>>(
        oh, woT, out, SEQ, DIM, DIM);
}